// round 10
// baseline (speedup 1.0000x reference)
#include <cuda_runtime.h>
#include <cuda_bf16.h>

#define PS   4096
#define PDM  2048
#define PNH  16
#define PNHK 8
#define PDH  128
#define PKP  512

// ---------------------------------------------------------------------------
// Scratch
// ---------------------------------------------------------------------------
constexpr size_t SZ_XP  = (size_t)PS * PKP * 4;
constexpr size_t SZ_QWP = (size_t)2048 * PKP * 4;
constexpr size_t SZ_KWP = (size_t)1024 * PKP * 4;
constexpr size_t SZ_VWP = (size_t)1024 * PKP * 4;
constexpr size_t SZ_OWP = (size_t)2048 * PKP * 4;
constexpr size_t SZ_QQ  = (size_t)PS * 2048 * 2;
constexpr size_t SZ_QK  = (size_t)PS * 1024 * 2;
constexpr size_t SZ_QF  = (size_t)PNH  * PS * PDH * 2;
constexpr size_t SZ_KF  = (size_t)PNHK * PS * PDH * 2;
constexpr size_t SZ_VF  = (size_t)PNHK * PS * PDH * 2;
constexpr size_t SZ_XO  = (size_t)PS * PDM * 4;
constexpr size_t SZ_XOQ = (size_t)PS * PKP * 4;
constexpr size_t SZ_XOS = (size_t)PS * 4;

constexpr size_t OFF_XP  = 0;
constexpr size_t OFF_QWP = OFF_XP  + SZ_XP;
constexpr size_t OFF_KWP = OFF_QWP + SZ_QWP;
constexpr size_t OFF_VWP = OFF_KWP + SZ_KWP;
constexpr size_t OFF_OWP = OFF_VWP + SZ_VWP;
constexpr size_t OFF_QQ  = OFF_OWP + SZ_OWP;
constexpr size_t OFF_QK  = OFF_QQ  + SZ_QQ;
constexpr size_t OFF_QF  = OFF_QK  + SZ_QK;
constexpr size_t OFF_KF  = OFF_QF  + SZ_QF;
constexpr size_t OFF_VF  = OFF_KF  + SZ_KF;
constexpr size_t OFF_XO  = OFF_VF  + SZ_VF;
constexpr size_t OFF_XOQ = OFF_XO  + SZ_XO;
constexpr size_t OFF_XOS = OFF_XOQ + SZ_XOQ;
constexpr size_t SCRATCH_BYTES = OFF_XOS + SZ_XOS;

__device__ __align__(256) unsigned char g_scratch[SCRATCH_BYTES];

// ---------------------------------------------------------------------------
// Pack int32-stored int8 values, 4 per word
// ---------------------------------------------------------------------------
__global__ __launch_bounds__(256)
void pack_i8(const int* __restrict__ src, int* __restrict__ dst, int n4)
{
    int i = blockIdx.x * 256 + threadIdx.x;
    if (i < n4) {
        int4 v = ((const int4*)src)[i];
        dst[i] = (v.x & 0xFF) | ((v.y & 0xFF) << 8) | ((v.z & 0xFF) << 16) | (v.w << 24);
    }
}

// ---------------------------------------------------------------------------
// dp4a GEMM, one output per thread, 16x16 tile.
// omode: 0 = bf16 store [m*ldc+n]
//        1 = bf16 store head-major (V): [(n>>7)][m][n&127]
//        2 = FLOAT32 store [m*ldc+n] of float(bf16(v))  <-- final output
// ---------------------------------------------------------------------------
__global__ __launch_bounds__(256)
void gemm2(const int* __restrict__ Ap, const int* __restrict__ Bp,
           const float* __restrict__ asc, const float* __restrict__ bsc,
           void* __restrict__ Cv, int ldc, int omode)
{
    __shared__ int As[16][68];
    __shared__ int Bs[16][68];

    const int tx = threadIdx.x, ty = threadIdx.y;
    const int tid = ty * 16 + tx;
    const int m0 = blockIdx.y * 16, n0 = blockIdx.x * 16;
    const int lr = tid >> 4, lc = (tid & 15) * 4;

    int acc = 0;
    for (int kt = 0; kt < PKP; kt += 64) {
        __syncthreads();
        *(int4*)&As[lr][lc] = *(const int4*)(Ap + (size_t)(m0 + lr) * PKP + kt + lc);
        *(int4*)&Bs[lr][lc] = *(const int4*)(Bp + (size_t)(n0 + lr) * PKP + kt + lc);
        __syncthreads();
#pragma unroll
        for (int k4 = 0; k4 < 64; k4 += 4) {
            int4 a = *(const int4*)&As[ty][k4];
            int4 b = *(const int4*)&Bs[tx][k4];
            acc = __dp4a(a.x, b.x, acc);
            acc = __dp4a(a.y, b.y, acc);
            acc = __dp4a(a.z, b.z, acc);
            acc = __dp4a(a.w, b.w, acc);
        }
    }

    const int m = m0 + ty, n = n0 + tx;
    float v = (float)acc * asc[m] * bsc[n];
    if (omode == 0) {
        ((__nv_bfloat16*)Cv)[(size_t)m * ldc + n] = __float2bfloat16(v);
    } else if (omode == 1) {
        ((__nv_bfloat16*)Cv)[((size_t)(n >> 7) * PS + m) * PDH + (n & 127)] = __float2bfloat16(v);
    } else {
        // final output: reference rounds to bf16, harness buffer is float32
        ((float*)Cv)[(size_t)m * ldc + n] = __bfloat162float(__float2bfloat16(v));
    }
}

// ---------------------------------------------------------------------------
// RMSNorm + RoPE, one block (128 threads) per (token, head).
// ---------------------------------------------------------------------------
__global__ __launch_bounds__(128)
void norm_rope2(const __nv_bfloat16* __restrict__ in, const float* __restrict__ nw,
                const float* __restrict__ cosp, const float* __restrict__ sinp,
                __nv_bfloat16* __restrict__ out, int nh)
{
    __shared__ float ss[128];
    __shared__ float ys[128];
    const int s = blockIdx.x, h = blockIdx.y, t = threadIdx.x;

    float x = __bfloat162float(in[((size_t)s * nh + h) * PDH + t]);
    ss[t] = x * x;
    __syncthreads();
    for (int o = 64; o > 0; o >>= 1) {
        if (t < o) ss[t] += ss[t + o];
        __syncthreads();
    }
    float r = rsqrtf(ss[0] * (1.0f / 128.0f) + 1e-6f);

    float y = __bfloat162float(__float2bfloat16(x * r * nw[t]));
    ys[t] = y;
    __syncthreads();
    float rh = (t < 64) ? -ys[t + 64] : ys[t - 64];

    float c  = __bfloat162float(__float2bfloat16(cosp[(size_t)s * PDH + t]));
    float sn = __bfloat162float(__float2bfloat16(sinp[(size_t)s * PDH + t]));
    float t1 = __bfloat162float(__float2bfloat16(y * c));
    float t2 = __bfloat162float(__float2bfloat16(rh * sn));
    out[((size_t)h * PS + s) * PDH + t] = __float2bfloat16(t1 + t2);
}

// ---------------------------------------------------------------------------
// Attention, warp-per-query-row. fp32, causal, GQA(G=2).
// ---------------------------------------------------------------------------
__global__ __launch_bounds__(256)
void attn_rows(const __nv_bfloat16* __restrict__ Q, const __nv_bfloat16* __restrict__ K,
               const __nv_bfloat16* __restrict__ V, const float* __restrict__ oisc,
               float* __restrict__ XO)
{
    __shared__ __nv_bfloat16 Ks[64][128];
    __shared__ __nv_bfloat16 Vs[64][128];

    const int tid  = threadIdx.x;
    const int w    = tid >> 5, lane = tid & 31;
    const int h    = blockIdx.y, hk = h >> 1;
    const int gr   = blockIdx.x * 8 + w;
    const int lastTile = blockIdx.x >> 3;

    const __nv_bfloat16* Kg = K + (size_t)hk * PS * PDH;
    const __nv_bfloat16* Vg = V + (size_t)hk * PS * PDH;

    const __nv_bfloat16* qp = Q + ((size_t)h * PS + gr) * PDH + lane * 4;
    uint2 qu = *(const uint2*)qp;
    float2 qa = __bfloat1622float2(*(const __nv_bfloat162*)&qu.x);
    float2 qb = __bfloat1622float2(*(const __nv_bfloat162*)&qu.y);

    const float scale = 0.08838834764831845f;
    float l = 0.0f;
    float o0 = 0.0f, o1 = 0.0f, o2 = 0.0f, o3 = 0.0f;

    for (int jt = 0; jt <= lastTile; jt++) {
        __syncthreads();
        const uint4* gk = (const uint4*)(Kg + (size_t)jt * 64 * PDH);
        const uint4* gv = (const uint4*)(Vg + (size_t)jt * 64 * PDH);
#pragma unroll
        for (int p = 0; p < 4; p++) {
            int idx = tid + p * 256;
            ((uint4*)Ks)[idx] = gk[idx];
            ((uint4*)Vs)[idx] = gv[idx];
        }
        __syncthreads();

        const int jlim = (jt == lastTile) ? (gr & 63) : 63;
        for (int j = 0; j <= jlim; j++) {
            uint2 ku = *(const uint2*)&Ks[j][lane * 4];
            float2 k0 = __bfloat1622float2(*(const __nv_bfloat162*)&ku.x);
            float2 k1 = __bfloat1622float2(*(const __nv_bfloat162*)&ku.y);
            float pd = qa.x * k0.x + qa.y * k0.y + qb.x * k1.x + qb.y * k1.y;
            pd += __shfl_xor_sync(0xffffffffu, pd, 16);
            pd += __shfl_xor_sync(0xffffffffu, pd, 8);
            pd += __shfl_xor_sync(0xffffffffu, pd, 4);
            pd += __shfl_xor_sync(0xffffffffu, pd, 2);
            pd += __shfl_xor_sync(0xffffffffu, pd, 1);
            float pw = __expf(pd * scale);

            uint2 vu = *(const uint2*)&Vs[j][lane * 4];
            float2 v0 = __bfloat1622float2(*(const __nv_bfloat162*)&vu.x);
            float2 v1 = __bfloat1622float2(*(const __nv_bfloat162*)&vu.y);
            l  += pw;
            o0 += pw * v0.x;
            o1 += pw * v0.y;
            o2 += pw * v1.x;
            o3 += pw * v1.y;
        }
    }

    const float inv = 1.0f / l;
    const int oc = h * PDH + lane * 4;
    float* xo = XO + (size_t)gr * PDM + oc;
    xo[0] = o0 * inv / oisc[oc + 0];
    xo[1] = o1 * inv / oisc[oc + 1];
    xo[2] = o2 * inv / oisc[oc + 2];
    xo[3] = o3 * inv / oisc[oc + 3];
}

// ---------------------------------------------------------------------------
// Per-token int8 quantization + packing.
// ---------------------------------------------------------------------------
__global__ __launch_bounds__(256)
void quant2(const float* __restrict__ XO, int* __restrict__ Xq, float* __restrict__ Xs)
{
    __shared__ float red[256];
    const int t = blockIdx.x, tid = threadIdx.x;

    float v[8];
    float m = 0.0f;
#pragma unroll
    for (int i = 0; i < 8; i++) {
        v[i] = XO[(size_t)t * PDM + tid * 8 + i];
        m = fmaxf(m, fabsf(v[i]));
    }
    red[tid] = m;
    __syncthreads();
    for (int o = 128; o > 0; o >>= 1) {
        if (tid < o) red[tid] = fmaxf(red[tid], red[tid + o]);
        __syncthreads();
    }
    float sc = fmaxf(red[0] * (1.0f / 127.0f), 1e-7f);

    int q[8];
#pragma unroll
    for (int i = 0; i < 8; i++)
        q[i] = (int)fminf(fmaxf(rintf(v[i] / sc), -128.0f), 127.0f);
    int p0 = (q[0] & 0xFF) | ((q[1] & 0xFF) << 8) | ((q[2] & 0xFF) << 16) | (q[3] << 24);
    int p1 = (q[4] & 0xFF) | ((q[5] & 0xFF) << 8) | ((q[6] & 0xFF) << 16) | (q[7] << 24);
    Xq[(size_t)t * PKP + tid * 2]     = p0;
    Xq[(size_t)t * PKP + tid * 2 + 1] = p1;
    if (tid == 0) Xs[t] = sc;
}

// ---------------------------------------------------------------------------
// Launch (insertion-order input mapping; OUTPUT IS FLOAT32)
// ---------------------------------------------------------------------------
extern "C" void kernel_launch(void* const* d_in, const int* in_sizes, int n_in,
                              void* d_out, int out_size)
{
    const int*   x_i8 = (const int*)d_in[0];
    const float* x_s  = (const float*)d_in[1];
    const float* cosp = (const float*)d_in[3];
    const float* sinp = (const float*)d_in[4];
    const int*   q_w  = (const int*)d_in[5];
    const float* q_ws = (const float*)d_in[6];
    const int*   k_w  = (const int*)d_in[7];
    const float* k_ws = (const float*)d_in[8];
    const int*   v_w  = (const int*)d_in[9];
    const float* v_ws = (const float*)d_in[10];
    const int*   o_w  = (const int*)d_in[11];
    const float* o_ws = (const float*)d_in[12];
    const float* o_is = (const float*)d_in[13];
    const float* qnw  = (const float*)d_in[14];
    const float* knw  = (const float*)d_in[15];

    unsigned char* base = nullptr;
    cudaGetSymbolAddress((void**)&base, g_scratch);

    int*           xp  = (int*)(base + OFF_XP);
    int*           qwp = (int*)(base + OFF_QWP);
    int*           kwp = (int*)(base + OFF_KWP);
    int*           vwp = (int*)(base + OFF_VWP);
    int*           owp = (int*)(base + OFF_OWP);
    __nv_bfloat16* qq  = (__nv_bfloat16*)(base + OFF_QQ);
    __nv_bfloat16* qk  = (__nv_bfloat16*)(base + OFF_QK);
    __nv_bfloat16* qf  = (__nv_bfloat16*)(base + OFF_QF);
    __nv_bfloat16* kf  = (__nv_bfloat16*)(base + OFF_KF);
    __nv_bfloat16* vf  = (__nv_bfloat16*)(base + OFF_VF);
    float*         xo  = (float*)(base + OFF_XO);
    int*           xoq = (int*)(base + OFF_XOQ);
    float*         xos = (float*)(base + OFF_XOS);

    dim3 b2(16, 16);

    // pack
    pack_i8<<<(PS * PKP) / 256, 256>>>(x_i8, xp, PS * PKP);
    pack_i8<<<(2048 * PKP) / 256, 256>>>(q_w, qwp, 2048 * PKP);
    pack_i8<<<(1024 * PKP) / 256, 256>>>(k_w, kwp, 1024 * PKP);
    pack_i8<<<(1024 * PKP) / 256, 256>>>(v_w, vwp, 1024 * PKP);
    pack_i8<<<(2048 * PKP) / 256, 256>>>(o_w, owp, 2048 * PKP);

    // QKV projections (V written directly head-major)
    gemm2<<<dim3(128, 256), b2>>>(xp, qwp, x_s, q_ws, qq, 2048, 0);
    gemm2<<<dim3(64, 256),  b2>>>(xp, kwp, x_s, k_ws, qk, 1024, 0);
    gemm2<<<dim3(64, 256),  b2>>>(xp, vwp, x_s, v_ws, vf, 0,    1);

    // rmsnorm + rope -> head-major
    norm_rope2<<<dim3(PS, PNH),  128>>>(qq, qnw, cosp, sinp, qf, PNH);
    norm_rope2<<<dim3(PS, PNHK), 128>>>(qk, knw, cosp, sinp, kf, PNHK);

    // attention (warp per row), folds /o_input_scale
    attn_rows<<<dim3(PS / 8, PNH), 256>>>(qf, kf, vf, o_is, xo);

    // per-token quant + pack
    quant2<<<PS, 256>>>(xo, xoq, xos);

    // o-proj -> FLOAT32 output (bf16-rounded values)
    gemm2<<<dim3(128, 256), b2>>>(xoq, owp, xos, o_ws, d_out, 2048, 2);
}

// round 11
// speedup vs baseline: 2.0786x; 2.0786x over previous
#include <cuda_runtime.h>
#include <cuda_bf16.h>

#define PS   4096
#define PDM  2048
#define PNH  16
#define PNHK 8
#define PDH  128
#define PKP  512

// ---------------------------------------------------------------------------
// Scratch
// ---------------------------------------------------------------------------
constexpr size_t SZ_XP  = (size_t)PS * PKP * 4;
constexpr size_t SZ_QWP = (size_t)2048 * PKP * 4;
constexpr size_t SZ_KWP = (size_t)1024 * PKP * 4;
constexpr size_t SZ_VWP = (size_t)1024 * PKP * 4;
constexpr size_t SZ_OWP = (size_t)2048 * PKP * 4;
constexpr size_t SZ_QQ  = (size_t)PS * 2048 * 2;
constexpr size_t SZ_QK  = (size_t)PS * 1024 * 2;
constexpr size_t SZ_QF  = (size_t)PNH  * PS * PDH * 2;
constexpr size_t SZ_KF  = (size_t)PNHK * PS * PDH * 2;
constexpr size_t SZ_VF  = (size_t)PNHK * PS * PDH * 2;
constexpr size_t SZ_XO  = (size_t)PS * PDM * 4;
constexpr size_t SZ_XOQ = (size_t)PS * PKP * 4;
constexpr size_t SZ_XOS = (size_t)PS * 4;

constexpr size_t OFF_XP  = 0;
constexpr size_t OFF_QWP = OFF_XP  + SZ_XP;
constexpr size_t OFF_KWP = OFF_QWP + SZ_QWP;
constexpr size_t OFF_VWP = OFF_KWP + SZ_KWP;
constexpr size_t OFF_OWP = OFF_VWP + SZ_VWP;
constexpr size_t OFF_QQ  = OFF_OWP + SZ_OWP;
constexpr size_t OFF_QK  = OFF_QQ  + SZ_QQ;
constexpr size_t OFF_QF  = OFF_QK  + SZ_QK;
constexpr size_t OFF_KF  = OFF_QF  + SZ_QF;
constexpr size_t OFF_VF  = OFF_KF  + SZ_KF;
constexpr size_t OFF_XO  = OFF_VF  + SZ_VF;
constexpr size_t OFF_XOQ = OFF_XO  + SZ_XO;
constexpr size_t OFF_XOS = OFF_XOQ + SZ_XOQ;
constexpr size_t SCRATCH_BYTES = OFF_XOS + SZ_XOS;

__device__ __align__(256) unsigned char g_scratch[SCRATCH_BYTES];

// ---------------------------------------------------------------------------
// Pack int32-stored int8 values, 4 per word
// ---------------------------------------------------------------------------
__global__ __launch_bounds__(256)
void pack_i8(const int* __restrict__ src, int* __restrict__ dst, int n4)
{
    int i = blockIdx.x * 256 + threadIdx.x;
    if (i < n4) {
        int4 v = ((const int4*)src)[i];
        dst[i] = (v.x & 0xFF) | ((v.y & 0xFF) << 8) | ((v.z & 0xFF) << 16) | (v.w << 24);
    }
}

// ---------------------------------------------------------------------------
// Register-tiled dp4a GEMM: BM=BN=128, BK=32 packed ints, 8x8 outputs/thread.
// C[m,n] = (sum_k A[m,k]*B[n,k]) * asc[m] * bsc[n]
// omode: 0 = bf16 [m*ldc+n]; 1 = bf16 head-major [(n>>7)][m][n&127];
//        2 = float32 [m*ldc+n] of float(bf16(v))   (final output)
// ---------------------------------------------------------------------------
__global__ __launch_bounds__(256)
void gemm_big(const int* __restrict__ Ap, const int* __restrict__ Bp,
              const float* __restrict__ asc, const float* __restrict__ bsc,
              void* __restrict__ Cv, int ldc, int omode)
{
    __shared__ int As[32][128];   // k-major
    __shared__ int Bs[32][128];

    const int tid = threadIdx.x;
    const int tx = tid & 15, ty = tid >> 4;
    const int m0 = blockIdx.y * 128, n0 = blockIdx.x * 128;
    const int row = tid & 127, half = tid >> 7;

    int acc[8][8];
#pragma unroll
    for (int i = 0; i < 8; i++)
#pragma unroll
        for (int j = 0; j < 8; j++) acc[i][j] = 0;

    for (int k0 = 0; k0 < PKP; k0 += 32) {
        __syncthreads();
        const int4* ga = (const int4*)(Ap + (size_t)(m0 + row) * PKP + k0 + half * 16);
        const int4* gb = (const int4*)(Bp + (size_t)(n0 + row) * PKP + k0 + half * 16);
#pragma unroll
        for (int p = 0; p < 4; p++) {
            int kk = half * 16 + p * 4;
            int4 va = ga[p];
            As[kk][row] = va.x; As[kk + 1][row] = va.y; As[kk + 2][row] = va.z; As[kk + 3][row] = va.w;
            int4 vb = gb[p];
            Bs[kk][row] = vb.x; Bs[kk + 1][row] = vb.y; Bs[kk + 2][row] = vb.z; Bs[kk + 3][row] = vb.w;
        }
        __syncthreads();
#pragma unroll 8
        for (int kk = 0; kk < 32; kk++) {
            int4 a0 = *(const int4*)&As[kk][ty * 8];
            int4 a1 = *(const int4*)&As[kk][ty * 8 + 4];
            int4 b0 = *(const int4*)&Bs[kk][tx * 8];
            int4 b1 = *(const int4*)&Bs[kk][tx * 8 + 4];
            int a[8] = {a0.x, a0.y, a0.z, a0.w, a1.x, a1.y, a1.z, a1.w};
            int b[8] = {b0.x, b0.y, b0.z, b0.w, b1.x, b1.y, b1.z, b1.w};
#pragma unroll
            for (int i = 0; i < 8; i++)
#pragma unroll
                for (int j = 0; j < 8; j++)
                    acc[i][j] = __dp4a(a[i], b[j], acc[i][j]);
        }
    }

    float av[8], bv[8];
#pragma unroll
    for (int i = 0; i < 8; i++) av[i] = asc[m0 + ty * 8 + i];
#pragma unroll
    for (int j = 0; j < 8; j++) bv[j] = bsc[n0 + tx * 8 + j];
#pragma unroll
    for (int i = 0; i < 8; i++) {
        int m = m0 + ty * 8 + i;
#pragma unroll
        for (int j = 0; j < 8; j++) {
            int n = n0 + tx * 8 + j;
            float v = (float)acc[i][j] * av[i] * bv[j];
            if (omode == 0)
                ((__nv_bfloat16*)Cv)[(size_t)m * ldc + n] = __float2bfloat16(v);
            else if (omode == 1)
                ((__nv_bfloat16*)Cv)[((size_t)(n >> 7) * PS + m) * PDH + (n & 127)] = __float2bfloat16(v);
            else
                ((float*)Cv)[(size_t)m * ldc + n] = __bfloat162float(__float2bfloat16(v));
        }
    }
}

// ---------------------------------------------------------------------------
// RMSNorm + RoPE, one block (128 threads) per (token, head).
// ---------------------------------------------------------------------------
__global__ __launch_bounds__(128)
void norm_rope2(const __nv_bfloat16* __restrict__ in, const float* __restrict__ nw,
                const float* __restrict__ cosp, const float* __restrict__ sinp,
                __nv_bfloat16* __restrict__ out, int nh)
{
    __shared__ float ss[128];
    __shared__ float ys[128];
    const int s = blockIdx.x, h = blockIdx.y, t = threadIdx.x;

    float x = __bfloat162float(in[((size_t)s * nh + h) * PDH + t]);
    ss[t] = x * x;
    __syncthreads();
    for (int o = 64; o > 0; o >>= 1) {
        if (t < o) ss[t] += ss[t + o];
        __syncthreads();
    }
    float r = rsqrtf(ss[0] * (1.0f / 128.0f) + 1e-6f);

    float y = __bfloat162float(__float2bfloat16(x * r * nw[t]));
    ys[t] = y;
    __syncthreads();
    float rh = (t < 64) ? -ys[t + 64] : ys[t - 64];

    float c  = __bfloat162float(__float2bfloat16(cosp[(size_t)s * PDH + t]));
    float sn = __bfloat162float(__float2bfloat16(sinp[(size_t)s * PDH + t]));
    float t1 = __bfloat162float(__float2bfloat16(y * c));
    float t2 = __bfloat162float(__float2bfloat16(rh * sn));
    out[((size_t)h * PS + s) * PDH + t] = __float2bfloat16(t1 + t2);
}

// ---------------------------------------------------------------------------
// Tiled flash attention, fp32, causal, GQA(G=2). BM=BN=64, 256 threads.
// No max-subtraction (|s| <= ~11.3 after rmsnorm -> exp safe in fp32).
// Q/K channel-major f32 (S loop), V sequence-major stride 129 (PV loop).
// Sequential single-accumulator order matches reference summation.
// ---------------------------------------------------------------------------
#define VSTR 129
constexpr int FA_SMEM = (2 * 128 * 64 + 64 * VSTR + 64 * 68) * 4;  // 115968 B

__global__ __launch_bounds__(256)
void flash2(const __nv_bfloat16* __restrict__ Q, const __nv_bfloat16* __restrict__ K,
            const __nv_bfloat16* __restrict__ V, const float* __restrict__ oisc,
            float* __restrict__ XO)
{
    extern __shared__ float sm[];
    float* Qs = sm;                 // [128][64]  channel-major
    float* Ks = Qs + 128 * 64;      // [128][64]
    float* Vs = Ks + 128 * 64;      // [64][VSTR] sequence-major
    float* Ps = Vs + 64 * VSTR;     // [64][68]

    const int tid = threadIdx.x, tx = tid & 15, ty = tid >> 4;
    const int qb = blockIdx.x, h = blockIdx.y, hk = h >> 1;
    const int lrow = tid & 63, lcb = tid >> 6;

    const __nv_bfloat16* Qg = Q + ((size_t)h * PS + qb * 64) * PDH;
    const __nv_bfloat16* Kg = K + (size_t)hk * PS * PDH;
    const __nv_bfloat16* Vg = V + (size_t)hk * PS * PDH;

    // Q tile -> channel-major f32
#pragma unroll
    for (int p = 0; p < 4; p++) {
        int ch = lcb * 4 + p;
        uint4 u = *(const uint4*)(Qg + (size_t)lrow * PDH + ch * 8);
        const __nv_bfloat162* hv = (const __nv_bfloat162*)&u;
#pragma unroll
        for (int q = 0; q < 4; q++) {
            float2 f = __bfloat1622float2(hv[q]);
            Qs[(ch * 8 + 2 * q)     * 64 + lrow] = f.x;
            Qs[(ch * 8 + 2 * q + 1) * 64 + lrow] = f.y;
        }
    }

    float oacc[4][8];
    float li[4];
#pragma unroll
    for (int i = 0; i < 4; i++) {
        li[i] = 0.0f;
#pragma unroll
        for (int j = 0; j < 8; j++) oacc[i][j] = 0.0f;
    }
    const float scale = 0.08838834764831845f;   // 1/sqrt(128)

    for (int jt = 0; jt <= qb; jt++) {
        __syncthreads();
#pragma unroll
        for (int p = 0; p < 4; p++) {
            int ch = lcb * 4 + p;
            size_t goff = ((size_t)(jt * 64 + lrow)) * PDH + ch * 8;
            uint4 uk = *(const uint4*)(Kg + goff);
            uint4 uv = *(const uint4*)(Vg + goff);
            const __nv_bfloat162* pk = (const __nv_bfloat162*)&uk;
            const __nv_bfloat162* pv = (const __nv_bfloat162*)&uv;
#pragma unroll
            for (int q = 0; q < 4; q++) {
                float2 fk = __bfloat1622float2(pk[q]);
                float2 fv = __bfloat1622float2(pv[q]);
                Ks[(ch * 8 + 2 * q)     * 64 + lrow] = fk.x;
                Ks[(ch * 8 + 2 * q + 1) * 64 + lrow] = fk.y;
                Vs[lrow * VSTR + ch * 8 + 2 * q]     = fv.x;
                Vs[lrow * VSTR + ch * 8 + 2 * q + 1] = fv.y;
            }
        }
        __syncthreads();

        // S = Q K^T, 4x4 per thread, sequential over k (reference order)
        float sreg[4][4];
#pragma unroll
        for (int i = 0; i < 4; i++)
#pragma unroll
            for (int j = 0; j < 4; j++) sreg[i][j] = 0.0f;
#pragma unroll 4
        for (int k = 0; k < 128; k++) {
            float4 a = *(const float4*)&Qs[k * 64 + ty * 4];
            float4 b = *(const float4*)&Ks[k * 64 + tx * 4];
            float af[4] = {a.x, a.y, a.z, a.w};
            float bf[4] = {b.x, b.y, b.z, b.w};
#pragma unroll
            for (int i = 0; i < 4; i++)
#pragma unroll
                for (int j = 0; j < 4; j++) sreg[i][j] += af[i] * bf[j];
        }

        // p = exp(s*scale), causal-masked; row-sum into li
#pragma unroll
        for (int i = 0; i < 4; i++) {
            int gr = qb * 64 + ty * 4 + i;
            float p4[4];
            float ps = 0.0f;
#pragma unroll
            for (int j = 0; j < 4; j++) {
                int gc = jt * 64 + tx * 4 + j;
                float p = (gc <= gr) ? __expf(sreg[i][j] * scale) : 0.0f;
                p4[j] = p; ps += p;
            }
            ps += __shfl_xor_sync(0xffffffffu, ps, 1);
            ps += __shfl_xor_sync(0xffffffffu, ps, 2);
            ps += __shfl_xor_sync(0xffffffffu, ps, 4);
            ps += __shfl_xor_sync(0xffffffffu, ps, 8);
            li[i] += ps;
            *(float4*)&Ps[(ty * 4 + i) * 68 + tx * 4] = make_float4(p4[0], p4[1], p4[2], p4[3]);
        }
        __syncthreads();

        // O += P * V  (V seq-major: Vs[k][d], d = tx + 16*j)
#pragma unroll 2
        for (int k = 0; k < 64; k++) {
            float a[4], b[8];
#pragma unroll
            for (int i = 0; i < 4; i++) a[i] = Ps[(ty * 4 + i) * 68 + k];
#pragma unroll
            for (int j = 0; j < 8; j++) b[j] = Vs[k * VSTR + tx + 16 * j];
#pragma unroll
            for (int i = 0; i < 4; i++)
#pragma unroll
                for (int j = 0; j < 8; j++) oacc[i][j] += a[i] * b[j];
        }
    }

    // epilogue: /l and /o_input_scale
#pragma unroll
    for (int i = 0; i < 4; i++) {
        int gr = qb * 64 + ty * 4 + i;
        float inv = 1.0f / li[i];
#pragma unroll
        for (int j = 0; j < 8; j++) {
            int oc = h * PDH + tx + 16 * j;
            XO[(size_t)gr * PDM + oc] = oacc[i][j] * inv / oisc[oc];
        }
    }
}

// ---------------------------------------------------------------------------
// Per-token int8 quantization + packing.
// ---------------------------------------------------------------------------
__global__ __launch_bounds__(256)
void quant2(const float* __restrict__ XO, int* __restrict__ Xq, float* __restrict__ Xs)
{
    __shared__ float red[256];
    const int t = blockIdx.x, tid = threadIdx.x;

    float v[8];
    float m = 0.0f;
#pragma unroll
    for (int i = 0; i < 8; i++) {
        v[i] = XO[(size_t)t * PDM + tid * 8 + i];
        m = fmaxf(m, fabsf(v[i]));
    }
    red[tid] = m;
    __syncthreads();
    for (int o = 128; o > 0; o >>= 1) {
        if (tid < o) red[tid] = fmaxf(red[tid], red[tid + o]);
        __syncthreads();
    }
    float sc = fmaxf(red[0] * (1.0f / 127.0f), 1e-7f);

    int q[8];
#pragma unroll
    for (int i = 0; i < 8; i++)
        q[i] = (int)fminf(fmaxf(rintf(v[i] / sc), -128.0f), 127.0f);
    int p0 = (q[0] & 0xFF) | ((q[1] & 0xFF) << 8) | ((q[2] & 0xFF) << 16) | (q[3] << 24);
    int p1 = (q[4] & 0xFF) | ((q[5] & 0xFF) << 8) | ((q[6] & 0xFF) << 16) | (q[7] << 24);
    Xq[(size_t)t * PKP + tid * 2]     = p0;
    Xq[(size_t)t * PKP + tid * 2 + 1] = p1;
    if (tid == 0) Xs[t] = sc;
}

// ---------------------------------------------------------------------------
// Launch (insertion-order input mapping; OUTPUT IS FLOAT32)
// ---------------------------------------------------------------------------
extern "C" void kernel_launch(void* const* d_in, const int* in_sizes, int n_in,
                              void* d_out, int out_size)
{
    const int*   x_i8 = (const int*)d_in[0];
    const float* x_s  = (const float*)d_in[1];
    const float* cosp = (const float*)d_in[3];
    const float* sinp = (const float*)d_in[4];
    const int*   q_w  = (const int*)d_in[5];
    const float* q_ws = (const float*)d_in[6];
    const int*   k_w  = (const int*)d_in[7];
    const float* k_ws = (const float*)d_in[8];
    const int*   v_w  = (const int*)d_in[9];
    const float* v_ws = (const float*)d_in[10];
    const int*   o_w  = (const int*)d_in[11];
    const float* o_ws = (const float*)d_in[12];
    const float* o_is = (const float*)d_in[13];
    const float* qnw  = (const float*)d_in[14];
    const float* knw  = (const float*)d_in[15];

    unsigned char* base = nullptr;
    cudaGetSymbolAddress((void**)&base, g_scratch);

    int*           xp  = (int*)(base + OFF_XP);
    int*           qwp = (int*)(base + OFF_QWP);
    int*           kwp = (int*)(base + OFF_KWP);
    int*           vwp = (int*)(base + OFF_VWP);
    int*           owp = (int*)(base + OFF_OWP);
    __nv_bfloat16* qq  = (__nv_bfloat16*)(base + OFF_QQ);
    __nv_bfloat16* qk  = (__nv_bfloat16*)(base + OFF_QK);
    __nv_bfloat16* qf  = (__nv_bfloat16*)(base + OFF_QF);
    __nv_bfloat16* kf  = (__nv_bfloat16*)(base + OFF_KF);
    __nv_bfloat16* vf  = (__nv_bfloat16*)(base + OFF_VF);
    float*         xo  = (float*)(base + OFF_XO);
    int*           xoq = (int*)(base + OFF_XOQ);
    float*         xos = (float*)(base + OFF_XOS);

    // pack
    pack_i8<<<(PS * PKP) / 256, 256>>>(x_i8, xp, PS * PKP);
    pack_i8<<<(2048 * PKP) / 256, 256>>>(q_w, qwp, 2048 * PKP);
    pack_i8<<<(1024 * PKP) / 256, 256>>>(k_w, kwp, 1024 * PKP);
    pack_i8<<<(1024 * PKP) / 256, 256>>>(v_w, vwp, 1024 * PKP);
    pack_i8<<<(2048 * PKP) / 256, 256>>>(o_w, owp, 2048 * PKP);

    // QKV projections (V written directly head-major)
    gemm_big<<<dim3(16, 32), 256>>>(xp, qwp, x_s, q_ws, qq, 2048, 0);
    gemm_big<<<dim3(8, 32),  256>>>(xp, kwp, x_s, k_ws, qk, 1024, 0);
    gemm_big<<<dim3(8, 32),  256>>>(xp, vwp, x_s, v_ws, vf, 0,    1);

    // rmsnorm + rope -> head-major
    norm_rope2<<<dim3(PS, PNH),  128>>>(qq, qnw, cosp, sinp, qf, PNH);
    norm_rope2<<<dim3(PS, PNHK), 128>>>(qk, knw, cosp, sinp, kf, PNHK);

    // tiled flash attention, folds /o_input_scale
    cudaFuncSetAttribute(flash2, cudaFuncAttributeMaxDynamicSharedMemorySize, FA_SMEM);
    flash2<<<dim3(PS / 64, PNH), 256, FA_SMEM>>>(qf, kf, vf, o_is, xo);

    // per-token quant + pack
    quant2<<<PS, 256>>>(xo, xoq, xos);

    // o-proj -> FLOAT32 output (bf16-rounded values)
    gemm_big<<<dim3(16, 32), 256>>>(xoq, owp, xos, o_ws, d_out, 2048, 2);
}

// round 12
// speedup vs baseline: 4.6256x; 2.2253x over previous
#include <cuda_runtime.h>
#include <cuda_bf16.h>
#include <cstdint>

#define PS   4096
#define PDM  2048
#define PNH  16
#define PNHK 8
#define PDH  128
#define PKP  512

// ---------------------------------------------------------------------------
// Scratch
// ---------------------------------------------------------------------------
constexpr size_t SZ_XP  = (size_t)PS * PKP * 4;
constexpr size_t SZ_QWP = (size_t)2048 * PKP * 4;
constexpr size_t SZ_KWP = (size_t)1024 * PKP * 4;
constexpr size_t SZ_VWP = (size_t)1024 * PKP * 4;
constexpr size_t SZ_OWP = (size_t)2048 * PKP * 4;
constexpr size_t SZ_QQ  = (size_t)PS * 2048 * 2;
constexpr size_t SZ_QK  = (size_t)PS * 1024 * 2;
constexpr size_t SZ_QF  = (size_t)PNH  * PS * PDH * 2;
constexpr size_t SZ_KF  = (size_t)PNHK * PS * PDH * 2;
constexpr size_t SZ_VF  = (size_t)PNHK * PS * PDH * 2;
constexpr size_t SZ_XO  = (size_t)PS * PDM * 4;
constexpr size_t SZ_XOQ = (size_t)PS * PKP * 4;
constexpr size_t SZ_XOS = (size_t)PS * 4;

constexpr size_t OFF_XP  = 0;
constexpr size_t OFF_QWP = OFF_XP  + SZ_XP;
constexpr size_t OFF_KWP = OFF_QWP + SZ_QWP;
constexpr size_t OFF_VWP = OFF_KWP + SZ_KWP;
constexpr size_t OFF_OWP = OFF_VWP + SZ_VWP;
constexpr size_t OFF_QQ  = OFF_OWP + SZ_OWP;
constexpr size_t OFF_QK  = OFF_QQ  + SZ_QQ;
constexpr size_t OFF_QF  = OFF_QK  + SZ_QK;
constexpr size_t OFF_KF  = OFF_QF  + SZ_QF;
constexpr size_t OFF_VF  = OFF_KF  + SZ_KF;
constexpr size_t OFF_XO  = OFF_VF  + SZ_VF;
constexpr size_t OFF_XOQ = OFF_XO  + SZ_XO;
constexpr size_t OFF_XOS = OFF_XOQ + SZ_XOQ;
constexpr size_t SCRATCH_BYTES = OFF_XOS + SZ_XOS;

__device__ __align__(256) unsigned char g_scratch[SCRATCH_BYTES];

// ---------------------------------------------------------------------------
// Pack int32-stored int8 values, 4 per word
// ---------------------------------------------------------------------------
__global__ __launch_bounds__(256)
void pack_i8(const int* __restrict__ src, int* __restrict__ dst, int n4)
{
    int i = blockIdx.x * 256 + threadIdx.x;
    if (i < n4) {
        int4 v = ((const int4*)src)[i];
        dst[i] = (v.x & 0xFF) | ((v.y & 0xFF) << 8) | ((v.z & 0xFF) << 16) | (v.w << 24);
    }
}

// ---------------------------------------------------------------------------
// Register-tiled dp4a GEMM: BM=BN=128, BK=32 packed ints, 8x8 outputs/thread.
// omode: 0 = bf16 [m*ldc+n]; 1 = bf16 head-major; 2 = float32 of bf16(v)
// ---------------------------------------------------------------------------
__global__ __launch_bounds__(256)
void gemm_big(const int* __restrict__ Ap, const int* __restrict__ Bp,
              const float* __restrict__ asc, const float* __restrict__ bsc,
              void* __restrict__ Cv, int ldc, int omode)
{
    __shared__ int As[32][128];
    __shared__ int Bs[32][128];

    const int tid = threadIdx.x;
    const int tx = tid & 15, ty = tid >> 4;
    const int m0 = blockIdx.y * 128, n0 = blockIdx.x * 128;
    const int row = tid & 127, half = tid >> 7;

    int acc[8][8];
#pragma unroll
    for (int i = 0; i < 8; i++)
#pragma unroll
        for (int j = 0; j < 8; j++) acc[i][j] = 0;

    for (int k0 = 0; k0 < PKP; k0 += 32) {
        __syncthreads();
        const int4* ga = (const int4*)(Ap + (size_t)(m0 + row) * PKP + k0 + half * 16);
        const int4* gb = (const int4*)(Bp + (size_t)(n0 + row) * PKP + k0 + half * 16);
#pragma unroll
        for (int p = 0; p < 4; p++) {
            int kk = half * 16 + p * 4;
            int4 va = ga[p];
            As[kk][row] = va.x; As[kk + 1][row] = va.y; As[kk + 2][row] = va.z; As[kk + 3][row] = va.w;
            int4 vb = gb[p];
            Bs[kk][row] = vb.x; Bs[kk + 1][row] = vb.y; Bs[kk + 2][row] = vb.z; Bs[kk + 3][row] = vb.w;
        }
        __syncthreads();
#pragma unroll 8
        for (int kk = 0; kk < 32; kk++) {
            int4 a0 = *(const int4*)&As[kk][ty * 8];
            int4 a1 = *(const int4*)&As[kk][ty * 8 + 4];
            int4 b0 = *(const int4*)&Bs[kk][tx * 8];
            int4 b1 = *(const int4*)&Bs[kk][tx * 8 + 4];
            int a[8] = {a0.x, a0.y, a0.z, a0.w, a1.x, a1.y, a1.z, a1.w};
            int b[8] = {b0.x, b0.y, b0.z, b0.w, b1.x, b1.y, b1.z, b1.w};
#pragma unroll
            for (int i = 0; i < 8; i++)
#pragma unroll
                for (int j = 0; j < 8; j++)
                    acc[i][j] = __dp4a(a[i], b[j], acc[i][j]);
        }
    }

    float av[8], bv[8];
#pragma unroll
    for (int i = 0; i < 8; i++) av[i] = asc[m0 + ty * 8 + i];
#pragma unroll
    for (int j = 0; j < 8; j++) bv[j] = bsc[n0 + tx * 8 + j];
#pragma unroll
    for (int i = 0; i < 8; i++) {
        int m = m0 + ty * 8 + i;
#pragma unroll
        for (int j = 0; j < 8; j++) {
            int n = n0 + tx * 8 + j;
            float v = (float)acc[i][j] * av[i] * bv[j];
            if (omode == 0)
                ((__nv_bfloat16*)Cv)[(size_t)m * ldc + n] = __float2bfloat16(v);
            else if (omode == 1)
                ((__nv_bfloat16*)Cv)[((size_t)(n >> 7) * PS + m) * PDH + (n & 127)] = __float2bfloat16(v);
            else
                ((float*)Cv)[(size_t)m * ldc + n] = __bfloat162float(__float2bfloat16(v));
        }
    }
}

// ---------------------------------------------------------------------------
// RMSNorm + RoPE, one block (128 threads) per (token, head).
// ---------------------------------------------------------------------------
__global__ __launch_bounds__(128)
void norm_rope2(const __nv_bfloat16* __restrict__ in, const float* __restrict__ nw,
                const float* __restrict__ cosp, const float* __restrict__ sinp,
                __nv_bfloat16* __restrict__ out, int nh)
{
    __shared__ float ss[128];
    __shared__ float ys[128];
    const int s = blockIdx.x, h = blockIdx.y, t = threadIdx.x;

    float x = __bfloat162float(in[((size_t)s * nh + h) * PDH + t]);
    ss[t] = x * x;
    __syncthreads();
    for (int o = 64; o > 0; o >>= 1) {
        if (t < o) ss[t] += ss[t + o];
        __syncthreads();
    }
    float r = rsqrtf(ss[0] * (1.0f / 128.0f) + 1e-6f);

    float y = __bfloat162float(__float2bfloat16(x * r * nw[t]));
    ys[t] = y;
    __syncthreads();
    float rh = (t < 64) ? -ys[t + 64] : ys[t - 64];

    float c  = __bfloat162float(__float2bfloat16(cosp[(size_t)s * PDH + t]));
    float sn = __bfloat162float(__float2bfloat16(sinp[(size_t)s * PDH + t]));
    float t1 = __bfloat162float(__float2bfloat16(y * c));
    float t2 = __bfloat162float(__float2bfloat16(rh * sn));
    out[((size_t)h * PS + s) * PDH + t] = __float2bfloat16(t1 + t2);
}

// ---------------------------------------------------------------------------
// HMMA flash attention (FA2-style register pipeline), causal, GQA(G=2).
// BM=128 (8 warps x m16), BN=64, DH=128. S via bf16 mma (exact products,
// f32 accum). P split hi/lo bf16 -> two PV mmas (error ~2^-16). No max
// subtraction (|s*scale| <= ~14, fp32-safe).
// ---------------------------------------------------------------------------
#define QSTR 136          // Q/K smem row stride in bf16 (68 words: conflict-free frags)
#define VSTRT 72          // Vt smem row stride in bf16 (36 words)
constexpr int FAM_SMEM = (128 * QSTR + 64 * QSTR + 128 * VSTRT) * 2;  // 70656 B

#define MMA16816(d, a, b) \
    asm volatile("mma.sync.aligned.m16n8k16.row.col.f32.bf16.bf16.f32 " \
                 "{%0,%1,%2,%3}, {%4,%5,%6,%7}, {%8,%9}, {%0,%1,%2,%3};" \
                 : "+f"(d[0]), "+f"(d[1]), "+f"(d[2]), "+f"(d[3]) \
                 : "r"(a[0]), "r"(a[1]), "r"(a[2]), "r"(a[3]), "r"(b[0]), "r"(b[1]))

__device__ __forceinline__ uint32_t packbf2(float lo, float hi)
{
    __nv_bfloat162 h = __floats2bfloat162_rn(lo, hi);
    return *(uint32_t*)&h;
}

__global__ __launch_bounds__(256)
void flash_mma(const __nv_bfloat16* __restrict__ Q, const __nv_bfloat16* __restrict__ K,
               const __nv_bfloat16* __restrict__ V, const float* __restrict__ oisc,
               float* __restrict__ XO)
{
    extern __shared__ __nv_bfloat16 smb[];
    __nv_bfloat16* Qs = smb;                    // [128][QSTR]
    __nv_bfloat16* Ks = Qs + 128 * QSTR;        // [64][QSTR]
    __nv_bfloat16* Vt = Ks + 64 * QSTR;         // [128][VSTRT] (dh-major)
    const uint32_t* Qw = (const uint32_t*)Qs;   // stride 68 words
    const uint32_t* Kw = (const uint32_t*)Ks;
    const uint32_t* Vw = (const uint32_t*)Vt;

    const int tid  = threadIdx.x;
    const int w    = tid >> 5, lane = tid & 31;
    const int g    = lane >> 2, t4 = lane & 3;
    const int qb   = 31 - blockIdx.x;           // big tiles first
    const int h    = blockIdx.y, hk = h >> 1;

    const __nv_bfloat16* Qg = Q + ((size_t)h * PS + qb * 128) * PDH;
    const __nv_bfloat16* Kg = K + (size_t)hk * PS * PDH;
    const __nv_bfloat16* Vg = V + (size_t)hk * PS * PDH;

    // Q tile -> smem (row-major, stride QSTR)
    {
        int row = tid >> 1, dhb = (tid & 1) * 64;
        const uint4* src = (const uint4*)(Qg + (size_t)row * PDH + dhb);
        uint4* dst = (uint4*)(Qs + row * QSTR + dhb);
#pragma unroll
        for (int i = 0; i < 8; i++) dst[i] = src[i];
    }

    float oac[16][4];
#pragma unroll
    for (int n = 0; n < 16; n++)
#pragma unroll
        for (int c = 0; c < 4; c++) oac[n][c] = 0.0f;
    float li0 = 0.0f, li1 = 0.0f;
    const float scale = 0.08838834764831845f;

    const int gr0 = qb * 128 + w * 16 + g;
    const int gr1 = gr0 + 8;
    const int jtmax = 2 * qb + 1;

    for (int jt = 0; jt <= jtmax; jt++) {
        __syncthreads();
        // K tile (row-major) and V tile (transposed -> Vt[dh][kv])
        {
            int row = tid >> 2, dhb = (tid & 3) * 32;
            const uint4* src = (const uint4*)(Kg + (size_t)(jt * 64 + row) * PDH + dhb);
            uint4* dst = (uint4*)(Ks + row * QSTR + dhb);
#pragma unroll
            for (int i = 0; i < 4; i++) dst[i] = src[i];

            int kv = tid & 63, dvb = (tid >> 6) * 32;
            const uint4* vs = (const uint4*)(Vg + (size_t)(jt * 64 + kv) * PDH + dvb);
#pragma unroll
            for (int i = 0; i < 4; i++) {
                uint4 u = vs[i];
                const __nv_bfloat16* e = (const __nv_bfloat16*)&u;
#pragma unroll
                for (int j = 0; j < 8; j++)
                    Vt[(dvb + i * 8 + j) * VSTRT + kv] = e[j];
            }
        }
        __syncthreads();

        // ----- S = Q K^T : 8 n-tiles x 8 k-tiles of m16n8k16 -----
        float sc[8][4];
#pragma unroll
        for (int n = 0; n < 8; n++)
#pragma unroll
            for (int c = 0; c < 4; c++) sc[n][c] = 0.0f;

#pragma unroll
        for (int kt = 0; kt < 8; kt++) {
            uint32_t a[4];
            int abase = (w * 16 + g) * 68 + kt * 8 + t4;
            a[0] = Qw[abase];
            a[1] = Qw[abase + 8 * 68];
            a[2] = Qw[abase + 4];
            a[3] = Qw[abase + 8 * 68 + 4];
#pragma unroll
            for (int nt = 0; nt < 8; nt++) {
                uint32_t b[2];
                int bbase = (nt * 8 + g) * 68 + kt * 8 + t4;
                b[0] = Kw[bbase];
                b[1] = Kw[bbase + 4];
                MMA16816(sc[nt], a, b);
            }
        }

        // ----- softmax (no max-subtraction), causal mask, row sums -----
        float rs0 = 0.0f, rs1 = 0.0f;
        const int colb = jt * 64 + t4 * 2;
#pragma unroll
        for (int nt = 0; nt < 8; nt++) {
            int c0 = colb + nt * 8;
            float p0 = (c0     <= gr0) ? __expf(sc[nt][0] * scale) : 0.0f;
            float p1 = (c0 + 1 <= gr0) ? __expf(sc[nt][1] * scale) : 0.0f;
            float p2 = (c0     <= gr1) ? __expf(sc[nt][2] * scale) : 0.0f;
            float p3 = (c0 + 1 <= gr1) ? __expf(sc[nt][3] * scale) : 0.0f;
            sc[nt][0] = p0; sc[nt][1] = p1; sc[nt][2] = p2; sc[nt][3] = p3;
            rs0 += p0 + p1;
            rs1 += p2 + p3;
        }
        rs0 += __shfl_xor_sync(0xffffffffu, rs0, 1);
        rs0 += __shfl_xor_sync(0xffffffffu, rs0, 2);
        rs1 += __shfl_xor_sync(0xffffffffu, rs1, 1);
        rs1 += __shfl_xor_sync(0xffffffffu, rs1, 2);
        li0 += rs0;
        li1 += rs1;

        // ----- repack P into hi/lo bf16 A-fragments (4 k-tiles of k16) -----
        uint32_t Phi[4][4], Plo[4][4];
#pragma unroll
        for (int kt = 0; kt < 4; kt++) {
#pragma unroll
            for (int hv = 0; hv < 2; hv++) {
                float* c = sc[2 * kt + hv];
                __nv_bfloat16 h0 = __float2bfloat16_rn(c[0]);
                __nv_bfloat16 h1 = __float2bfloat16_rn(c[1]);
                __nv_bfloat16 h2 = __float2bfloat16_rn(c[2]);
                __nv_bfloat16 h3 = __float2bfloat16_rn(c[3]);
                float l0 = c[0] - __bfloat162float(h0);
                float l1 = c[1] - __bfloat162float(h1);
                float l2 = c[2] - __bfloat162float(h2);
                float l3 = c[3] - __bfloat162float(h3);
                Phi[kt][hv * 2 + 0] = ((uint32_t)*(uint16_t*)&h1 << 16) | *(uint16_t*)&h0;
                Phi[kt][hv * 2 + 1] = ((uint32_t)*(uint16_t*)&h3 << 16) | *(uint16_t*)&h2;
                Plo[kt][hv * 2 + 0] = packbf2(l0, l1);
                Plo[kt][hv * 2 + 1] = packbf2(l2, l3);
            }
        }
        // reorder: A regs must be [ (g,k0-1), (g+8,k0-1), (g,k8-9), (g+8,k8-9) ]
        // built above as [t0c01, t0c23, t1c01, t1c23] == [(g,k0),(g+8,k0),(g,k8),(g+8,k8)] ✓

        // ----- O += P * V : 16 n-tiles (dh) x 4 k-tiles, hi+lo -----
#pragma unroll
        for (int nt2 = 0; nt2 < 16; nt2++) {
#pragma unroll
            for (int kt = 0; kt < 4; kt++) {
                uint32_t b[2];
                int bbase = (nt2 * 8 + g) * 36 + kt * 8 + t4;
                b[0] = Vw[bbase];
                b[1] = Vw[bbase + 4];
                MMA16816(oac[nt2], Phi[kt], b);
                MMA16816(oac[nt2], Plo[kt], b);
            }
        }
    }

    // ----- epilogue: /l and /o_input_scale -----
    const float inv0 = 1.0f / li0;
    const float inv1 = 1.0f / li1;
#pragma unroll
    for (int nt2 = 0; nt2 < 16; nt2++) {
        int oc = h * PDH + nt2 * 8 + t4 * 2;
        float s0 = oisc[oc], s1 = oisc[oc + 1];
        XO[(size_t)gr0 * PDM + oc]     = oac[nt2][0] * inv0 / s0;
        XO[(size_t)gr0 * PDM + oc + 1] = oac[nt2][1] * inv0 / s1;
        XO[(size_t)gr1 * PDM + oc]     = oac[nt2][2] * inv1 / s0;
        XO[(size_t)gr1 * PDM + oc + 1] = oac[nt2][3] * inv1 / s1;
    }
}

// ---------------------------------------------------------------------------
// Per-token int8 quantization + packing.
// ---------------------------------------------------------------------------
__global__ __launch_bounds__(256)
void quant2(const float* __restrict__ XO, int* __restrict__ Xq, float* __restrict__ Xs)
{
    __shared__ float red[256];
    const int t = blockIdx.x, tid = threadIdx.x;

    float v[8];
    float m = 0.0f;
#pragma unroll
    for (int i = 0; i < 8; i++) {
        v[i] = XO[(size_t)t * PDM + tid * 8 + i];
        m = fmaxf(m, fabsf(v[i]));
    }
    red[tid] = m;
    __syncthreads();
    for (int o = 128; o > 0; o >>= 1) {
        if (tid < o) red[tid] = fmaxf(red[tid], red[tid + o]);
        __syncthreads();
    }
    float sc = fmaxf(red[0] * (1.0f / 127.0f), 1e-7f);

    int q[8];
#pragma unroll
    for (int i = 0; i < 8; i++)
        q[i] = (int)fminf(fmaxf(rintf(v[i] / sc), -128.0f), 127.0f);
    int p0 = (q[0] & 0xFF) | ((q[1] & 0xFF) << 8) | ((q[2] & 0xFF) << 16) | (q[3] << 24);
    int p1 = (q[4] & 0xFF) | ((q[5] & 0xFF) << 8) | ((q[6] & 0xFF) << 16) | (q[7] << 24);
    Xq[(size_t)t * PKP + tid * 2]     = p0;
    Xq[(size_t)t * PKP + tid * 2 + 1] = p1;
    if (tid == 0) Xs[t] = sc;
}

// ---------------------------------------------------------------------------
// Launch
// ---------------------------------------------------------------------------
extern "C" void kernel_launch(void* const* d_in, const int* in_sizes, int n_in,
                              void* d_out, int out_size)
{
    const int*   x_i8 = (const int*)d_in[0];
    const float* x_s  = (const float*)d_in[1];
    const float* cosp = (const float*)d_in[3];
    const float* sinp = (const float*)d_in[4];
    const int*   q_w  = (const int*)d_in[5];
    const float* q_ws = (const float*)d_in[6];
    const int*   k_w  = (const int*)d_in[7];
    const float* k_ws = (const float*)d_in[8];
    const int*   v_w  = (const int*)d_in[9];
    const float* v_ws = (const float*)d_in[10];
    const int*   o_w  = (const int*)d_in[11];
    const float* o_ws = (const float*)d_in[12];
    const float* o_is = (const float*)d_in[13];
    const float* qnw  = (const float*)d_in[14];
    const float* knw  = (const float*)d_in[15];

    unsigned char* base = nullptr;
    cudaGetSymbolAddress((void**)&base, g_scratch);

    int*           xp  = (int*)(base + OFF_XP);
    int*           qwp = (int*)(base + OFF_QWP);
    int*           kwp = (int*)(base + OFF_KWP);
    int*           vwp = (int*)(base + OFF_VWP);
    int*           owp = (int*)(base + OFF_OWP);
    __nv_bfloat16* qq  = (__nv_bfloat16*)(base + OFF_QQ);
    __nv_bfloat16* qk  = (__nv_bfloat16*)(base + OFF_QK);
    __nv_bfloat16* qf  = (__nv_bfloat16*)(base + OFF_QF);
    __nv_bfloat16* kf  = (__nv_bfloat16*)(base + OFF_KF);
    __nv_bfloat16* vf  = (__nv_bfloat16*)(base + OFF_VF);
    float*         xo  = (float*)(base + OFF_XO);
    int*           xoq = (int*)(base + OFF_XOQ);
    float*         xos = (float*)(base + OFF_XOS);

    // pack
    pack_i8<<<(PS * PKP) / 256, 256>>>(x_i8, xp, PS * PKP);
    pack_i8<<<(2048 * PKP) / 256, 256>>>(q_w, qwp, 2048 * PKP);
    pack_i8<<<(1024 * PKP) / 256, 256>>>(k_w, kwp, 1024 * PKP);
    pack_i8<<<(1024 * PKP) / 256, 256>>>(v_w, vwp, 1024 * PKP);
    pack_i8<<<(2048 * PKP) / 256, 256>>>(o_w, owp, 2048 * PKP);

    // QKV projections (V written directly head-major)
    gemm_big<<<dim3(16, 32), 256>>>(xp, qwp, x_s, q_ws, qq, 2048, 0);
    gemm_big<<<dim3(8, 32),  256>>>(xp, kwp, x_s, k_ws, qk, 1024, 0);
    gemm_big<<<dim3(8, 32),  256>>>(xp, vwp, x_s, v_ws, vf, 0,    1);

    // rmsnorm + rope -> head-major
    norm_rope2<<<dim3(PS, PNH),  128>>>(qq, qnw, cosp, sinp, qf, PNH);
    norm_rope2<<<dim3(PS, PNHK), 128>>>(qk, knw, cosp, sinp, kf, PNHK);

    // HMMA flash attention, folds /o_input_scale
    cudaFuncSetAttribute(flash_mma, cudaFuncAttributeMaxDynamicSharedMemorySize, FAM_SMEM);
    flash_mma<<<dim3(32, PNH), 256, FAM_SMEM>>>(qf, kf, vf, o_is, xo);

    // per-token quant + pack
    quant2<<<PS, 256>>>(xo, xoq, xos);

    // o-proj -> FLOAT32 output (bf16-rounded values)
    gemm_big<<<dim3(16, 32), 256>>>(xoq, owp, xos, o_ws, d_out, 2048, 2);
}

// round 13
// speedup vs baseline: 4.9585x; 1.0720x over previous
#include <cuda_runtime.h>
#include <cuda_bf16.h>
#include <cstdint>

#define PS   4096
#define PDM  2048
#define PNH  16
#define PNHK 8
#define PDH  128
#define PKP  512

// ---------------------------------------------------------------------------
// Scratch
// ---------------------------------------------------------------------------
constexpr size_t SZ_XP  = (size_t)PS * PKP * 4;
constexpr size_t SZ_QWP = (size_t)2048 * PKP * 4;
constexpr size_t SZ_KWP = (size_t)1024 * PKP * 4;
constexpr size_t SZ_VWP = (size_t)1024 * PKP * 4;
constexpr size_t SZ_OWP = (size_t)2048 * PKP * 4;
constexpr size_t SZ_QQ  = (size_t)PS * 2048 * 2;
constexpr size_t SZ_QK  = (size_t)PS * 1024 * 2;
constexpr size_t SZ_QF  = (size_t)PNH  * PS * PDH * 2;
constexpr size_t SZ_KF  = (size_t)PNHK * PS * PDH * 2;
constexpr size_t SZ_VF  = (size_t)PNHK * PS * PDH * 2;
constexpr size_t SZ_XO  = (size_t)PS * PDM * 4;
constexpr size_t SZ_XOQ = (size_t)PS * PKP * 4;
constexpr size_t SZ_XOS = (size_t)PS * 4;

constexpr size_t OFF_XP  = 0;
constexpr size_t OFF_QWP = OFF_XP  + SZ_XP;
constexpr size_t OFF_KWP = OFF_QWP + SZ_QWP;
constexpr size_t OFF_VWP = OFF_KWP + SZ_KWP;
constexpr size_t OFF_OWP = OFF_VWP + SZ_VWP;
constexpr size_t OFF_QQ  = OFF_OWP + SZ_OWP;
constexpr size_t OFF_QK  = OFF_QQ  + SZ_QQ;
constexpr size_t OFF_QF  = OFF_QK  + SZ_QK;
constexpr size_t OFF_KF  = OFF_QF  + SZ_QF;
constexpr size_t OFF_VF  = OFF_KF  + SZ_KF;
constexpr size_t OFF_XO  = OFF_VF  + SZ_VF;
constexpr size_t OFF_XOQ = OFF_XO  + SZ_XO;
constexpr size_t OFF_XOS = OFF_XOQ + SZ_XOQ;
constexpr size_t SCRATCH_BYTES = OFF_XOS + SZ_XOS;

__device__ __align__(256) unsigned char g_scratch[SCRATCH_BYTES];

// ---------------------------------------------------------------------------
// Pack int32-stored int8 values, 4 per word
// ---------------------------------------------------------------------------
__global__ __launch_bounds__(256)
void pack_i8(const int* __restrict__ src, int* __restrict__ dst, int n4)
{
    int i = blockIdx.x * 256 + threadIdx.x;
    if (i < n4) {
        int4 v = ((const int4*)src)[i];
        dst[i] = (v.x & 0xFF) | ((v.y & 0xFF) << 8) | ((v.z & 0xFF) << 16) | (v.w << 24);
    }
}

// ---------------------------------------------------------------------------
// IMMA GEMM (mma.sync.m16n8k32.s8): BM=BN=128, BK=32 words (128 int8).
// 8 warps = 2(m) x 4(n); warp tile m64 x n32 = 4x4 mma tiles.
// A packed [M][512] words, B packed [N][512] words.
// omode: 0 = bf16 [m*ldc+n]; 1 = bf16 head-major; 2 = float32 of bf16(v)
// ---------------------------------------------------------------------------
#define IMMA16832(d, a, b) \
    asm volatile("mma.sync.aligned.m16n8k32.row.col.s32.s8.s8.s32 " \
                 "{%0,%1,%2,%3}, {%4,%5,%6,%7}, {%8,%9}, {%0,%1,%2,%3};" \
                 : "+r"(d[0]), "+r"(d[1]), "+r"(d[2]), "+r"(d[3]) \
                 : "r"(a[0]), "r"(a[1]), "r"(a[2]), "r"(a[3]), "r"(b[0]), "r"(b[1]))

#define GST 36   // smem row stride in words: frag banks (4g+t4)%32 all-distinct

__global__ __launch_bounds__(256)
void gemm_imma(const int* __restrict__ Ap, const int* __restrict__ Bp,
               const float* __restrict__ asc, const float* __restrict__ bsc,
               void* __restrict__ Cv, int ldc, int omode)
{
    __shared__ int As[128 * GST];
    __shared__ int Bs[128 * GST];

    const int tid = threadIdx.x;
    const int w = tid >> 5, lane = tid & 31;
    const int g = lane >> 2, t4 = lane & 3;
    const int wm = w >> 2, wn = w & 3;
    const int m0 = blockIdx.y * 128, n0 = blockIdx.x * 128;

    const int lrow = tid >> 1, lhalf = (tid & 1) * 16;

    uint32_t acc[4][4][4];
#pragma unroll
    for (int mt = 0; mt < 4; mt++)
#pragma unroll
        for (int nt = 0; nt < 4; nt++)
#pragma unroll
            for (int c = 0; c < 4; c++) acc[mt][nt][c] = 0;

    for (int k0 = 0; k0 < PKP; k0 += 32) {
        __syncthreads();
        {
            const int4* ga = (const int4*)(Ap + (size_t)(m0 + lrow) * PKP + k0 + lhalf);
            const int4* gb = (const int4*)(Bp + (size_t)(n0 + lrow) * PKP + k0 + lhalf);
            int4* da = (int4*)&As[lrow * GST + lhalf];
            int4* db = (int4*)&Bs[lrow * GST + lhalf];
#pragma unroll
            for (int p = 0; p < 4; p++) { da[p] = ga[p]; db[p] = gb[p]; }
        }
        __syncthreads();

#pragma unroll
        for (int ks = 0; ks < 4; ks++) {
            uint32_t a[4][4];
#pragma unroll
            for (int mt = 0; mt < 4; mt++) {
                int base = (wm * 64 + mt * 16 + g) * GST + ks * 8 + t4;
                a[mt][0] = As[base];
                a[mt][1] = As[base + 8 * GST];
                a[mt][2] = As[base + 4];
                a[mt][3] = As[base + 8 * GST + 4];
            }
#pragma unroll
            for (int nt = 0; nt < 4; nt++) {
                int bbase = (wn * 32 + nt * 8 + g) * GST + ks * 8 + t4;
                uint32_t b[2] = { (uint32_t)Bs[bbase], (uint32_t)Bs[bbase + 4] };
#pragma unroll
                for (int mt = 0; mt < 4; mt++)
                    IMMA16832(acc[mt][nt], a[mt], b);
            }
        }
    }

    // epilogue
#pragma unroll
    for (int mt = 0; mt < 4; mt++) {
        int r0 = m0 + wm * 64 + mt * 16 + g;
        int r1 = r0 + 8;
        float a0 = asc[r0], a1 = asc[r1];
#pragma unroll
        for (int nt = 0; nt < 4; nt++) {
            int n = n0 + wn * 32 + nt * 8 + t4 * 2;
            float b0 = bsc[n], b1 = bsc[n + 1];
            float v00 = (float)(int)acc[mt][nt][0] * a0 * b0;
            float v01 = (float)(int)acc[mt][nt][1] * a0 * b1;
            float v10 = (float)(int)acc[mt][nt][2] * a1 * b0;
            float v11 = (float)(int)acc[mt][nt][3] * a1 * b1;
            if (omode == 0) {
                __nv_bfloat16* C = (__nv_bfloat16*)Cv;
                C[(size_t)r0 * ldc + n]     = __float2bfloat16(v00);
                C[(size_t)r0 * ldc + n + 1] = __float2bfloat16(v01);
                C[(size_t)r1 * ldc + n]     = __float2bfloat16(v10);
                C[(size_t)r1 * ldc + n + 1] = __float2bfloat16(v11);
            } else if (omode == 1) {
                __nv_bfloat16* C = (__nv_bfloat16*)Cv;
                C[((size_t)(n >> 7) * PS + r0) * PDH + (n & 127)]           = __float2bfloat16(v00);
                C[((size_t)((n + 1) >> 7) * PS + r0) * PDH + ((n + 1) & 127)] = __float2bfloat16(v01);
                C[((size_t)(n >> 7) * PS + r1) * PDH + (n & 127)]           = __float2bfloat16(v10);
                C[((size_t)((n + 1) >> 7) * PS + r1) * PDH + ((n + 1) & 127)] = __float2bfloat16(v11);
            } else {
                float* C = (float*)Cv;
                C[(size_t)r0 * ldc + n]     = __bfloat162float(__float2bfloat16(v00));
                C[(size_t)r0 * ldc + n + 1] = __bfloat162float(__float2bfloat16(v01));
                C[(size_t)r1 * ldc + n]     = __bfloat162float(__float2bfloat16(v10));
                C[(size_t)r1 * ldc + n + 1] = __bfloat162float(__float2bfloat16(v11));
            }
        }
    }
}

// ---------------------------------------------------------------------------
// RMSNorm + RoPE, one block (128 threads) per (token, head).
// ---------------------------------------------------------------------------
__global__ __launch_bounds__(128)
void norm_rope2(const __nv_bfloat16* __restrict__ in, const float* __restrict__ nw,
                const float* __restrict__ cosp, const float* __restrict__ sinp,
                __nv_bfloat16* __restrict__ out, int nh)
{
    __shared__ float ss[128];
    __shared__ float ys[128];
    const int s = blockIdx.x, h = blockIdx.y, t = threadIdx.x;

    float x = __bfloat162float(in[((size_t)s * nh + h) * PDH + t]);
    ss[t] = x * x;
    __syncthreads();
    for (int o = 64; o > 0; o >>= 1) {
        if (t < o) ss[t] += ss[t + o];
        __syncthreads();
    }
    float r = rsqrtf(ss[0] * (1.0f / 128.0f) + 1e-6f);

    float y = __bfloat162float(__float2bfloat16(x * r * nw[t]));
    ys[t] = y;
    __syncthreads();
    float rh = (t < 64) ? -ys[t + 64] : ys[t - 64];

    float c  = __bfloat162float(__float2bfloat16(cosp[(size_t)s * PDH + t]));
    float sn = __bfloat162float(__float2bfloat16(sinp[(size_t)s * PDH + t]));
    float t1 = __bfloat162float(__float2bfloat16(y * c));
    float t2 = __bfloat162float(__float2bfloat16(rh * sn));
    out[((size_t)h * PS + s) * PDH + t] = __float2bfloat16(t1 + t2);
}

// ---------------------------------------------------------------------------
// HMMA flash attention (FA2-style), causal, GQA(G=2). BM=128, BN=64.
// ---------------------------------------------------------------------------
#define QSTR 136
#define VSTRT 72
constexpr int FAM_SMEM = (128 * QSTR + 64 * QSTR + 128 * VSTRT) * 2;

#define MMA16816(d, a, b) \
    asm volatile("mma.sync.aligned.m16n8k16.row.col.f32.bf16.bf16.f32 " \
                 "{%0,%1,%2,%3}, {%4,%5,%6,%7}, {%8,%9}, {%0,%1,%2,%3};" \
                 : "+f"(d[0]), "+f"(d[1]), "+f"(d[2]), "+f"(d[3]) \
                 : "r"(a[0]), "r"(a[1]), "r"(a[2]), "r"(a[3]), "r"(b[0]), "r"(b[1]))

__device__ __forceinline__ uint32_t packbf2(float lo, float hi)
{
    __nv_bfloat162 h = __floats2bfloat162_rn(lo, hi);
    return *(uint32_t*)&h;
}

__global__ __launch_bounds__(256)
void flash_mma(const __nv_bfloat16* __restrict__ Q, const __nv_bfloat16* __restrict__ K,
               const __nv_bfloat16* __restrict__ V, const float* __restrict__ oisc,
               float* __restrict__ XO)
{
    extern __shared__ __nv_bfloat16 smb[];
    __nv_bfloat16* Qs = smb;
    __nv_bfloat16* Ks = Qs + 128 * QSTR;
    __nv_bfloat16* Vt = Ks + 64 * QSTR;
    const uint32_t* Qw = (const uint32_t*)Qs;
    const uint32_t* Kw = (const uint32_t*)Ks;
    const uint32_t* Vw = (const uint32_t*)Vt;

    const int tid  = threadIdx.x;
    const int w    = tid >> 5, lane = tid & 31;
    const int g    = lane >> 2, t4 = lane & 3;
    const int qb   = 31 - blockIdx.x;
    const int h    = blockIdx.y, hk = h >> 1;

    const __nv_bfloat16* Qg = Q + ((size_t)h * PS + qb * 128) * PDH;
    const __nv_bfloat16* Kg = K + (size_t)hk * PS * PDH;
    const __nv_bfloat16* Vg = V + (size_t)hk * PS * PDH;

    {
        int row = tid >> 1, dhb = (tid & 1) * 64;
        const uint4* src = (const uint4*)(Qg + (size_t)row * PDH + dhb);
        uint4* dst = (uint4*)(Qs + row * QSTR + dhb);
#pragma unroll
        for (int i = 0; i < 8; i++) dst[i] = src[i];
    }

    float oac[16][4];
#pragma unroll
    for (int n = 0; n < 16; n++)
#pragma unroll
        for (int c = 0; c < 4; c++) oac[n][c] = 0.0f;
    float li0 = 0.0f, li1 = 0.0f;
    const float scale = 0.08838834764831845f;

    const int gr0 = qb * 128 + w * 16 + g;
    const int gr1 = gr0 + 8;
    const int jtmax = 2 * qb + 1;

    for (int jt = 0; jt <= jtmax; jt++) {
        __syncthreads();
        {
            int row = tid >> 2, dhb = (tid & 3) * 32;
            const uint4* src = (const uint4*)(Kg + (size_t)(jt * 64 + row) * PDH + dhb);
            uint4* dst = (uint4*)(Ks + row * QSTR + dhb);
#pragma unroll
            for (int i = 0; i < 4; i++) dst[i] = src[i];

            int kv = tid & 63, dvb = (tid >> 6) * 32;
            const uint4* vs = (const uint4*)(Vg + (size_t)(jt * 64 + kv) * PDH + dvb);
#pragma unroll
            for (int i = 0; i < 4; i++) {
                uint4 u = vs[i];
                const __nv_bfloat16* e = (const __nv_bfloat16*)&u;
#pragma unroll
                for (int j = 0; j < 8; j++)
                    Vt[(dvb + i * 8 + j) * VSTRT + kv] = e[j];
            }
        }
        __syncthreads();

        float sc[8][4];
#pragma unroll
        for (int n = 0; n < 8; n++)
#pragma unroll
            for (int c = 0; c < 4; c++) sc[n][c] = 0.0f;

#pragma unroll
        for (int kt = 0; kt < 8; kt++) {
            uint32_t a[4];
            int abase = (w * 16 + g) * 68 + kt * 8 + t4;
            a[0] = Qw[abase];
            a[1] = Qw[abase + 8 * 68];
            a[2] = Qw[abase + 4];
            a[3] = Qw[abase + 8 * 68 + 4];
#pragma unroll
            for (int nt = 0; nt < 8; nt++) {
                uint32_t b[2];
                int bbase = (nt * 8 + g) * 68 + kt * 8 + t4;
                b[0] = Kw[bbase];
                b[1] = Kw[bbase + 4];
                MMA16816(sc[nt], a, b);
            }
        }

        float rs0 = 0.0f, rs1 = 0.0f;
        const int colb = jt * 64 + t4 * 2;
#pragma unroll
        for (int nt = 0; nt < 8; nt++) {
            int c0 = colb + nt * 8;
            float p0 = (c0     <= gr0) ? __expf(sc[nt][0] * scale) : 0.0f;
            float p1 = (c0 + 1 <= gr0) ? __expf(sc[nt][1] * scale) : 0.0f;
            float p2 = (c0     <= gr1) ? __expf(sc[nt][2] * scale) : 0.0f;
            float p3 = (c0 + 1 <= gr1) ? __expf(sc[nt][3] * scale) : 0.0f;
            sc[nt][0] = p0; sc[nt][1] = p1; sc[nt][2] = p2; sc[nt][3] = p3;
            rs0 += p0 + p1;
            rs1 += p2 + p3;
        }
        rs0 += __shfl_xor_sync(0xffffffffu, rs0, 1);
        rs0 += __shfl_xor_sync(0xffffffffu, rs0, 2);
        rs1 += __shfl_xor_sync(0xffffffffu, rs1, 1);
        rs1 += __shfl_xor_sync(0xffffffffu, rs1, 2);
        li0 += rs0;
        li1 += rs1;

        uint32_t Phi[4][4], Plo[4][4];
#pragma unroll
        for (int kt = 0; kt < 4; kt++) {
#pragma unroll
            for (int hv = 0; hv < 2; hv++) {
                float* c = sc[2 * kt + hv];
                __nv_bfloat16 h0 = __float2bfloat16_rn(c[0]);
                __nv_bfloat16 h1 = __float2bfloat16_rn(c[1]);
                __nv_bfloat16 h2 = __float2bfloat16_rn(c[2]);
                __nv_bfloat16 h3 = __float2bfloat16_rn(c[3]);
                float l0 = c[0] - __bfloat162float(h0);
                float l1 = c[1] - __bfloat162float(h1);
                float l2 = c[2] - __bfloat162float(h2);
                float l3 = c[3] - __bfloat162float(h3);
                Phi[kt][hv * 2 + 0] = ((uint32_t)*(uint16_t*)&h1 << 16) | *(uint16_t*)&h0;
                Phi[kt][hv * 2 + 1] = ((uint32_t)*(uint16_t*)&h3 << 16) | *(uint16_t*)&h2;
                Plo[kt][hv * 2 + 0] = packbf2(l0, l1);
                Plo[kt][hv * 2 + 1] = packbf2(l2, l3);
            }
        }

#pragma unroll
        for (int nt2 = 0; nt2 < 16; nt2++) {
#pragma unroll
            for (int kt = 0; kt < 4; kt++) {
                uint32_t b[2];
                int bbase = (nt2 * 8 + g) * 36 + kt * 8 + t4;
                b[0] = Vw[bbase];
                b[1] = Vw[bbase + 4];
                MMA16816(oac[nt2], Phi[kt], b);
                MMA16816(oac[nt2], Plo[kt], b);
            }
        }
    }

    const float inv0 = 1.0f / li0;
    const float inv1 = 1.0f / li1;
#pragma unroll
    for (int nt2 = 0; nt2 < 16; nt2++) {
        int oc = h * PDH + nt2 * 8 + t4 * 2;
        float s0 = oisc[oc], s1 = oisc[oc + 1];
        XO[(size_t)gr0 * PDM + oc]     = oac[nt2][0] * inv0 / s0;
        XO[(size_t)gr0 * PDM + oc + 1] = oac[nt2][1] * inv0 / s1;
        XO[(size_t)gr1 * PDM + oc]     = oac[nt2][2] * inv1 / s0;
        XO[(size_t)gr1 * PDM + oc + 1] = oac[nt2][3] * inv1 / s1;
    }
}

// ---------------------------------------------------------------------------
// Per-token int8 quantization + packing.
// ---------------------------------------------------------------------------
__global__ __launch_bounds__(256)
void quant2(const float* __restrict__ XO, int* __restrict__ Xq, float* __restrict__ Xs)
{
    __shared__ float red[256];
    const int t = blockIdx.x, tid = threadIdx.x;

    float v[8];
    float m = 0.0f;
#pragma unroll
    for (int i = 0; i < 8; i++) {
        v[i] = XO[(size_t)t * PDM + tid * 8 + i];
        m = fmaxf(m, fabsf(v[i]));
    }
    red[tid] = m;
    __syncthreads();
    for (int o = 128; o > 0; o >>= 1) {
        if (tid < o) red[tid] = fmaxf(red[tid], red[tid + o]);
        __syncthreads();
    }
    float sc = fmaxf(red[0] * (1.0f / 127.0f), 1e-7f);

    int q[8];
#pragma unroll
    for (int i = 0; i < 8; i++)
        q[i] = (int)fminf(fmaxf(rintf(v[i] / sc), -128.0f), 127.0f);
    int p0 = (q[0] & 0xFF) | ((q[1] & 0xFF) << 8) | ((q[2] & 0xFF) << 16) | (q[3] << 24);
    int p1 = (q[4] & 0xFF) | ((q[5] & 0xFF) << 8) | ((q[6] & 0xFF) << 16) | (q[7] << 24);
    Xq[(size_t)t * PKP + tid * 2]     = p0;
    Xq[(size_t)t * PKP + tid * 2 + 1] = p1;
    if (tid == 0) Xs[t] = sc;
}

// ---------------------------------------------------------------------------
// Launch
// ---------------------------------------------------------------------------
extern "C" void kernel_launch(void* const* d_in, const int* in_sizes, int n_in,
                              void* d_out, int out_size)
{
    const int*   x_i8 = (const int*)d_in[0];
    const float* x_s  = (const float*)d_in[1];
    const float* cosp = (const float*)d_in[3];
    const float* sinp = (const float*)d_in[4];
    const int*   q_w  = (const int*)d_in[5];
    const float* q_ws = (const float*)d_in[6];
    const int*   k_w  = (const int*)d_in[7];
    const float* k_ws = (const float*)d_in[8];
    const int*   v_w  = (const int*)d_in[9];
    const float* v_ws = (const float*)d_in[10];
    const int*   o_w  = (const int*)d_in[11];
    const float* o_ws = (const float*)d_in[12];
    const float* o_is = (const float*)d_in[13];
    const float* qnw  = (const float*)d_in[14];
    const float* knw  = (const float*)d_in[15];

    unsigned char* base = nullptr;
    cudaGetSymbolAddress((void**)&base, g_scratch);

    int*           xp  = (int*)(base + OFF_XP);
    int*           qwp = (int*)(base + OFF_QWP);
    int*           kwp = (int*)(base + OFF_KWP);
    int*           vwp = (int*)(base + OFF_VWP);
    int*           owp = (int*)(base + OFF_OWP);
    __nv_bfloat16* qq  = (__nv_bfloat16*)(base + OFF_QQ);
    __nv_bfloat16* qk  = (__nv_bfloat16*)(base + OFF_QK);
    __nv_bfloat16* qf  = (__nv_bfloat16*)(base + OFF_QF);
    __nv_bfloat16* kf  = (__nv_bfloat16*)(base + OFF_KF);
    __nv_bfloat16* vf  = (__nv_bfloat16*)(base + OFF_VF);
    float*         xo  = (float*)(base + OFF_XO);
    int*           xoq = (int*)(base + OFF_XOQ);
    float*         xos = (float*)(base + OFF_XOS);

    // pack
    pack_i8<<<(PS * PKP) / 256, 256>>>(x_i8, xp, PS * PKP);
    pack_i8<<<(2048 * PKP) / 256, 256>>>(q_w, qwp, 2048 * PKP);
    pack_i8<<<(1024 * PKP) / 256, 256>>>(k_w, kwp, 1024 * PKP);
    pack_i8<<<(1024 * PKP) / 256, 256>>>(v_w, vwp, 1024 * PKP);
    pack_i8<<<(2048 * PKP) / 256, 256>>>(o_w, owp, 2048 * PKP);

    // QKV projections via IMMA (V written directly head-major)
    gemm_imma<<<dim3(16, 32), 256>>>(xp, qwp, x_s, q_ws, qq, 2048, 0);
    gemm_imma<<<dim3(8, 32),  256>>>(xp, kwp, x_s, k_ws, qk, 1024, 0);
    gemm_imma<<<dim3(8, 32),  256>>>(xp, vwp, x_s, v_ws, vf, 0,    1);

    // rmsnorm + rope -> head-major
    norm_rope2<<<dim3(PS, PNH),  128>>>(qq, qnw, cosp, sinp, qf, PNH);
    norm_rope2<<<dim3(PS, PNHK), 128>>>(qk, knw, cosp, sinp, kf, PNHK);

    // HMMA flash attention, folds /o_input_scale
    cudaFuncSetAttribute(flash_mma, cudaFuncAttributeMaxDynamicSharedMemorySize, FAM_SMEM);
    flash_mma<<<dim3(32, PNH), 256, FAM_SMEM>>>(qf, kf, vf, o_is, xo);

    // per-token quant + pack
    quant2<<<PS, 256>>>(xo, xoq, xos);

    // o-proj via IMMA -> FLOAT32 output (bf16-rounded values)
    gemm_imma<<<dim3(16, 32), 256>>>(xoq, owp, xos, o_ws, d_out, 2048, 2);
}

// round 14
// speedup vs baseline: 5.3479x; 1.0785x over previous
#include <cuda_runtime.h>
#include <cuda_bf16.h>
#include <cstdint>

#define PS   4096
#define PDM  2048
#define PNH  16
#define PNHK 8
#define PDH  128
#define PKP  512

// ---------------------------------------------------------------------------
// Scratch
// ---------------------------------------------------------------------------
constexpr size_t SZ_XP  = (size_t)PS * PKP * 4;
constexpr size_t SZ_QWP = (size_t)2048 * PKP * 4;
constexpr size_t SZ_KWP = (size_t)1024 * PKP * 4;
constexpr size_t SZ_VWP = (size_t)1024 * PKP * 4;
constexpr size_t SZ_OWP = (size_t)2048 * PKP * 4;
constexpr size_t SZ_QQ  = (size_t)PS * 2048 * 2;
constexpr size_t SZ_QK  = (size_t)PS * 1024 * 2;
constexpr size_t SZ_QF  = (size_t)PNH  * PS * PDH * 2;
constexpr size_t SZ_KF  = (size_t)PNHK * PS * PDH * 2;
constexpr size_t SZ_VF  = (size_t)PNHK * PS * PDH * 2;
constexpr size_t SZ_XO  = (size_t)PS * PDM * 4;
constexpr size_t SZ_XOQ = (size_t)PS * PKP * 4;
constexpr size_t SZ_XOS = (size_t)PS * 4;

constexpr size_t OFF_XP  = 0;
constexpr size_t OFF_QWP = OFF_XP  + SZ_XP;
constexpr size_t OFF_KWP = OFF_QWP + SZ_QWP;
constexpr size_t OFF_VWP = OFF_KWP + SZ_KWP;
constexpr size_t OFF_OWP = OFF_VWP + SZ_VWP;
constexpr size_t OFF_QQ  = OFF_OWP + SZ_OWP;
constexpr size_t OFF_QK  = OFF_QQ  + SZ_QQ;
constexpr size_t OFF_QF  = OFF_QK  + SZ_QK;
constexpr size_t OFF_KF  = OFF_QF  + SZ_QF;
constexpr size_t OFF_VF  = OFF_KF  + SZ_KF;
constexpr size_t OFF_XO  = OFF_VF  + SZ_VF;
constexpr size_t OFF_XOQ = OFF_XO  + SZ_XO;
constexpr size_t OFF_XOS = OFF_XOQ + SZ_XOQ;
constexpr size_t SCRATCH_BYTES = OFF_XOS + SZ_XOS;

__device__ __align__(256) unsigned char g_scratch[SCRATCH_BYTES];

// ---------------------------------------------------------------------------
// PTX helpers
// ---------------------------------------------------------------------------
#define CP_ASYNC16(dst, src) \
    asm volatile("cp.async.cg.shared.global [%0], [%1], 16;" :: "r"(dst), "l"(src))
#define CP_COMMIT() asm volatile("cp.async.commit_group;")
#define CP_WAIT(n)  asm volatile("cp.async.wait_group %0;" :: "n"(n))

#define IMMA16832(d, a, b) \
    asm volatile("mma.sync.aligned.m16n8k32.row.col.s32.s8.s8.s32 " \
                 "{%0,%1,%2,%3}, {%4,%5,%6,%7}, {%8,%9}, {%0,%1,%2,%3};" \
                 : "+r"(d[0]), "+r"(d[1]), "+r"(d[2]), "+r"(d[3]) \
                 : "r"(a[0]), "r"(a[1]), "r"(a[2]), "r"(a[3]), "r"(b[0]), "r"(b[1]))

#define MMA16816(d, a, b) \
    asm volatile("mma.sync.aligned.m16n8k16.row.col.f32.bf16.bf16.f32 " \
                 "{%0,%1,%2,%3}, {%4,%5,%6,%7}, {%8,%9}, {%0,%1,%2,%3};" \
                 : "+f"(d[0]), "+f"(d[1]), "+f"(d[2]), "+f"(d[3]) \
                 : "r"(a[0]), "r"(a[1]), "r"(a[2]), "r"(a[3]), "r"(b[0]), "r"(b[1]))

#define LDSM4(r0, r1, r2, r3, addr) \
    asm volatile("ldmatrix.sync.aligned.m8n8.x4.shared.b16 {%0,%1,%2,%3}, [%4];" \
                 : "=r"(r0), "=r"(r1), "=r"(r2), "=r"(r3) : "r"(addr))

#define LDSM4T(r0, r1, r2, r3, addr) \
    asm volatile("ldmatrix.sync.aligned.m8n8.x4.trans.shared.b16 {%0,%1,%2,%3}, [%4];" \
                 : "=r"(r0), "=r"(r1), "=r"(r2), "=r"(r3) : "r"(addr))

// ---------------------------------------------------------------------------
// Pack int32-stored int8 values, 4 per word
// ---------------------------------------------------------------------------
__global__ __launch_bounds__(256)
void pack_i8(const int* __restrict__ src, int* __restrict__ dst, int n4)
{
    int i = blockIdx.x * 256 + threadIdx.x;
    if (i < n4) {
        int4 v = ((const int4*)src)[i];
        dst[i] = (v.x & 0xFF) | ((v.y & 0xFF) << 8) | ((v.z & 0xFF) << 16) | (v.w << 24);
    }
}

// ---------------------------------------------------------------------------
// IMMA GEMM with cp.async 2-stage pipeline. BM=BN=128, BK=32 words.
// 8 warps = 2(m) x 4(n); warp tile m64 x n32.
// omode: 0 = bf16 [m*ldc+n]; 1 = bf16 head-major; 2 = float32 of bf16(v)
// ---------------------------------------------------------------------------
#define GST 36
constexpr int GEMM_SMEM = 4 * 128 * GST * 4;   // 2 stages x (A+B) = 73728 B

__global__ __launch_bounds__(256)
void gemm_imma(const int* __restrict__ Ap, const int* __restrict__ Bp,
               const float* __restrict__ asc, const float* __restrict__ bsc,
               void* __restrict__ Cv, int ldc, int omode)
{
    extern __shared__ int gsm[];
    int* As = gsm;                       // [2][128*GST]
    int* Bs = gsm + 2 * 128 * GST;       // [2][128*GST]
    const uint32_t aB = (uint32_t)__cvta_generic_to_shared(As);
    const uint32_t bB = (uint32_t)__cvta_generic_to_shared(Bs);

    const int tid = threadIdx.x;
    const int w = tid >> 5, lane = tid & 31;
    const int g = lane >> 2, t4 = lane & 3;
    const int wm = w >> 2, wn = w & 3;
    const int m0 = blockIdx.y * 128, n0 = blockIdx.x * 128;
    const int lrow = tid >> 1, lhalf = (tid & 1) * 16;

    const int* gaRow = Ap + (size_t)(m0 + lrow) * PKP + lhalf;
    const int* gbRow = Bp + (size_t)(n0 + lrow) * PKP + lhalf;
    const uint32_t sOff = (uint32_t)(lrow * GST + lhalf) * 4;

    uint32_t acc[4][4][4];
#pragma unroll
    for (int mt = 0; mt < 4; mt++)
#pragma unroll
        for (int nt = 0; nt < 4; nt++)
#pragma unroll
            for (int c = 0; c < 4; c++) acc[mt][nt][c] = 0;

    // prologue: stage 0
    {
        uint32_t da = aB + sOff, db = bB + sOff;
#pragma unroll
        for (int p = 0; p < 4; p++) {
            CP_ASYNC16(da + p * 16, gaRow + p * 4);
            CP_ASYNC16(db + p * 16, gbRow + p * 4);
        }
        CP_COMMIT();
    }

    for (int kt = 0; kt < 16; kt++) {
        const int cur = kt & 1;
        if (kt < 15) {
            const int nxt = cur ^ 1;
            uint32_t da = aB + (uint32_t)(nxt * 128 * GST) * 4 + sOff;
            uint32_t db = bB + (uint32_t)(nxt * 128 * GST) * 4 + sOff;
            const int* ga = gaRow + (kt + 1) * 32;
            const int* gb = gbRow + (kt + 1) * 32;
#pragma unroll
            for (int p = 0; p < 4; p++) {
                CP_ASYNC16(da + p * 16, ga + p * 4);
                CP_ASYNC16(db + p * 16, gb + p * 4);
            }
            CP_COMMIT();
            CP_WAIT(1);
        } else {
            CP_WAIT(0);
        }
        __syncthreads();

        const int* Ac = As + cur * 128 * GST;
        const int* Bc = Bs + cur * 128 * GST;
#pragma unroll
        for (int ks = 0; ks < 4; ks++) {
            uint32_t a[4][4];
#pragma unroll
            for (int mt = 0; mt < 4; mt++) {
                int base = (wm * 64 + mt * 16 + g) * GST + ks * 8 + t4;
                a[mt][0] = Ac[base];
                a[mt][1] = Ac[base + 8 * GST];
                a[mt][2] = Ac[base + 4];
                a[mt][3] = Ac[base + 8 * GST + 4];
            }
#pragma unroll
            for (int nt = 0; nt < 4; nt++) {
                int bbase = (wn * 32 + nt * 8 + g) * GST + ks * 8 + t4;
                uint32_t b[2] = { (uint32_t)Bc[bbase], (uint32_t)Bc[bbase + 4] };
#pragma unroll
                for (int mt = 0; mt < 4; mt++)
                    IMMA16832(acc[mt][nt], a[mt], b);
            }
        }
        __syncthreads();
    }

    // epilogue
#pragma unroll
    for (int mt = 0; mt < 4; mt++) {
        int r0 = m0 + wm * 64 + mt * 16 + g;
        int r1 = r0 + 8;
        float a0 = asc[r0], a1 = asc[r1];
#pragma unroll
        for (int nt = 0; nt < 4; nt++) {
            int n = n0 + wn * 32 + nt * 8 + t4 * 2;
            float b0 = bsc[n], b1 = bsc[n + 1];
            float v00 = (float)(int)acc[mt][nt][0] * a0 * b0;
            float v01 = (float)(int)acc[mt][nt][1] * a0 * b1;
            float v10 = (float)(int)acc[mt][nt][2] * a1 * b0;
            float v11 = (float)(int)acc[mt][nt][3] * a1 * b1;
            if (omode == 0) {
                __nv_bfloat16* C = (__nv_bfloat16*)Cv;
                C[(size_t)r0 * ldc + n]     = __float2bfloat16(v00);
                C[(size_t)r0 * ldc + n + 1] = __float2bfloat16(v01);
                C[(size_t)r1 * ldc + n]     = __float2bfloat16(v10);
                C[(size_t)r1 * ldc + n + 1] = __float2bfloat16(v11);
            } else if (omode == 1) {
                __nv_bfloat16* C = (__nv_bfloat16*)Cv;
                C[((size_t)(n >> 7) * PS + r0) * PDH + (n & 127)]             = __float2bfloat16(v00);
                C[((size_t)((n + 1) >> 7) * PS + r0) * PDH + ((n + 1) & 127)] = __float2bfloat16(v01);
                C[((size_t)(n >> 7) * PS + r1) * PDH + (n & 127)]             = __float2bfloat16(v10);
                C[((size_t)((n + 1) >> 7) * PS + r1) * PDH + ((n + 1) & 127)] = __float2bfloat16(v11);
            } else {
                float* C = (float*)Cv;
                C[(size_t)r0 * ldc + n]     = __bfloat162float(__float2bfloat16(v00));
                C[(size_t)r0 * ldc + n + 1] = __bfloat162float(__float2bfloat16(v01));
                C[(size_t)r1 * ldc + n]     = __bfloat162float(__float2bfloat16(v10));
                C[(size_t)r1 * ldc + n + 1] = __bfloat162float(__float2bfloat16(v11));
            }
        }
    }
}

// ---------------------------------------------------------------------------
// RMSNorm + RoPE, one block (128 threads) per (token, head).
// ---------------------------------------------------------------------------
__global__ __launch_bounds__(128)
void norm_rope2(const __nv_bfloat16* __restrict__ in, const float* __restrict__ nw,
                const float* __restrict__ cosp, const float* __restrict__ sinp,
                __nv_bfloat16* __restrict__ out, int nh)
{
    __shared__ float ss[128];
    __shared__ float ys[128];
    const int s = blockIdx.x, h = blockIdx.y, t = threadIdx.x;

    float x = __bfloat162float(in[((size_t)s * nh + h) * PDH + t]);
    ss[t] = x * x;
    __syncthreads();
    for (int o = 64; o > 0; o >>= 1) {
        if (t < o) ss[t] += ss[t + o];
        __syncthreads();
    }
    float r = rsqrtf(ss[0] * (1.0f / 128.0f) + 1e-6f);

    float y = __bfloat162float(__float2bfloat16(x * r * nw[t]));
    ys[t] = y;
    __syncthreads();
    float rh = (t < 64) ? -ys[t + 64] : ys[t - 64];

    float c  = __bfloat162float(__float2bfloat16(cosp[(size_t)s * PDH + t]));
    float sn = __bfloat162float(__float2bfloat16(sinp[(size_t)s * PDH + t]));
    float t1 = __bfloat162float(__float2bfloat16(y * c));
    float t2 = __bfloat162float(__float2bfloat16(rh * sn));
    out[((size_t)h * PS + s) * PDH + t] = __float2bfloat16(t1 + t2);
}

// ---------------------------------------------------------------------------
// HMMA flash attention, causal, GQA(G=2). BM=128, BN=64, DH=128.
// ldmatrix fragments; Q frags preloaded (loop-invariant); V row-major with
// ldmatrix.trans (no scalar transpose). Split-precision P (hi+lo bf16).
// ---------------------------------------------------------------------------
#define QSTR 136
constexpr int FAM_SMEM = (128 + 64 + 64) * QSTR * 2;  // 69632 B

__device__ __forceinline__ uint32_t packbf2(float lo, float hi)
{
    __nv_bfloat162 h = __floats2bfloat162_rn(lo, hi);
    return *(uint32_t*)&h;
}

__global__ __launch_bounds__(256)
void flash_mma(const __nv_bfloat16* __restrict__ Q, const __nv_bfloat16* __restrict__ K,
               const __nv_bfloat16* __restrict__ V, const float* __restrict__ oisc,
               float* __restrict__ XO)
{
    extern __shared__ __nv_bfloat16 smb[];
    __nv_bfloat16* Qs = smb;                 // [128][QSTR]
    __nv_bfloat16* Ks = Qs + 128 * QSTR;     // [64][QSTR]
    __nv_bfloat16* Vs = Ks + 64 * QSTR;      // [64][QSTR] row-major
    const uint32_t qsB = (uint32_t)__cvta_generic_to_shared(Qs);
    const uint32_t ksB = (uint32_t)__cvta_generic_to_shared(Ks);
    const uint32_t vsB = (uint32_t)__cvta_generic_to_shared(Vs);

    const int tid  = threadIdx.x;
    const int w    = tid >> 5, lane = tid & 31;
    const int g    = lane >> 2, t4 = lane & 3;
    const int wi   = lane & 15, hi = lane >> 4;
    const int qb   = 31 - blockIdx.x;
    const int h    = blockIdx.y, hk = h >> 1;

    const __nv_bfloat16* Qg = Q + ((size_t)h * PS + qb * 128) * PDH;
    const __nv_bfloat16* Kg = K + (size_t)hk * PS * PDH;
    const __nv_bfloat16* Vg = V + (size_t)hk * PS * PDH;

    // Q tile -> smem
    {
        int row = tid >> 1, dhb = (tid & 1) * 64;
        const uint4* src = (const uint4*)(Qg + (size_t)row * PDH + dhb);
        uint4* dst = (uint4*)(Qs + row * QSTR + dhb);
#pragma unroll
        for (int i = 0; i < 8; i++) dst[i] = src[i];
    }
    __syncthreads();

    // preload Q fragments (invariant over jt): 8 kt x 4 regs
    uint32_t qa[8][4];
#pragma unroll
    for (int kt = 0; kt < 8; kt++) {
        uint32_t addr = qsB + (uint32_t)(((w * 16 + wi) * QSTR + kt * 16 + hi * 8) * 2);
        LDSM4(qa[kt][0], qa[kt][1], qa[kt][2], qa[kt][3], addr);
    }

    float oac[16][4];
#pragma unroll
    for (int n = 0; n < 16; n++)
#pragma unroll
        for (int c = 0; c < 4; c++) oac[n][c] = 0.0f;
    float li0 = 0.0f, li1 = 0.0f;
    const float scale = 0.08838834764831845f;

    const int gr0 = qb * 128 + w * 16 + g;
    const int gr1 = gr0 + 8;
    const int jtmax = 2 * qb + 1;

    for (int jt = 0; jt <= jtmax; jt++) {
        __syncthreads();
        {
            int row = tid >> 2, dhb = (tid & 3) * 32;
            const uint4* sk = (const uint4*)(Kg + (size_t)(jt * 64 + row) * PDH + dhb);
            const uint4* sv = (const uint4*)(Vg + (size_t)(jt * 64 + row) * PDH + dhb);
            uint4* dk = (uint4*)(Ks + row * QSTR + dhb);
            uint4* dv = (uint4*)(Vs + row * QSTR + dhb);
#pragma unroll
            for (int i = 0; i < 4; i++) { dk[i] = sk[i]; dv[i] = sv[i]; }
        }
        __syncthreads();

        // ----- S = Q K^T -----
        float sc[8][4];
#pragma unroll
        for (int n = 0; n < 8; n++)
#pragma unroll
            for (int c = 0; c < 4; c++) sc[n][c] = 0.0f;

#pragma unroll
        for (int kt = 0; kt < 8; kt++) {
#pragma unroll
            for (int ntp = 0; ntp < 4; ntp++) {
                uint32_t b0, b1, b2, b3;
                uint32_t addr = ksB + (uint32_t)(((ntp * 16 + hi * 8 + (wi & 7)) * QSTR
                                                  + kt * 16 + (wi >> 3) * 8) * 2);
                LDSM4(b0, b1, b2, b3, addr);
                uint32_t bA[2] = { b0, b1 };
                uint32_t bB2[2] = { b2, b3 };
                MMA16816(sc[ntp * 2],     qa[kt], bA);
                MMA16816(sc[ntp * 2 + 1], qa[kt], bB2);
            }
        }

        // ----- softmax (no max-subtraction), causal, row sums -----
        float rs0 = 0.0f, rs1 = 0.0f;
        const int colb = jt * 64 + t4 * 2;
#pragma unroll
        for (int nt = 0; nt < 8; nt++) {
            int c0 = colb + nt * 8;
            float p0 = (c0     <= gr0) ? __expf(sc[nt][0] * scale) : 0.0f;
            float p1 = (c0 + 1 <= gr0) ? __expf(sc[nt][1] * scale) : 0.0f;
            float p2 = (c0     <= gr1) ? __expf(sc[nt][2] * scale) : 0.0f;
            float p3 = (c0 + 1 <= gr1) ? __expf(sc[nt][3] * scale) : 0.0f;
            sc[nt][0] = p0; sc[nt][1] = p1; sc[nt][2] = p2; sc[nt][3] = p3;
            rs0 += p0 + p1;
            rs1 += p2 + p3;
        }
        rs0 += __shfl_xor_sync(0xffffffffu, rs0, 1);
        rs0 += __shfl_xor_sync(0xffffffffu, rs0, 2);
        rs1 += __shfl_xor_sync(0xffffffffu, rs1, 1);
        rs1 += __shfl_xor_sync(0xffffffffu, rs1, 2);
        li0 += rs0;
        li1 += rs1;

        // ----- repack P hi/lo bf16 A-fragments -----
        uint32_t Phi[4][4], Plo[4][4];
#pragma unroll
        for (int kt = 0; kt < 4; kt++) {
#pragma unroll
            for (int hv = 0; hv < 2; hv++) {
                float* c = sc[2 * kt + hv];
                __nv_bfloat16 h0 = __float2bfloat16_rn(c[0]);
                __nv_bfloat16 h1 = __float2bfloat16_rn(c[1]);
                __nv_bfloat16 h2 = __float2bfloat16_rn(c[2]);
                __nv_bfloat16 h3 = __float2bfloat16_rn(c[3]);
                float l0 = c[0] - __bfloat162float(h0);
                float l1 = c[1] - __bfloat162float(h1);
                float l2 = c[2] - __bfloat162float(h2);
                float l3 = c[3] - __bfloat162float(h3);
                Phi[kt][hv * 2 + 0] = ((uint32_t)*(uint16_t*)&h1 << 16) | *(uint16_t*)&h0;
                Phi[kt][hv * 2 + 1] = ((uint32_t)*(uint16_t*)&h3 << 16) | *(uint16_t*)&h2;
                Plo[kt][hv * 2 + 0] = packbf2(l0, l1);
                Plo[kt][hv * 2 + 1] = packbf2(l2, l3);
            }
        }

        // ----- O += P * V  (V frags via ldmatrix.trans) -----
#pragma unroll
        for (int kt = 0; kt < 4; kt++) {
#pragma unroll
            for (int ntp = 0; ntp < 8; ntp++) {
                uint32_t b0, b1, b2, b3;
                uint32_t addr = vsB + (uint32_t)(((kt * 16 + wi) * QSTR
                                                  + ntp * 16 + hi * 8) * 2);
                LDSM4T(b0, b1, b2, b3, addr);
                uint32_t bA[2] = { b0, b1 };
                uint32_t bB2[2] = { b2, b3 };
                MMA16816(oac[ntp * 2],     Phi[kt], bA);
                MMA16816(oac[ntp * 2],     Plo[kt], bA);
                MMA16816(oac[ntp * 2 + 1], Phi[kt], bB2);
                MMA16816(oac[ntp * 2 + 1], Plo[kt], bB2);
            }
        }
    }

    // ----- epilogue -----
    const float inv0 = 1.0f / li0;
    const float inv1 = 1.0f / li1;
#pragma unroll
    for (int nt2 = 0; nt2 < 16; nt2++) {
        int oc = h * PDH + nt2 * 8 + t4 * 2;
        float s0 = oisc[oc], s1 = oisc[oc + 1];
        XO[(size_t)gr0 * PDM + oc]     = oac[nt2][0] * inv0 / s0;
        XO[(size_t)gr0 * PDM + oc + 1] = oac[nt2][1] * inv0 / s1;
        XO[(size_t)gr1 * PDM + oc]     = oac[nt2][2] * inv1 / s0;
        XO[(size_t)gr1 * PDM + oc + 1] = oac[nt2][3] * inv1 / s1;
    }
}

// ---------------------------------------------------------------------------
// Per-token int8 quantization + packing.
// ---------------------------------------------------------------------------
__global__ __launch_bounds__(256)
void quant2(const float* __restrict__ XO, int* __restrict__ Xq, float* __restrict__ Xs)
{
    __shared__ float red[256];
    const int t = blockIdx.x, tid = threadIdx.x;

    float v[8];
    float m = 0.0f;
#pragma unroll
    for (int i = 0; i < 8; i++) {
        v[i] = XO[(size_t)t * PDM + tid * 8 + i];
        m = fmaxf(m, fabsf(v[i]));
    }
    red[tid] = m;
    __syncthreads();
    for (int o = 128; o > 0; o >>= 1) {
        if (tid < o) red[tid] = fmaxf(red[tid], red[tid + o]);
        __syncthreads();
    }
    float sc = fmaxf(red[0] * (1.0f / 127.0f), 1e-7f);

    int q[8];
#pragma unroll
    for (int i = 0; i < 8; i++)
        q[i] = (int)fminf(fmaxf(rintf(v[i] / sc), -128.0f), 127.0f);
    int p0 = (q[0] & 0xFF) | ((q[1] & 0xFF) << 8) | ((q[2] & 0xFF) << 16) | (q[3] << 24);
    int p1 = (q[4] & 0xFF) | ((q[5] & 0xFF) << 8) | ((q[6] & 0xFF) << 16) | (q[7] << 24);
    Xq[(size_t)t * PKP + tid * 2]     = p0;
    Xq[(size_t)t * PKP + tid * 2 + 1] = p1;
    if (tid == 0) Xs[t] = sc;
}

// ---------------------------------------------------------------------------
// Launch
// ---------------------------------------------------------------------------
extern "C" void kernel_launch(void* const* d_in, const int* in_sizes, int n_in,
                              void* d_out, int out_size)
{
    const int*   x_i8 = (const int*)d_in[0];
    const float* x_s  = (const float*)d_in[1];
    const float* cosp = (const float*)d_in[3];
    const float* sinp = (const float*)d_in[4];
    const int*   q_w  = (const int*)d_in[5];
    const float* q_ws = (const float*)d_in[6];
    const int*   k_w  = (const int*)d_in[7];
    const float* k_ws = (const float*)d_in[8];
    const int*   v_w  = (const int*)d_in[9];
    const float* v_ws = (const float*)d_in[10];
    const int*   o_w  = (const int*)d_in[11];
    const float* o_ws = (const float*)d_in[12];
    const float* o_is = (const float*)d_in[13];
    const float* qnw  = (const float*)d_in[14];
    const float* knw  = (const float*)d_in[15];

    unsigned char* base = nullptr;
    cudaGetSymbolAddress((void**)&base, g_scratch);

    int*           xp  = (int*)(base + OFF_XP);
    int*           qwp = (int*)(base + OFF_QWP);
    int*           kwp = (int*)(base + OFF_KWP);
    int*           vwp = (int*)(base + OFF_VWP);
    int*           owp = (int*)(base + OFF_OWP);
    __nv_bfloat16* qq  = (__nv_bfloat16*)(base + OFF_QQ);
    __nv_bfloat16* qk  = (__nv_bfloat16*)(base + OFF_QK);
    __nv_bfloat16* qf  = (__nv_bfloat16*)(base + OFF_QF);
    __nv_bfloat16* kf  = (__nv_bfloat16*)(base + OFF_KF);
    __nv_bfloat16* vf  = (__nv_bfloat16*)(base + OFF_VF);
    float*         xo  = (float*)(base + OFF_XO);
    int*           xoq = (int*)(base + OFF_XOQ);
    float*         xos = (float*)(base + OFF_XOS);

    cudaFuncSetAttribute(gemm_imma, cudaFuncAttributeMaxDynamicSharedMemorySize, GEMM_SMEM);
    cudaFuncSetAttribute(flash_mma, cudaFuncAttributeMaxDynamicSharedMemorySize, FAM_SMEM);

    // pack
    pack_i8<<<(PS * PKP) / 256, 256>>>(x_i8, xp, PS * PKP);
    pack_i8<<<(2048 * PKP) / 256, 256>>>(q_w, qwp, 2048 * PKP);
    pack_i8<<<(1024 * PKP) / 256, 256>>>(k_w, kwp, 1024 * PKP);
    pack_i8<<<(1024 * PKP) / 256, 256>>>(v_w, vwp, 1024 * PKP);
    pack_i8<<<(2048 * PKP) / 256, 256>>>(o_w, owp, 2048 * PKP);

    // QKV projections via pipelined IMMA
    gemm_imma<<<dim3(16, 32), 256, GEMM_SMEM>>>(xp, qwp, x_s, q_ws, qq, 2048, 0);
    gemm_imma<<<dim3(8, 32),  256, GEMM_SMEM>>>(xp, kwp, x_s, k_ws, qk, 1024, 0);
    gemm_imma<<<dim3(8, 32),  256, GEMM_SMEM>>>(xp, vwp, x_s, v_ws, vf, 0,    1);

    // rmsnorm + rope -> head-major
    norm_rope2<<<dim3(PS, PNH),  128>>>(qq, qnw, cosp, sinp, qf, PNH);
    norm_rope2<<<dim3(PS, PNHK), 128>>>(qk, knw, cosp, sinp, kf, PNHK);

    // flash attention
    flash_mma<<<dim3(32, PNH), 256, FAM_SMEM>>>(qf, kf, vf, o_is, xo);

    // per-token quant + pack
    quant2<<<PS, 256>>>(xo, xoq, xos);

    // o-proj -> FLOAT32 output (bf16-rounded values)
    gemm_imma<<<dim3(16, 32), 256, GEMM_SMEM>>>(xoq, owp, xos, o_ws, d_out, 2048, 2);
}

// round 15
// speedup vs baseline: 5.5993x; 1.0470x over previous
#include <cuda_runtime.h>
#include <cuda_bf16.h>
#include <cstdint>

#define PS   4096
#define PDM  2048
#define PNH  16
#define PNHK 8
#define PDH  128
#define PKP  512

// ---------------------------------------------------------------------------
// Scratch
// ---------------------------------------------------------------------------
constexpr size_t SZ_XP  = (size_t)PS * PKP * 4;
constexpr size_t SZ_QWP = (size_t)2048 * PKP * 4;
constexpr size_t SZ_KWP = (size_t)1024 * PKP * 4;
constexpr size_t SZ_VWP = (size_t)1024 * PKP * 4;
constexpr size_t SZ_OWP = (size_t)2048 * PKP * 4;
constexpr size_t SZ_QQ  = (size_t)PS * 2048 * 2;
constexpr size_t SZ_QK  = (size_t)PS * 1024 * 2;
constexpr size_t SZ_QF  = (size_t)PNH  * PS * PDH * 2;
constexpr size_t SZ_KF  = (size_t)PNHK * PS * PDH * 2;
constexpr size_t SZ_VF  = (size_t)PNHK * PS * PDH * 2;
constexpr size_t SZ_XO  = (size_t)PS * PDM * 4;
constexpr size_t SZ_XOQ = (size_t)PS * PKP * 4;
constexpr size_t SZ_XOS = (size_t)PS * 4;

constexpr size_t OFF_XP  = 0;
constexpr size_t OFF_QWP = OFF_XP  + SZ_XP;
constexpr size_t OFF_KWP = OFF_QWP + SZ_QWP;
constexpr size_t OFF_VWP = OFF_KWP + SZ_KWP;
constexpr size_t OFF_OWP = OFF_VWP + SZ_VWP;
constexpr size_t OFF_QQ  = OFF_OWP + SZ_OWP;
constexpr size_t OFF_QK  = OFF_QQ  + SZ_QQ;
constexpr size_t OFF_QF  = OFF_QK  + SZ_QK;
constexpr size_t OFF_KF  = OFF_QF  + SZ_QF;
constexpr size_t OFF_VF  = OFF_KF  + SZ_KF;
constexpr size_t OFF_XO  = OFF_VF  + SZ_VF;
constexpr size_t OFF_XOQ = OFF_XO  + SZ_XO;
constexpr size_t OFF_XOS = OFF_XOQ + SZ_XOQ;
constexpr size_t SCRATCH_BYTES = OFF_XOS + SZ_XOS;

__device__ __align__(256) unsigned char g_scratch[SCRATCH_BYTES];

// ---------------------------------------------------------------------------
// PTX helpers
// ---------------------------------------------------------------------------
#define CP_ASYNC16(dst, src) \
    asm volatile("cp.async.cg.shared.global [%0], [%1], 16;" :: "r"(dst), "l"(src))
#define CP_COMMIT() asm volatile("cp.async.commit_group;")
#define CP_WAIT0()  asm volatile("cp.async.wait_group 0;")
#define CP_WAIT1()  asm volatile("cp.async.wait_group 1;")

#define IMMA16832(d, a, b) \
    asm volatile("mma.sync.aligned.m16n8k32.row.col.s32.s8.s8.s32 " \
                 "{%0,%1,%2,%3}, {%4,%5,%6,%7}, {%8,%9}, {%0,%1,%2,%3};" \
                 : "+r"(d[0]), "+r"(d[1]), "+r"(d[2]), "+r"(d[3]) \
                 : "r"(a[0]), "r"(a[1]), "r"(a[2]), "r"(a[3]), "r"(b[0]), "r"(b[1]))

#define MMA16816(d, a, b) \
    asm volatile("mma.sync.aligned.m16n8k16.row.col.f32.bf16.bf16.f32 " \
                 "{%0,%1,%2,%3}, {%4,%5,%6,%7}, {%8,%9}, {%0,%1,%2,%3};" \
                 : "+f"(d[0]), "+f"(d[1]), "+f"(d[2]), "+f"(d[3]) \
                 : "r"(a[0]), "r"(a[1]), "r"(a[2]), "r"(a[3]), "r"(b[0]), "r"(b[1]))

#define LDSM4(r0, r1, r2, r3, addr) \
    asm volatile("ldmatrix.sync.aligned.m8n8.x4.shared.b16 {%0,%1,%2,%3}, [%4];" \
                 : "=r"(r0), "=r"(r1), "=r"(r2), "=r"(r3) : "r"(addr))

#define LDSM4T(r0, r1, r2, r3, addr) \
    asm volatile("ldmatrix.sync.aligned.m8n8.x4.trans.shared.b16 {%0,%1,%2,%3}, [%4];" \
                 : "=r"(r0), "=r"(r1), "=r"(r2), "=r"(r3) : "r"(addr))

// ---------------------------------------------------------------------------
// Fused pack: all 5 regions in one launch (dst regions contiguous in scratch)
// word counts: x 2097152 | qw 1048576 | kw 524288 | vw 524288 | ow 1048576
// ---------------------------------------------------------------------------
__global__ __launch_bounds__(256)
void pack_all(const int* __restrict__ x, const int* __restrict__ qw,
              const int* __restrict__ kw, const int* __restrict__ vw,
              const int* __restrict__ ow, int* __restrict__ dst)
{
    int i = blockIdx.x * 256 + threadIdx.x;
    const int* src;
    int li = i;
    if (i < 2097152)            { src = x;  }
    else if (i < 3145728)       { src = qw; li = i - 2097152; }
    else if (i < 3670016)       { src = kw; li = i - 3145728; }
    else if (i < 4194304)       { src = vw; li = i - 3670016; }
    else                        { src = ow; li = i - 4194304; }
    int4 v = ((const int4*)src)[li];
    dst[i] = (v.x & 0xFF) | ((v.y & 0xFF) << 8) | ((v.z & 0xFF) << 16) | (v.w << 24);
}

// ---------------------------------------------------------------------------
// IMMA GEMM, 3-stage cp.async ring, one barrier per k-tile.
// BM=BN=128, BK=32 words; 8 warps = 2(m) x 4(n).
// omode: 0 = bf16 [m*ldc+n]; 1 = bf16 head-major; 2 = float32 of bf16(v)
// ---------------------------------------------------------------------------
#define GST 36
constexpr int GEMM_SMEM = 6 * 128 * GST * 4;   // 3 stages x (A+B) = 110592 B

__global__ __launch_bounds__(256)
void gemm_imma(const int* __restrict__ Ap, const int* __restrict__ Bp,
               const float* __restrict__ asc, const float* __restrict__ bsc,
               void* __restrict__ Cv, int ldc, int omode)
{
    extern __shared__ int gsm[];
    int* As = gsm;                       // [3][128*GST]
    int* Bs = gsm + 3 * 128 * GST;       // [3][128*GST]
    const uint32_t aB = (uint32_t)__cvta_generic_to_shared(As);
    const uint32_t bB = (uint32_t)__cvta_generic_to_shared(Bs);

    const int tid = threadIdx.x;
    const int w = tid >> 5, lane = tid & 31;
    const int g = lane >> 2, t4 = lane & 3;
    const int wm = w >> 2, wn = w & 3;
    const int m0 = blockIdx.y * 128, n0 = blockIdx.x * 128;
    const int lrow = tid >> 1, lhalf = (tid & 1) * 16;

    const int* gaRow = Ap + (size_t)(m0 + lrow) * PKP + lhalf;
    const int* gbRow = Bp + (size_t)(n0 + lrow) * PKP + lhalf;
    const uint32_t sOff = (uint32_t)(lrow * GST + lhalf) * 4;

    uint32_t acc[4][4][4];
#pragma unroll
    for (int mt = 0; mt < 4; mt++)
#pragma unroll
        for (int nt = 0; nt < 4; nt++)
#pragma unroll
            for (int c = 0; c < 4; c++) acc[mt][nt][c] = 0;

    // prologue: stages 0,1
#pragma unroll
    for (int s = 0; s < 2; s++) {
        uint32_t da = aB + (uint32_t)(s * 128 * GST) * 4 + sOff;
        uint32_t db = bB + (uint32_t)(s * 128 * GST) * 4 + sOff;
#pragma unroll
        for (int p = 0; p < 4; p++) {
            CP_ASYNC16(da + p * 16, gaRow + s * 32 + p * 4);
            CP_ASYNC16(db + p * 16, gbRow + s * 32 + p * 4);
        }
        CP_COMMIT();
    }

    for (int kt = 0; kt < 16; kt++) {
        if (kt < 15) { CP_WAIT1(); } else { CP_WAIT0(); }
        __syncthreads();   // stage kt visible; compute(kt-1) finished by all

        if (kt + 2 < 16) {
            const int slot = (kt + 2) % 3;
            uint32_t da = aB + (uint32_t)(slot * 128 * GST) * 4 + sOff;
            uint32_t db = bB + (uint32_t)(slot * 128 * GST) * 4 + sOff;
            const int* ga = gaRow + (kt + 2) * 32;
            const int* gb = gbRow + (kt + 2) * 32;
#pragma unroll
            for (int p = 0; p < 4; p++) {
                CP_ASYNC16(da + p * 16, ga + p * 4);
                CP_ASYNC16(db + p * 16, gb + p * 4);
            }
            CP_COMMIT();
        }

        const int cur = kt % 3;
        const int* Ac = As + cur * 128 * GST;
        const int* Bc = Bs + cur * 128 * GST;
#pragma unroll
        for (int ks = 0; ks < 4; ks++) {
            uint32_t a[4][4];
#pragma unroll
            for (int mt = 0; mt < 4; mt++) {
                int base = (wm * 64 + mt * 16 + g) * GST + ks * 8 + t4;
                a[mt][0] = Ac[base];
                a[mt][1] = Ac[base + 8 * GST];
                a[mt][2] = Ac[base + 4];
                a[mt][3] = Ac[base + 8 * GST + 4];
            }
#pragma unroll
            for (int nt = 0; nt < 4; nt++) {
                int bbase = (wn * 32 + nt * 8 + g) * GST + ks * 8 + t4;
                uint32_t b[2] = { (uint32_t)Bc[bbase], (uint32_t)Bc[bbase + 4] };
#pragma unroll
                for (int mt = 0; mt < 4; mt++)
                    IMMA16832(acc[mt][nt], a[mt], b);
            }
        }
    }

    // epilogue
#pragma unroll
    for (int mt = 0; mt < 4; mt++) {
        int r0 = m0 + wm * 64 + mt * 16 + g;
        int r1 = r0 + 8;
        float a0 = asc[r0], a1 = asc[r1];
#pragma unroll
        for (int nt = 0; nt < 4; nt++) {
            int n = n0 + wn * 32 + nt * 8 + t4 * 2;
            float b0 = bsc[n], b1 = bsc[n + 1];
            float v00 = (float)(int)acc[mt][nt][0] * a0 * b0;
            float v01 = (float)(int)acc[mt][nt][1] * a0 * b1;
            float v10 = (float)(int)acc[mt][nt][2] * a1 * b0;
            float v11 = (float)(int)acc[mt][nt][3] * a1 * b1;
            if (omode == 0) {
                __nv_bfloat16* C = (__nv_bfloat16*)Cv;
                C[(size_t)r0 * ldc + n]     = __float2bfloat16(v00);
                C[(size_t)r0 * ldc + n + 1] = __float2bfloat16(v01);
                C[(size_t)r1 * ldc + n]     = __float2bfloat16(v10);
                C[(size_t)r1 * ldc + n + 1] = __float2bfloat16(v11);
            } else if (omode == 1) {
                __nv_bfloat16* C = (__nv_bfloat16*)Cv;
                C[((size_t)(n >> 7) * PS + r0) * PDH + (n & 127)]             = __float2bfloat16(v00);
                C[((size_t)((n + 1) >> 7) * PS + r0) * PDH + ((n + 1) & 127)] = __float2bfloat16(v01);
                C[((size_t)(n >> 7) * PS + r1) * PDH + (n & 127)]             = __float2bfloat16(v10);
                C[((size_t)((n + 1) >> 7) * PS + r1) * PDH + ((n + 1) & 127)] = __float2bfloat16(v11);
            } else {
                float* C = (float*)Cv;
                C[(size_t)r0 * ldc + n]     = __bfloat162float(__float2bfloat16(v00));
                C[(size_t)r0 * ldc + n + 1] = __bfloat162float(__float2bfloat16(v01));
                C[(size_t)r1 * ldc + n]     = __bfloat162float(__float2bfloat16(v10));
                C[(size_t)r1 * ldc + n + 1] = __bfloat162float(__float2bfloat16(v11));
            }
        }
    }
}

// ---------------------------------------------------------------------------
// RMSNorm + RoPE, one warp per (token, head); 8 per block, no block barriers.
// ---------------------------------------------------------------------------
__global__ __launch_bounds__(256)
void norm_rope_w(const __nv_bfloat16* __restrict__ in, const float* __restrict__ nw,
                 const float* __restrict__ cosp, const float* __restrict__ sinp,
                 __nv_bfloat16* __restrict__ out, int nh)
{
    int gw = (blockIdx.x * 256 + threadIdx.x) >> 5;
    int lane = threadIdx.x & 31;
    int s = gw / nh, h = gw - s * nh;
    if (s >= PS) return;

    const __nv_bfloat16* xi = in + ((size_t)s * nh + h) * PDH;
    float x[4];
#pragma unroll
    for (int k = 0; k < 4; k++) x[k] = __bfloat162float(xi[lane + 32 * k]);

    float ss = x[0]*x[0] + x[1]*x[1] + x[2]*x[2] + x[3]*x[3];
    ss += __shfl_xor_sync(0xffffffffu, ss, 16);
    ss += __shfl_xor_sync(0xffffffffu, ss, 8);
    ss += __shfl_xor_sync(0xffffffffu, ss, 4);
    ss += __shfl_xor_sync(0xffffffffu, ss, 2);
    ss += __shfl_xor_sync(0xffffffffu, ss, 1);
    float r = rsqrtf(ss * (1.0f / 128.0f) + 1e-6f);

    float y[4];
#pragma unroll
    for (int k = 0; k < 4; k++) {
        int col = lane + 32 * k;
        y[k] = __bfloat162float(__float2bfloat16(x[k] * r * nw[col]));
    }
    float rh[4] = { -y[2], -y[3], y[0], y[1] };   // rotate_half across stride-32 groups

    __nv_bfloat16* od = out + ((size_t)h * PS + s) * PDH;
#pragma unroll
    for (int k = 0; k < 4; k++) {
        int col = lane + 32 * k;
        float c  = __bfloat162float(__float2bfloat16(cosp[(size_t)s * PDH + col]));
        float sn = __bfloat162float(__float2bfloat16(sinp[(size_t)s * PDH + col]));
        float t1 = __bfloat162float(__float2bfloat16(y[k] * c));
        float t2 = __bfloat162float(__float2bfloat16(rh[k] * sn));
        od[col] = __float2bfloat16(t1 + t2);
    }
}

// ---------------------------------------------------------------------------
// HMMA flash attention, cp.async double-buffered K/V. BM=128, BN=64.
// ---------------------------------------------------------------------------
#define QSTR 136
constexpr int FAM_SMEM = (128 + 4 * 64) * QSTR * 2;  // Q + 2x(K,V) = 104448 B

__device__ __forceinline__ uint32_t packbf2(float lo, float hi)
{
    __nv_bfloat162 h = __floats2bfloat162_rn(lo, hi);
    return *(uint32_t*)&h;
}

__global__ __launch_bounds__(256)
void flash_mma(const __nv_bfloat16* __restrict__ Q, const __nv_bfloat16* __restrict__ K,
               const __nv_bfloat16* __restrict__ V, const float* __restrict__ oisc,
               float* __restrict__ XO)
{
    extern __shared__ __nv_bfloat16 smb[];
    __nv_bfloat16* Qs = smb;                    // [128][QSTR]
    __nv_bfloat16* Ks = Qs + 128 * QSTR;        // [2][64][QSTR]
    __nv_bfloat16* Vs = Ks + 2 * 64 * QSTR;     // [2][64][QSTR]
    const uint32_t qsB = (uint32_t)__cvta_generic_to_shared(Qs);
    const uint32_t ksB = (uint32_t)__cvta_generic_to_shared(Ks);
    const uint32_t vsB = (uint32_t)__cvta_generic_to_shared(Vs);
    constexpr uint32_t STG = 64 * QSTR * 2;     // bytes per K/V stage

    const int tid  = threadIdx.x;
    const int w    = tid >> 5, lane = tid & 31;
    const int g    = lane >> 2, t4 = lane & 3;
    const int wi   = lane & 15, hi = lane >> 4;
    const int qb   = 31 - blockIdx.x;
    const int h    = blockIdx.y, hk = h >> 1;

    const __nv_bfloat16* Qg = Q + ((size_t)h * PS + qb * 128) * PDH;
    const __nv_bfloat16* Kg = K + (size_t)hk * PS * PDH;
    const __nv_bfloat16* Vg = V + (size_t)hk * PS * PDH;

    // per-thread K/V load slices (4 x 16B each for K and V)
    const int lrow = tid >> 2, ldhb = (tid & 3) * 32;
    const uint32_t lOff = (uint32_t)(lrow * QSTR + ldhb) * 2;

    // Q tile -> smem
    {
        int row = tid >> 1, dhb = (tid & 1) * 64;
        const uint4* src = (const uint4*)(Qg + (size_t)row * PDH + dhb);
        uint4* dst = (uint4*)(Qs + row * QSTR + dhb);
#pragma unroll
        for (int i = 0; i < 8; i++) dst[i] = src[i];
    }

    // prologue: async load K/V tile jt=0 into stage 0
    {
        const __nv_bfloat16* sk = Kg + (size_t)lrow * PDH + ldhb;
        const __nv_bfloat16* sv = Vg + (size_t)lrow * PDH + ldhb;
#pragma unroll
        for (int i = 0; i < 4; i++) {
            CP_ASYNC16(ksB + lOff + i * 16, sk + i * 8);
            CP_ASYNC16(vsB + lOff + i * 16, sv + i * 8);
        }
        CP_COMMIT();
    }
    __syncthreads();   // Q smem ready (scalar stores) for fragment preload

    // preload Q fragments (invariant over jt)
    uint32_t qa[8][4];
#pragma unroll
    for (int kt = 0; kt < 8; kt++) {
        uint32_t addr = qsB + (uint32_t)(((w * 16 + wi) * QSTR + kt * 16 + hi * 8) * 2);
        LDSM4(qa[kt][0], qa[kt][1], qa[kt][2], qa[kt][3], addr);
    }

    float oac[16][4];
#pragma unroll
    for (int n = 0; n < 16; n++)
#pragma unroll
        for (int c = 0; c < 4; c++) oac[n][c] = 0.0f;
    float li0 = 0.0f, li1 = 0.0f;
    const float scale = 0.08838834764831845f;

    const int gr0 = qb * 128 + w * 16 + g;
    const int gr1 = gr0 + 8;
    const int jtmax = 2 * qb + 1;

    for (int jt = 0; jt <= jtmax; jt++) {
        const uint32_t cur = (uint32_t)(jt & 1) * STG;
        CP_WAIT0();
        __syncthreads();   // stage cur visible; compute(jt-1) done by all

        if (jt < jtmax) {
            const uint32_t nxt = (uint32_t)((jt + 1) & 1) * STG;
            const __nv_bfloat16* sk = Kg + (size_t)((jt + 1) * 64 + lrow) * PDH + ldhb;
            const __nv_bfloat16* sv = Vg + (size_t)((jt + 1) * 64 + lrow) * PDH + ldhb;
#pragma unroll
            for (int i = 0; i < 4; i++) {
                CP_ASYNC16(ksB + nxt + lOff + i * 16, sk + i * 8);
                CP_ASYNC16(vsB + nxt + lOff + i * 16, sv + i * 8);
            }
            CP_COMMIT();
        }

        // ----- S = Q K^T -----
        float sc[8][4];
#pragma unroll
        for (int n = 0; n < 8; n++)
#pragma unroll
            for (int c = 0; c < 4; c++) sc[n][c] = 0.0f;

#pragma unroll
        for (int kt = 0; kt < 8; kt++) {
#pragma unroll
            for (int ntp = 0; ntp < 4; ntp++) {
                uint32_t b0, b1, b2, b3;
                uint32_t addr = ksB + cur + (uint32_t)(((ntp * 16 + hi * 8 + (wi & 7)) * QSTR
                                                        + kt * 16 + (wi >> 3) * 8) * 2);
                LDSM4(b0, b1, b2, b3, addr);
                uint32_t bA[2] = { b0, b1 };
                uint32_t bB2[2] = { b2, b3 };
                MMA16816(sc[ntp * 2],     qa[kt], bA);
                MMA16816(sc[ntp * 2 + 1], qa[kt], bB2);
            }
        }

        // ----- softmax (no max-subtraction), causal, row sums -----
        float rs0 = 0.0f, rs1 = 0.0f;
        const int colb = jt * 64 + t4 * 2;
#pragma unroll
        for (int nt = 0; nt < 8; nt++) {
            int c0 = colb + nt * 8;
            float p0 = (c0     <= gr0) ? __expf(sc[nt][0] * scale) : 0.0f;
            float p1 = (c0 + 1 <= gr0) ? __expf(sc[nt][1] * scale) : 0.0f;
            float p2 = (c0     <= gr1) ? __expf(sc[nt][2] * scale) : 0.0f;
            float p3 = (c0 + 1 <= gr1) ? __expf(sc[nt][3] * scale) : 0.0f;
            sc[nt][0] = p0; sc[nt][1] = p1; sc[nt][2] = p2; sc[nt][3] = p3;
            rs0 += p0 + p1;
            rs1 += p2 + p3;
        }
        rs0 += __shfl_xor_sync(0xffffffffu, rs0, 1);
        rs0 += __shfl_xor_sync(0xffffffffu, rs0, 2);
        rs1 += __shfl_xor_sync(0xffffffffu, rs1, 1);
        rs1 += __shfl_xor_sync(0xffffffffu, rs1, 2);
        li0 += rs0;
        li1 += rs1;

        // ----- repack P hi/lo bf16 A-fragments -----
        uint32_t Phi[4][4], Plo[4][4];
#pragma unroll
        for (int kt = 0; kt < 4; kt++) {
#pragma unroll
            for (int hv = 0; hv < 2; hv++) {
                float* c = sc[2 * kt + hv];
                __nv_bfloat16 h0 = __float2bfloat16_rn(c[0]);
                __nv_bfloat16 h1 = __float2bfloat16_rn(c[1]);
                __nv_bfloat16 h2 = __float2bfloat16_rn(c[2]);
                __nv_bfloat16 h3 = __float2bfloat16_rn(c[3]);
                float l0 = c[0] - __bfloat162float(h0);
                float l1 = c[1] - __bfloat162float(h1);
                float l2 = c[2] - __bfloat162float(h2);
                float l3 = c[3] - __bfloat162float(h3);
                Phi[kt][hv * 2 + 0] = ((uint32_t)*(uint16_t*)&h1 << 16) | *(uint16_t*)&h0;
                Phi[kt][hv * 2 + 1] = ((uint32_t)*(uint16_t*)&h3 << 16) | *(uint16_t*)&h2;
                Plo[kt][hv * 2 + 0] = packbf2(l0, l1);
                Plo[kt][hv * 2 + 1] = packbf2(l2, l3);
            }
        }

        // ----- O += P * V  (V frags via ldmatrix.trans) -----
#pragma unroll
        for (int kt = 0; kt < 4; kt++) {
#pragma unroll
            for (int ntp = 0; ntp < 8; ntp++) {
                uint32_t b0, b1, b2, b3;
                uint32_t addr = vsB + cur + (uint32_t)(((kt * 16 + wi) * QSTR
                                                        + ntp * 16 + hi * 8) * 2);
                LDSM4T(b0, b1, b2, b3, addr);
                uint32_t bA[2] = { b0, b1 };
                uint32_t bB2[2] = { b2, b3 };
                MMA16816(oac[ntp * 2],     Phi[kt], bA);
                MMA16816(oac[ntp * 2],     Plo[kt], bA);
                MMA16816(oac[ntp * 2 + 1], Phi[kt], bB2);
                MMA16816(oac[ntp * 2 + 1], Plo[kt], bB2);
            }
        }
    }

    // ----- epilogue -----
    const float inv0 = 1.0f / li0;
    const float inv1 = 1.0f / li1;
#pragma unroll
    for (int nt2 = 0; nt2 < 16; nt2++) {
        int oc = h * PDH + nt2 * 8 + t4 * 2;
        float s0 = oisc[oc], s1 = oisc[oc + 1];
        XO[(size_t)gr0 * PDM + oc]     = oac[nt2][0] * inv0 / s0;
        XO[(size_t)gr0 * PDM + oc + 1] = oac[nt2][1] * inv0 / s1;
        XO[(size_t)gr1 * PDM + oc]     = oac[nt2][2] * inv1 / s0;
        XO[(size_t)gr1 * PDM + oc + 1] = oac[nt2][3] * inv1 / s1;
    }
}

// ---------------------------------------------------------------------------
// Per-token int8 quantization + packing.
// ---------------------------------------------------------------------------
__global__ __launch_bounds__(256)
void quant2(const float* __restrict__ XO, int* __restrict__ Xq, float* __restrict__ Xs)
{
    __shared__ float red[256];
    const int t = blockIdx.x, tid = threadIdx.x;

    float v[8];
    float m = 0.0f;
#pragma unroll
    for (int i = 0; i < 8; i++) {
        v[i] = XO[(size_t)t * PDM + tid * 8 + i];
        m = fmaxf(m, fabsf(v[i]));
    }
    red[tid] = m;
    __syncthreads();
    for (int o = 128; o > 0; o >>= 1) {
        if (tid < o) red[tid] = fmaxf(red[tid], red[tid + o]);
        __syncthreads();
    }
    float sc = fmaxf(red[0] * (1.0f / 127.0f), 1e-7f);

    int q[8];
#pragma unroll
    for (int i = 0; i < 8; i++)
        q[i] = (int)fminf(fmaxf(rintf(v[i] / sc), -128.0f), 127.0f);
    int p0 = (q[0] & 0xFF) | ((q[1] & 0xFF) << 8) | ((q[2] & 0xFF) << 16) | (q[3] << 24);
    int p1 = (q[4] & 0xFF) | ((q[5] & 0xFF) << 8) | ((q[6] & 0xFF) << 16) | (q[7] << 24);
    Xq[(size_t)t * PKP + tid * 2]     = p0;
    Xq[(size_t)t * PKP + tid * 2 + 1] = p1;
    if (tid == 0) Xs[t] = sc;
}

// ---------------------------------------------------------------------------
// Launch
// ---------------------------------------------------------------------------
extern "C" void kernel_launch(void* const* d_in, const int* in_sizes, int n_in,
                              void* d_out, int out_size)
{
    const int*   x_i8 = (const int*)d_in[0];
    const float* x_s  = (const float*)d_in[1];
    const float* cosp = (const float*)d_in[3];
    const float* sinp = (const float*)d_in[4];
    const int*   q_w  = (const int*)d_in[5];
    const float* q_ws = (const float*)d_in[6];
    const int*   k_w  = (const int*)d_in[7];
    const float* k_ws = (const float*)d_in[8];
    const int*   v_w  = (const int*)d_in[9];
    const float* v_ws = (const float*)d_in[10];
    const int*   o_w  = (const int*)d_in[11];
    const float* o_ws = (const float*)d_in[12];
    const float* o_is = (const float*)d_in[13];
    const float* qnw  = (const float*)d_in[14];
    const float* knw  = (const float*)d_in[15];

    unsigned char* base = nullptr;
    cudaGetSymbolAddress((void**)&base, g_scratch);

    int*           xp  = (int*)(base + OFF_XP);
    int*           qwp = (int*)(base + OFF_QWP);
    int*           kwp = (int*)(base + OFF_KWP);
    int*           vwp = (int*)(base + OFF_VWP);
    int*           owp = (int*)(base + OFF_OWP);
    __nv_bfloat16* qq  = (__nv_bfloat16*)(base + OFF_QQ);
    __nv_bfloat16* qk  = (__nv_bfloat16*)(base + OFF_QK);
    __nv_bfloat16* qf  = (__nv_bfloat16*)(base + OFF_QF);
    __nv_bfloat16* kf  = (__nv_bfloat16*)(base + OFF_KF);
    __nv_bfloat16* vf  = (__nv_bfloat16*)(base + OFF_VF);
    float*         xo  = (float*)(base + OFF_XO);
    int*           xoq = (int*)(base + OFF_XOQ);
    float*         xos = (float*)(base + OFF_XOS);

    cudaFuncSetAttribute(gemm_imma, cudaFuncAttributeMaxDynamicSharedMemorySize, GEMM_SMEM);
    cudaFuncSetAttribute(flash_mma, cudaFuncAttributeMaxDynamicSharedMemorySize, FAM_SMEM);

    // fused pack (dst regions contiguous: xp|qwp|kwp|vwp|owp)
    pack_all<<<5242880 / 256, 256>>>(x_i8, q_w, k_w, v_w, o_w, xp);

    // QKV projections via 3-stage pipelined IMMA
    gemm_imma<<<dim3(16, 32), 256, GEMM_SMEM>>>(xp, qwp, x_s, q_ws, qq, 2048, 0);
    gemm_imma<<<dim3(8, 32),  256, GEMM_SMEM>>>(xp, kwp, x_s, k_ws, qk, 1024, 0);
    gemm_imma<<<dim3(8, 32),  256, GEMM_SMEM>>>(xp, vwp, x_s, v_ws, vf, 0,    1);

    // rmsnorm + rope -> head-major (warp per (s,h))
    norm_rope_w<<<(PS * PNH)  / 8, 256>>>(qq, qnw, cosp, sinp, qf, PNH);
    norm_rope_w<<<(PS * PNHK) / 8, 256>>>(qk, knw, cosp, sinp, kf, PNHK);

    // flash attention (double-buffered K/V)
    flash_mma<<<dim3(32, PNH), 256, FAM_SMEM>>>(qf, kf, vf, o_is, xo);

    // per-token quant + pack
    quant2<<<PS, 256>>>(xo, xoq, xos);

    // o-proj -> FLOAT32 output (bf16-rounded values)
    gemm_imma<<<dim3(16, 32), 256, GEMM_SMEM>>>(xoq, owp, xos, o_ws, d_out, 2048, 2);
}

// round 16
// speedup vs baseline: 6.0272x; 1.0764x over previous
#include <cuda_runtime.h>
#include <cuda_bf16.h>
#include <cstdint>

#define PS   4096
#define PDM  2048
#define PNH  16
#define PNHK 8
#define PDH  128
#define PKP  512

// ---------------------------------------------------------------------------
// Scratch
// ---------------------------------------------------------------------------
constexpr size_t SZ_XP  = (size_t)PS * PKP * 4;
constexpr size_t SZ_QWP = (size_t)2048 * PKP * 4;
constexpr size_t SZ_KWP = (size_t)1024 * PKP * 4;
constexpr size_t SZ_VWP = (size_t)1024 * PKP * 4;
constexpr size_t SZ_OWP = (size_t)2048 * PKP * 4;
constexpr size_t SZ_QQ  = (size_t)PS * 2048 * 2;
constexpr size_t SZ_QK  = (size_t)PS * 1024 * 2;
constexpr size_t SZ_QF  = (size_t)PNH  * PS * PDH * 2;
constexpr size_t SZ_KF  = (size_t)PNHK * PS * PDH * 2;
constexpr size_t SZ_VF  = (size_t)PNHK * PS * PDH * 2;
constexpr size_t SZ_XO  = (size_t)PS * PDM * 4;
constexpr size_t SZ_XOQ = (size_t)PS * PKP * 4;
constexpr size_t SZ_XOS = (size_t)PS * 4;

constexpr size_t OFF_XP  = 0;
constexpr size_t OFF_QWP = OFF_XP  + SZ_XP;
constexpr size_t OFF_KWP = OFF_QWP + SZ_QWP;
constexpr size_t OFF_VWP = OFF_KWP + SZ_KWP;
constexpr size_t OFF_OWP = OFF_VWP + SZ_VWP;
constexpr size_t OFF_QQ  = OFF_OWP + SZ_OWP;
constexpr size_t OFF_QK  = OFF_QQ  + SZ_QQ;
constexpr size_t OFF_QF  = OFF_QK  + SZ_QK;
constexpr size_t OFF_KF  = OFF_QF  + SZ_QF;
constexpr size_t OFF_VF  = OFF_KF  + SZ_KF;
constexpr size_t OFF_XO  = OFF_VF  + SZ_VF;
constexpr size_t OFF_XOQ = OFF_XO  + SZ_XO;
constexpr size_t OFF_XOS = OFF_XOQ + SZ_XOQ;
constexpr size_t SCRATCH_BYTES = OFF_XOS + SZ_XOS;

__device__ __align__(256) unsigned char g_scratch[SCRATCH_BYTES];

// ---------------------------------------------------------------------------
// PTX helpers
// ---------------------------------------------------------------------------
#define CP_ASYNC16(dst, src) \
    asm volatile("cp.async.cg.shared.global [%0], [%1], 16;" :: "r"(dst), "l"(src))
#define CP_COMMIT() asm volatile("cp.async.commit_group;")
#define CP_WAIT0()  asm volatile("cp.async.wait_group 0;")

#define IMMA16832(d, a, b) \
    asm volatile("mma.sync.aligned.m16n8k32.row.col.s32.s8.s8.s32 " \
                 "{%0,%1,%2,%3}, {%4,%5,%6,%7}, {%8,%9}, {%0,%1,%2,%3};" \
                 : "+r"(d[0]), "+r"(d[1]), "+r"(d[2]), "+r"(d[3]) \
                 : "r"(a[0]), "r"(a[1]), "r"(a[2]), "r"(a[3]), "r"(b[0]), "r"(b[1]))

#define MMA16816(d, a, b) \
    asm volatile("mma.sync.aligned.m16n8k16.row.col.f32.bf16.bf16.f32 " \
                 "{%0,%1,%2,%3}, {%4,%5,%6,%7}, {%8,%9}, {%0,%1,%2,%3};" \
                 : "+f"(d[0]), "+f"(d[1]), "+f"(d[2]), "+f"(d[3]) \
                 : "r"(a[0]), "r"(a[1]), "r"(a[2]), "r"(a[3]), "r"(b[0]), "r"(b[1]))

#define LDSM4(r0, r1, r2, r3, addr) \
    asm volatile("ldmatrix.sync.aligned.m8n8.x4.shared.b16 {%0,%1,%2,%3}, [%4];" \
                 : "=r"(r0), "=r"(r1), "=r"(r2), "=r"(r3) : "r"(addr))

#define LDSM4T(r0, r1, r2, r3, addr) \
    asm volatile("ldmatrix.sync.aligned.m8n8.x4.trans.shared.b16 {%0,%1,%2,%3}, [%4];" \
                 : "=r"(r0), "=r"(r1), "=r"(r2), "=r"(r3) : "r"(addr))

// ---------------------------------------------------------------------------
// Fused pack: all 5 regions in one launch (dst contiguous: xp|qwp|kwp|vwp|owp)
// ---------------------------------------------------------------------------
__global__ __launch_bounds__(256)
void pack_all(const int* __restrict__ x, const int* __restrict__ qw,
              const int* __restrict__ kw, const int* __restrict__ vw,
              const int* __restrict__ ow, int* __restrict__ dst)
{
    int i = blockIdx.x * 256 + threadIdx.x;
    const int* src;
    int li = i;
    if (i < 2097152)            { src = x;  }
    else if (i < 3145728)       { src = qw; li = i - 2097152; }
    else if (i < 3670016)       { src = kw; li = i - 3145728; }
    else if (i < 4194304)       { src = vw; li = i - 3670016; }
    else                        { src = ow; li = i - 4194304; }
    int4 v = ((const int4*)src)[li];
    dst[i] = (v.x & 0xFF) | ((v.y & 0xFF) << 8) | ((v.z & 0xFF) << 16) | (v.w << 24);
}

// ---------------------------------------------------------------------------
// IMMA compute core: 2-stage cp.async ring, one barrier per k-tile.
// BM=BN=128, BK=32 words; 8 warps = 2(m) x 4(n).
// ---------------------------------------------------------------------------
#define GST 36
constexpr int GEMM_SMEM = 4 * 128 * GST * 4;   // 2 stages x (A+B) = 73728 B

__device__ __forceinline__
void imma_core(const int* __restrict__ Ap, const int* __restrict__ Bp,
               int m0, int n0, int tid, uint32_t acc[4][4][4], int* gsm)
{
    int* As = gsm;                       // [2][128*GST]
    int* Bs = gsm + 2 * 128 * GST;
    const uint32_t aB = (uint32_t)__cvta_generic_to_shared(As);
    const uint32_t bB = (uint32_t)__cvta_generic_to_shared(Bs);

    const int w = tid >> 5, lane = tid & 31;
    const int g = lane >> 2, t4 = lane & 3;
    const int wm = w >> 2, wn = w & 3;
    const int lrow = tid >> 1, lhalf = (tid & 1) * 16;

    const int* gaRow = Ap + (size_t)(m0 + lrow) * PKP + lhalf;
    const int* gbRow = Bp + (size_t)(n0 + lrow) * PKP + lhalf;
    const uint32_t sOff = (uint32_t)(lrow * GST + lhalf) * 4;

    // prologue: stage 0
    {
        uint32_t da = aB + sOff, db = bB + sOff;
#pragma unroll
        for (int p = 0; p < 4; p++) {
            CP_ASYNC16(da + p * 16, gaRow + p * 4);
            CP_ASYNC16(db + p * 16, gbRow + p * 4);
        }
        CP_COMMIT();
    }

    for (int kt = 0; kt < 16; kt++) {
        CP_WAIT0();
        __syncthreads();   // stage kt data visible to all; compute(kt-1) done by all

        if (kt < 15) {
            const int nxt = (kt + 1) & 1;
            uint32_t da = aB + (uint32_t)(nxt * 128 * GST) * 4 + sOff;
            uint32_t db = bB + (uint32_t)(nxt * 128 * GST) * 4 + sOff;
            const int* ga = gaRow + (kt + 1) * 32;
            const int* gb = gbRow + (kt + 1) * 32;
#pragma unroll
            for (int p = 0; p < 4; p++) {
                CP_ASYNC16(da + p * 16, ga + p * 4);
                CP_ASYNC16(db + p * 16, gb + p * 4);
            }
            CP_COMMIT();
        }

        const int cur = kt & 1;
        const int* Ac = As + cur * 128 * GST;
        const int* Bc = Bs + cur * 128 * GST;
#pragma unroll
        for (int ks = 0; ks < 4; ks++) {
            uint32_t a[4][4];
#pragma unroll
            for (int mt = 0; mt < 4; mt++) {
                int base = (wm * 64 + mt * 16 + g) * GST + ks * 8 + t4;
                a[mt][0] = Ac[base];
                a[mt][1] = Ac[base + 8 * GST];
                a[mt][2] = Ac[base + 4];
                a[mt][3] = Ac[base + 8 * GST + 4];
            }
#pragma unroll
            for (int nt = 0; nt < 4; nt++) {
                int bbase = (wn * 32 + nt * 8 + g) * GST + ks * 8 + t4;
                uint32_t b[2] = { (uint32_t)Bc[bbase], (uint32_t)Bc[bbase + 4] };
#pragma unroll
                for (int mt = 0; mt < 4; mt++)
                    IMMA16832(acc[mt][nt], a[mt], b);
            }
        }
    }
}

// ---------------------------------------------------------------------------
// Fused QKV GEMM: B rows [0,2048)=q_w, [2048,3072)=k_w, [3072,4096)=v_w
// (contiguous in scratch). Routing per 128-aligned n-block.
// ---------------------------------------------------------------------------
__global__ __launch_bounds__(256, 2)
void gemm_qkv(const int* __restrict__ Ap, const int* __restrict__ Bp,
              const float* __restrict__ xs,
              const float* __restrict__ qws, const float* __restrict__ kws,
              const float* __restrict__ vws,
              __nv_bfloat16* __restrict__ qq, __nv_bfloat16* __restrict__ qk,
              __nv_bfloat16* __restrict__ vf)
{
    extern __shared__ int gsm[];
    const int tid = threadIdx.x;
    const int m0 = blockIdx.y * 128, n0 = blockIdx.x * 128;

    uint32_t acc[4][4][4];
#pragma unroll
    for (int mt = 0; mt < 4; mt++)
#pragma unroll
        for (int nt = 0; nt < 4; nt++)
#pragma unroll
            for (int c = 0; c < 4; c++) acc[mt][nt][c] = 0;

    imma_core(Ap, Bp, m0, n0, tid, acc, gsm);

    const int w = tid >> 5, lane = tid & 31;
    const int g = lane >> 2, t4 = lane & 3;
    const int wm = w >> 2, wn = w & 3;

#pragma unroll
    for (int mt = 0; mt < 4; mt++) {
        int r0 = m0 + wm * 64 + mt * 16 + g;
        int r1 = r0 + 8;
        float a0 = xs[r0], a1 = xs[r1];
#pragma unroll
        for (int nt = 0; nt < 4; nt++) {
            int n = n0 + wn * 32 + nt * 8 + t4 * 2;
            float b0, b1;
            if (n0 < 2048)      { b0 = qws[n];        b1 = qws[n + 1]; }
            else if (n0 < 3072) { b0 = kws[n - 2048]; b1 = kws[n - 2047]; }
            else                { b0 = vws[n - 3072]; b1 = vws[n - 3071]; }
            float v00 = (float)(int)acc[mt][nt][0] * a0 * b0;
            float v01 = (float)(int)acc[mt][nt][1] * a0 * b1;
            float v10 = (float)(int)acc[mt][nt][2] * a1 * b0;
            float v11 = (float)(int)acc[mt][nt][3] * a1 * b1;
            if (n0 < 2048) {
                qq[(size_t)r0 * 2048 + n]     = __float2bfloat16(v00);
                qq[(size_t)r0 * 2048 + n + 1] = __float2bfloat16(v01);
                qq[(size_t)r1 * 2048 + n]     = __float2bfloat16(v10);
                qq[(size_t)r1 * 2048 + n + 1] = __float2bfloat16(v11);
            } else if (n0 < 3072) {
                int c = n - 2048;
                qk[(size_t)r0 * 1024 + c]     = __float2bfloat16(v00);
                qk[(size_t)r0 * 1024 + c + 1] = __float2bfloat16(v01);
                qk[(size_t)r1 * 1024 + c]     = __float2bfloat16(v10);
                qk[(size_t)r1 * 1024 + c + 1] = __float2bfloat16(v11);
            } else {
                int c = n - 3072;
                vf[((size_t)(c >> 7) * PS + r0) * PDH + (c & 127)]             = __float2bfloat16(v00);
                vf[((size_t)((c + 1) >> 7) * PS + r0) * PDH + ((c + 1) & 127)] = __float2bfloat16(v01);
                vf[((size_t)(c >> 7) * PS + r1) * PDH + (c & 127)]             = __float2bfloat16(v10);
                vf[((size_t)((c + 1) >> 7) * PS + r1) * PDH + ((c + 1) & 127)] = __float2bfloat16(v11);
            }
        }
    }
}

// ---------------------------------------------------------------------------
// o-proj GEMM -> float32 output of bf16-rounded values
// ---------------------------------------------------------------------------
__global__ __launch_bounds__(256, 2)
void gemm_o(const int* __restrict__ Ap, const int* __restrict__ Bp,
            const float* __restrict__ asc, const float* __restrict__ bsc,
            float* __restrict__ C)
{
    extern __shared__ int gsm[];
    const int tid = threadIdx.x;
    const int m0 = blockIdx.y * 128, n0 = blockIdx.x * 128;

    uint32_t acc[4][4][4];
#pragma unroll
    for (int mt = 0; mt < 4; mt++)
#pragma unroll
        for (int nt = 0; nt < 4; nt++)
#pragma unroll
            for (int c = 0; c < 4; c++) acc[mt][nt][c] = 0;

    imma_core(Ap, Bp, m0, n0, tid, acc, gsm);

    const int w = tid >> 5, lane = tid & 31;
    const int g = lane >> 2, t4 = lane & 3;
    const int wm = w >> 2, wn = w & 3;

#pragma unroll
    for (int mt = 0; mt < 4; mt++) {
        int r0 = m0 + wm * 64 + mt * 16 + g;
        int r1 = r0 + 8;
        float a0 = asc[r0], a1 = asc[r1];
#pragma unroll
        for (int nt = 0; nt < 4; nt++) {
            int n = n0 + wn * 32 + nt * 8 + t4 * 2;
            float b0 = bsc[n], b1 = bsc[n + 1];
            C[(size_t)r0 * 2048 + n]     = __bfloat162float(__float2bfloat16((float)(int)acc[mt][nt][0] * a0 * b0));
            C[(size_t)r0 * 2048 + n + 1] = __bfloat162float(__float2bfloat16((float)(int)acc[mt][nt][1] * a0 * b1));
            C[(size_t)r1 * 2048 + n]     = __bfloat162float(__float2bfloat16((float)(int)acc[mt][nt][2] * a1 * b0));
            C[(size_t)r1 * 2048 + n + 1] = __bfloat162float(__float2bfloat16((float)(int)acc[mt][nt][3] * a1 * b1));
        }
    }
}

// ---------------------------------------------------------------------------
// RMSNorm + RoPE, one warp per (token, head).
// ---------------------------------------------------------------------------
__global__ __launch_bounds__(256)
void norm_rope_w(const __nv_bfloat16* __restrict__ in, const float* __restrict__ nw,
                 const float* __restrict__ cosp, const float* __restrict__ sinp,
                 __nv_bfloat16* __restrict__ out, int nh)
{
    int gw = (blockIdx.x * 256 + threadIdx.x) >> 5;
    int lane = threadIdx.x & 31;
    int s = gw / nh, h = gw - s * nh;
    if (s >= PS) return;

    const __nv_bfloat16* xi = in + ((size_t)s * nh + h) * PDH;
    float x[4];
#pragma unroll
    for (int k = 0; k < 4; k++) x[k] = __bfloat162float(xi[lane + 32 * k]);

    float ss = x[0]*x[0] + x[1]*x[1] + x[2]*x[2] + x[3]*x[3];
    ss += __shfl_xor_sync(0xffffffffu, ss, 16);
    ss += __shfl_xor_sync(0xffffffffu, ss, 8);
    ss += __shfl_xor_sync(0xffffffffu, ss, 4);
    ss += __shfl_xor_sync(0xffffffffu, ss, 2);
    ss += __shfl_xor_sync(0xffffffffu, ss, 1);
    float r = rsqrtf(ss * (1.0f / 128.0f) + 1e-6f);

    float y[4];
#pragma unroll
    for (int k = 0; k < 4; k++) {
        int col = lane + 32 * k;
        y[k] = __bfloat162float(__float2bfloat16(x[k] * r * nw[col]));
    }
    float rh[4] = { -y[2], -y[3], y[0], y[1] };

    __nv_bfloat16* od = out + ((size_t)h * PS + s) * PDH;
#pragma unroll
    for (int k = 0; k < 4; k++) {
        int col = lane + 32 * k;
        float c  = __bfloat162float(__float2bfloat16(cosp[(size_t)s * PDH + col]));
        float sn = __bfloat162float(__float2bfloat16(sinp[(size_t)s * PDH + col]));
        float t1 = __bfloat162float(__float2bfloat16(y[k] * c));
        float t2 = __bfloat162float(__float2bfloat16(rh[k] * sn));
        od[col] = __float2bfloat16(t1 + t2);
    }
}

// ---------------------------------------------------------------------------
// HMMA flash attention, cp.async double-buffered K/V. BM=128, BN=64.
// ---------------------------------------------------------------------------
#define QSTR 136
constexpr int FAM_SMEM = (128 + 4 * 64) * QSTR * 2;  // 104448 B

__device__ __forceinline__ uint32_t packbf2(float lo, float hi)
{
    __nv_bfloat162 h = __floats2bfloat162_rn(lo, hi);
    return *(uint32_t*)&h;
}

__global__ __launch_bounds__(256)
void flash_mma(const __nv_bfloat16* __restrict__ Q, const __nv_bfloat16* __restrict__ K,
               const __nv_bfloat16* __restrict__ V, const float* __restrict__ oisc,
               float* __restrict__ XO)
{
    extern __shared__ __nv_bfloat16 smb[];
    __nv_bfloat16* Qs = smb;
    __nv_bfloat16* Ks = Qs + 128 * QSTR;
    __nv_bfloat16* Vs = Ks + 2 * 64 * QSTR;
    const uint32_t qsB = (uint32_t)__cvta_generic_to_shared(Qs);
    const uint32_t ksB = (uint32_t)__cvta_generic_to_shared(Ks);
    const uint32_t vsB = (uint32_t)__cvta_generic_to_shared(Vs);
    constexpr uint32_t STG = 64 * QSTR * 2;

    const int tid  = threadIdx.x;
    const int w    = tid >> 5, lane = tid & 31;
    const int g    = lane >> 2, t4 = lane & 3;
    const int wi   = lane & 15, hi = lane >> 4;
    const int qb   = 31 - blockIdx.x;
    const int h    = blockIdx.y, hk = h >> 1;

    const __nv_bfloat16* Qg = Q + ((size_t)h * PS + qb * 128) * PDH;
    const __nv_bfloat16* Kg = K + (size_t)hk * PS * PDH;
    const __nv_bfloat16* Vg = V + (size_t)hk * PS * PDH;

    const int lrow = tid >> 2, ldhb = (tid & 3) * 32;
    const uint32_t lOff = (uint32_t)(lrow * QSTR + ldhb) * 2;

    {
        int row = tid >> 1, dhb = (tid & 1) * 64;
        const uint4* src = (const uint4*)(Qg + (size_t)row * PDH + dhb);
        uint4* dst = (uint4*)(Qs + row * QSTR + dhb);
#pragma unroll
        for (int i = 0; i < 8; i++) dst[i] = src[i];
    }

    {
        const __nv_bfloat16* sk = Kg + (size_t)lrow * PDH + ldhb;
        const __nv_bfloat16* sv = Vg + (size_t)lrow * PDH + ldhb;
#pragma unroll
        for (int i = 0; i < 4; i++) {
            CP_ASYNC16(ksB + lOff + i * 16, sk + i * 8);
            CP_ASYNC16(vsB + lOff + i * 16, sv + i * 8);
        }
        CP_COMMIT();
    }
    __syncthreads();

    uint32_t qa[8][4];
#pragma unroll
    for (int kt = 0; kt < 8; kt++) {
        uint32_t addr = qsB + (uint32_t)(((w * 16 + wi) * QSTR + kt * 16 + hi * 8) * 2);
        LDSM4(qa[kt][0], qa[kt][1], qa[kt][2], qa[kt][3], addr);
    }

    float oac[16][4];
#pragma unroll
    for (int n = 0; n < 16; n++)
#pragma unroll
        for (int c = 0; c < 4; c++) oac[n][c] = 0.0f;
    float li0 = 0.0f, li1 = 0.0f;
    const float scale = 0.08838834764831845f;

    const int gr0 = qb * 128 + w * 16 + g;
    const int gr1 = gr0 + 8;
    const int jtmax = 2 * qb + 1;

    for (int jt = 0; jt <= jtmax; jt++) {
        const uint32_t cur = (uint32_t)(jt & 1) * STG;
        CP_WAIT0();
        __syncthreads();

        if (jt < jtmax) {
            const uint32_t nxt = (uint32_t)((jt + 1) & 1) * STG;
            const __nv_bfloat16* sk = Kg + (size_t)((jt + 1) * 64 + lrow) * PDH + ldhb;
            const __nv_bfloat16* sv = Vg + (size_t)((jt + 1) * 64 + lrow) * PDH + ldhb;
#pragma unroll
            for (int i = 0; i < 4; i++) {
                CP_ASYNC16(ksB + nxt + lOff + i * 16, sk + i * 8);
                CP_ASYNC16(vsB + nxt + lOff + i * 16, sv + i * 8);
            }
            CP_COMMIT();
        }

        float sc[8][4];
#pragma unroll
        for (int n = 0; n < 8; n++)
#pragma unroll
            for (int c = 0; c < 4; c++) sc[n][c] = 0.0f;

#pragma unroll
        for (int kt = 0; kt < 8; kt++) {
#pragma unroll
            for (int ntp = 0; ntp < 4; ntp++) {
                uint32_t b0, b1, b2, b3;
                uint32_t addr = ksB + cur + (uint32_t)(((ntp * 16 + hi * 8 + (wi & 7)) * QSTR
                                                        + kt * 16 + (wi >> 3) * 8) * 2);
                LDSM4(b0, b1, b2, b3, addr);
                uint32_t bA[2] = { b0, b1 };
                uint32_t bB2[2] = { b2, b3 };
                MMA16816(sc[ntp * 2],     qa[kt], bA);
                MMA16816(sc[ntp * 2 + 1], qa[kt], bB2);
            }
        }

        float rs0 = 0.0f, rs1 = 0.0f;
        const int colb = jt * 64 + t4 * 2;
#pragma unroll
        for (int nt = 0; nt < 8; nt++) {
            int c0 = colb + nt * 8;
            float p0 = (c0     <= gr0) ? __expf(sc[nt][0] * scale) : 0.0f;
            float p1 = (c0 + 1 <= gr0) ? __expf(sc[nt][1] * scale) : 0.0f;
            float p2 = (c0     <= gr1) ? __expf(sc[nt][2] * scale) : 0.0f;
            float p3 = (c0 + 1 <= gr1) ? __expf(sc[nt][3] * scale) : 0.0f;
            sc[nt][0] = p0; sc[nt][1] = p1; sc[nt][2] = p2; sc[nt][3] = p3;
            rs0 += p0 + p1;
            rs1 += p2 + p3;
        }
        rs0 += __shfl_xor_sync(0xffffffffu, rs0, 1);
        rs0 += __shfl_xor_sync(0xffffffffu, rs0, 2);
        rs1 += __shfl_xor_sync(0xffffffffu, rs1, 1);
        rs1 += __shfl_xor_sync(0xffffffffu, rs1, 2);
        li0 += rs0;
        li1 += rs1;

        uint32_t Phi[4][4], Plo[4][4];
#pragma unroll
        for (int kt = 0; kt < 4; kt++) {
#pragma unroll
            for (int hv = 0; hv < 2; hv++) {
                float* c = sc[2 * kt + hv];
                __nv_bfloat16 h0 = __float2bfloat16_rn(c[0]);
                __nv_bfloat16 h1 = __float2bfloat16_rn(c[1]);
                __nv_bfloat16 h2 = __float2bfloat16_rn(c[2]);
                __nv_bfloat16 h3 = __float2bfloat16_rn(c[3]);
                float l0 = c[0] - __bfloat162float(h0);
                float l1 = c[1] - __bfloat162float(h1);
                float l2 = c[2] - __bfloat162float(h2);
                float l3 = c[3] - __bfloat162float(h3);
                Phi[kt][hv * 2 + 0] = ((uint32_t)*(uint16_t*)&h1 << 16) | *(uint16_t*)&h0;
                Phi[kt][hv * 2 + 1] = ((uint32_t)*(uint16_t*)&h3 << 16) | *(uint16_t*)&h2;
                Plo[kt][hv * 2 + 0] = packbf2(l0, l1);
                Plo[kt][hv * 2 + 1] = packbf2(l2, l3);
            }
        }

#pragma unroll
        for (int kt = 0; kt < 4; kt++) {
#pragma unroll
            for (int ntp = 0; ntp < 8; ntp++) {
                uint32_t b0, b1, b2, b3;
                uint32_t addr = vsB + cur + (uint32_t)(((kt * 16 + wi) * QSTR
                                                        + ntp * 16 + hi * 8) * 2);
                LDSM4T(b0, b1, b2, b3, addr);
                uint32_t bA[2] = { b0, b1 };
                uint32_t bB2[2] = { b2, b3 };
                MMA16816(oac[ntp * 2],     Phi[kt], bA);
                MMA16816(oac[ntp * 2],     Plo[kt], bA);
                MMA16816(oac[ntp * 2 + 1], Phi[kt], bB2);
                MMA16816(oac[ntp * 2 + 1], Plo[kt], bB2);
            }
        }
    }

    const float inv0 = 1.0f / li0;
    const float inv1 = 1.0f / li1;
#pragma unroll
    for (int nt2 = 0; nt2 < 16; nt2++) {
        int oc = h * PDH + nt2 * 8 + t4 * 2;
        float s0 = oisc[oc], s1 = oisc[oc + 1];
        XO[(size_t)gr0 * PDM + oc]     = oac[nt2][0] * inv0 / s0;
        XO[(size_t)gr0 * PDM + oc + 1] = oac[nt2][1] * inv0 / s1;
        XO[(size_t)gr1 * PDM + oc]     = oac[nt2][2] * inv1 / s0;
        XO[(size_t)gr1 * PDM + oc + 1] = oac[nt2][3] * inv1 / s1;
    }
}

// ---------------------------------------------------------------------------
// Per-token int8 quantization + packing.
// ---------------------------------------------------------------------------
__global__ __launch_bounds__(256)
void quant2(const float* __restrict__ XO, int* __restrict__ Xq, float* __restrict__ Xs)
{
    __shared__ float red[256];
    const int t = blockIdx.x, tid = threadIdx.x;

    float v[8];
    float m = 0.0f;
#pragma unroll
    for (int i = 0; i < 8; i++) {
        v[i] = XO[(size_t)t * PDM + tid * 8 + i];
        m = fmaxf(m, fabsf(v[i]));
    }
    red[tid] = m;
    __syncthreads();
    for (int o = 128; o > 0; o >>= 1) {
        if (tid < o) red[tid] = fmaxf(red[tid], red[tid + o]);
        __syncthreads();
    }
    float sc = fmaxf(red[0] * (1.0f / 127.0f), 1e-7f);

    int q[8];
#pragma unroll
    for (int i = 0; i < 8; i++)
        q[i] = (int)fminf(fmaxf(rintf(v[i] / sc), -128.0f), 127.0f);
    int p0 = (q[0] & 0xFF) | ((q[1] & 0xFF) << 8) | ((q[2] & 0xFF) << 16) | (q[3] << 24);
    int p1 = (q[4] & 0xFF) | ((q[5] & 0xFF) << 8) | ((q[6] & 0xFF) << 16) | (q[7] << 24);
    Xq[(size_t)t * PKP + tid * 2]     = p0;
    Xq[(size_t)t * PKP + tid * 2 + 1] = p1;
    if (tid == 0) Xs[t] = sc;
}

// ---------------------------------------------------------------------------
// Launch
// ---------------------------------------------------------------------------
extern "C" void kernel_launch(void* const* d_in, const int* in_sizes, int n_in,
                              void* d_out, int out_size)
{
    const int*   x_i8 = (const int*)d_in[0];
    const float* x_s  = (const float*)d_in[1];
    const float* cosp = (const float*)d_in[3];
    const float* sinp = (const float*)d_in[4];
    const int*   q_w  = (const int*)d_in[5];
    const float* q_ws = (const float*)d_in[6];
    const int*   k_w  = (const int*)d_in[7];
    const float* k_ws = (const float*)d_in[8];
    const int*   v_w  = (const int*)d_in[9];
    const float* v_ws = (const float*)d_in[10];
    const int*   o_w  = (const int*)d_in[11];
    const float* o_ws = (const float*)d_in[12];
    const float* o_is = (const float*)d_in[13];
    const float* qnw  = (const float*)d_in[14];
    const float* knw  = (const float*)d_in[15];

    unsigned char* base = nullptr;
    cudaGetSymbolAddress((void**)&base, g_scratch);

    int*           xp  = (int*)(base + OFF_XP);
    int*           qwp = (int*)(base + OFF_QWP);   // qwp|kwp|vwp contiguous
    int*           owp = (int*)(base + OFF_OWP);
    __nv_bfloat16* qq  = (__nv_bfloat16*)(base + OFF_QQ);
    __nv_bfloat16* qk  = (__nv_bfloat16*)(base + OFF_QK);
    __nv_bfloat16* qf  = (__nv_bfloat16*)(base + OFF_QF);
    __nv_bfloat16* kf  = (__nv_bfloat16*)(base + OFF_KF);
    __nv_bfloat16* vf  = (__nv_bfloat16*)(base + OFF_VF);
    float*         xo  = (float*)(base + OFF_XO);
    int*           xoq = (int*)(base + OFF_XOQ);
    float*         xos = (float*)(base + OFF_XOS);

    cudaFuncSetAttribute(gemm_qkv, cudaFuncAttributeMaxDynamicSharedMemorySize, GEMM_SMEM);
    cudaFuncSetAttribute(gemm_o,   cudaFuncAttributeMaxDynamicSharedMemorySize, GEMM_SMEM);
    cudaFuncSetAttribute(flash_mma, cudaFuncAttributeMaxDynamicSharedMemorySize, FAM_SMEM);

    // fused pack
    pack_all<<<5242880 / 256, 256>>>(x_i8, q_w, k_w, v_w, o_w, xp);

    // fused QKV projection (one launch, 1024 blocks)
    gemm_qkv<<<dim3(32, 32), 256, GEMM_SMEM>>>(xp, qwp, x_s, q_ws, k_ws, v_ws, qq, qk, vf);

    // rmsnorm + rope -> head-major
    norm_rope_w<<<(PS * PNH)  / 8, 256>>>(qq, qnw, cosp, sinp, qf, PNH);
    norm_rope_w<<<(PS * PNHK) / 8, 256>>>(qk, knw, cosp, sinp, kf, PNHK);

    // flash attention
    flash_mma<<<dim3(32, PNH), 256, FAM_SMEM>>>(qf, kf, vf, o_is, xo);

    // per-token quant + pack
    quant2<<<PS, 256>>>(xo, xoq, xos);

    // o-proj -> FLOAT32 output
    gemm_o<<<dim3(16, 32), 256, GEMM_SMEM>>>(xoq, owp, xos, o_ws, (float*)d_out);
}

// round 17
// speedup vs baseline: 8.3819x; 1.3907x over previous
#include <cuda_runtime.h>
#include <cuda_bf16.h>
#include <cstdint>

#define PS   4096
#define PDM  2048
#define PNH  16
#define PNHK 8
#define PDH  128

// ---------------------------------------------------------------------------
// Scratch
// ---------------------------------------------------------------------------
constexpr size_t SZ_XB   = (size_t)PS * PDM * 2;          // x as bf16
constexpr size_t SZ_WQKV = (size_t)4096 * PDM * 2;        // qw|kw|vw bf16
constexpr size_t SZ_OWB  = (size_t)2048 * PDM * 2;        // ow bf16
constexpr size_t SZ_QQ   = (size_t)PS * 2048 * 2;
constexpr size_t SZ_QK   = (size_t)PS * 1024 * 2;
constexpr size_t SZ_QF   = (size_t)PNH  * PS * PDH * 2;
constexpr size_t SZ_KF   = (size_t)PNHK * PS * PDH * 2;
constexpr size_t SZ_VF   = (size_t)PNHK * PS * PDH * 2;
constexpr size_t SZ_XO   = (size_t)PS * PDM * 4;
constexpr size_t SZ_XOB  = (size_t)PS * PDM * 2;          // quantized xo bf16
constexpr size_t SZ_XOS  = (size_t)PS * 4;

constexpr size_t OFF_XB   = 0;
constexpr size_t OFF_WQKV = OFF_XB   + SZ_XB;
constexpr size_t OFF_OWB  = OFF_WQKV + SZ_WQKV;
constexpr size_t OFF_QQ   = OFF_OWB  + SZ_OWB;
constexpr size_t OFF_QK   = OFF_QQ   + SZ_QQ;
constexpr size_t OFF_QF   = OFF_QK   + SZ_QK;
constexpr size_t OFF_KF   = OFF_QF   + SZ_QF;
constexpr size_t OFF_VF   = OFF_KF   + SZ_KF;
constexpr size_t OFF_XO   = OFF_VF   + SZ_VF;
constexpr size_t OFF_XOB  = OFF_XO   + SZ_XO;
constexpr size_t OFF_XOS  = OFF_XOB  + SZ_XOB;
constexpr size_t SCRATCH_BYTES = OFF_XOS + SZ_XOS;

__device__ __align__(256) unsigned char g_scratch[SCRATCH_BYTES];

// ---------------------------------------------------------------------------
// PTX helpers
// ---------------------------------------------------------------------------
#define CP_ASYNC16(dst, src) \
    asm volatile("cp.async.cg.shared.global [%0], [%1], 16;" :: "r"(dst), "l"(src))
#define CP_COMMIT() asm volatile("cp.async.commit_group;")
#define CP_WAIT0()  asm volatile("cp.async.wait_group 0;")

#define MMA16816(d, a, b) \
    asm volatile("mma.sync.aligned.m16n8k16.row.col.f32.bf16.bf16.f32 " \
                 "{%0,%1,%2,%3}, {%4,%5,%6,%7}, {%8,%9}, {%0,%1,%2,%3};" \
                 : "+f"(d[0]), "+f"(d[1]), "+f"(d[2]), "+f"(d[3]) \
                 : "r"(a[0]), "r"(a[1]), "r"(a[2]), "r"(a[3]), "r"(b[0]), "r"(b[1]))

#define LDSM4(r0, r1, r2, r3, addr) \
    asm volatile("ldmatrix.sync.aligned.m8n8.x4.shared.b16 {%0,%1,%2,%3}, [%4];" \
                 : "=r"(r0), "=r"(r1), "=r"(r2), "=r"(r3) : "r"(addr))

#define LDSM4T(r0, r1, r2, r3, addr) \
    asm volatile("ldmatrix.sync.aligned.m8n8.x4.trans.shared.b16 {%0,%1,%2,%3}, [%4];" \
                 : "=r"(r0), "=r"(r1), "=r"(r2), "=r"(r3) : "r"(addr))

// ---------------------------------------------------------------------------
// Fused pack: int32-stored int8 -> bf16 (exact). 8 elements per thread.
// dst regions contiguous: xb | qw | kw | vw | ow
// element boundaries/8: 1048576 | 1572864 | 1835008 | 2097152 | 2621440
// ---------------------------------------------------------------------------
__global__ __launch_bounds__(256)
void pack_bf16(const int* __restrict__ x, const int* __restrict__ qw,
               const int* __restrict__ kw, const int* __restrict__ vw,
               const int* __restrict__ ow, __nv_bfloat16* __restrict__ dst)
{
    int i = blockIdx.x * 256 + threadIdx.x;
    const int* src;
    int li = i;
    if (i < 1048576)       { src = x;  }
    else if (i < 1572864)  { src = qw; li = i - 1048576; }
    else if (i < 1835008)  { src = kw; li = i - 1572864; }
    else if (i < 2097152)  { src = vw; li = i - 1835008; }
    else                   { src = ow; li = i - 2097152; }
    int4 a = ((const int4*)src)[li * 2];
    int4 b = ((const int4*)src)[li * 2 + 1];
    __nv_bfloat162 o[4];
    o[0] = __floats2bfloat162_rn((float)a.x, (float)a.y);
    o[1] = __floats2bfloat162_rn((float)a.z, (float)a.w);
    o[2] = __floats2bfloat162_rn((float)b.x, (float)b.y);
    o[3] = __floats2bfloat162_rn((float)b.z, (float)b.w);
    *(uint4*)(dst + (size_t)i * 8) = *(uint4*)o;
}

// ---------------------------------------------------------------------------
// bf16 HMMA GEMM core: BM=BN=128, BK=64 bf16, 2-stage cp.async ring.
// 8 warps = 2(m) x 4(n); warp tile m64 x n32. K = 2048.
// ---------------------------------------------------------------------------
#define BST 72   // smem row stride in bf16 (proven pattern: 36 words)
constexpr int GEMM_SMEM = 2 * 2 * 128 * BST * 2;   // 73728 B

__device__ __forceinline__
void hmma_core(const __nv_bfloat16* __restrict__ Ap, const __nv_bfloat16* __restrict__ Bp,
               int m0, int n0, int tid, float acc[4][4][4], __nv_bfloat16* smem)
{
    __nv_bfloat16* As = smem;                     // [2][128*BST]
    __nv_bfloat16* Bs = smem + 2 * 128 * BST;
    const uint32_t aB = (uint32_t)__cvta_generic_to_shared(As);
    const uint32_t bB = (uint32_t)__cvta_generic_to_shared(Bs);
    constexpr uint32_t STG = 128 * BST * 2;       // bytes per stage

    const int w = tid >> 5, lane = tid & 31;
    const int wi = lane & 15, hi = lane >> 4;
    const int wm = w >> 2, wn = w & 3;
    const int lrow = tid >> 1, lcol = (tid & 1) * 32;

    const __nv_bfloat16* gaRow = Ap + (size_t)(m0 + lrow) * PDM + lcol;
    const __nv_bfloat16* gbRow = Bp + (size_t)(n0 + lrow) * PDM + lcol;
    const uint32_t sOff = (uint32_t)(lrow * BST + lcol) * 2;

    // prologue: stage 0 (k-tile 0)
    {
        uint32_t da = aB + sOff, db = bB + sOff;
#pragma unroll
        for (int p = 0; p < 4; p++) {
            CP_ASYNC16(da + p * 16, gaRow + p * 8);
            CP_ASYNC16(db + p * 16, gbRow + p * 8);
        }
        CP_COMMIT();
    }

    for (int kt = 0; kt < 32; kt++) {
        CP_WAIT0();
        __syncthreads();   // stage kt visible; compute(kt-1) done by all

        if (kt < 31) {
            const uint32_t nxt = (uint32_t)((kt + 1) & 1) * STG;
            const __nv_bfloat16* ga = gaRow + (kt + 1) * 64;
            const __nv_bfloat16* gb = gbRow + (kt + 1) * 64;
#pragma unroll
            for (int p = 0; p < 4; p++) {
                CP_ASYNC16(aB + nxt + sOff + p * 16, ga + p * 8);
                CP_ASYNC16(bB + nxt + sOff + p * 16, gb + p * 8);
            }
            CP_COMMIT();
        }

        const uint32_t cur = (uint32_t)(kt & 1) * STG;
#pragma unroll
        for (int ks = 0; ks < 4; ks++) {
            uint32_t a[4][4];
#pragma unroll
            for (int mt = 0; mt < 4; mt++) {
                uint32_t addr = aB + cur +
                    (uint32_t)(((wm * 64 + mt * 16 + wi) * BST + ks * 16 + hi * 8) * 2);
                LDSM4(a[mt][0], a[mt][1], a[mt][2], a[mt][3], addr);
            }
#pragma unroll
            for (int nt2 = 0; nt2 < 2; nt2++) {
                uint32_t b0, b1, b2, b3;
                uint32_t addr = bB + cur +
                    (uint32_t)(((wn * 32 + nt2 * 16 + hi * 8 + (wi & 7)) * BST
                                + ks * 16 + (wi >> 3) * 8) * 2);
                LDSM4(b0, b1, b2, b3, addr);
                uint32_t bA[2] = { b0, b1 };
                uint32_t bB2[2] = { b2, b3 };
#pragma unroll
                for (int mt = 0; mt < 4; mt++) {
                    MMA16816(acc[mt][nt2 * 2],     a[mt], bA);
                    MMA16816(acc[mt][nt2 * 2 + 1], a[mt], bB2);
                }
            }
        }
    }
}

// ---------------------------------------------------------------------------
// Fused QKV GEMM: B rows [0,2048)=q_w, [2048,3072)=k_w, [3072,4096)=v_w.
// ---------------------------------------------------------------------------
__global__ __launch_bounds__(256, 2)
void gemm_qkv(const __nv_bfloat16* __restrict__ Ap, const __nv_bfloat16* __restrict__ Bp,
              const float* __restrict__ xs,
              const float* __restrict__ qws, const float* __restrict__ kws,
              const float* __restrict__ vws,
              __nv_bfloat16* __restrict__ qq, __nv_bfloat16* __restrict__ qk,
              __nv_bfloat16* __restrict__ vf)
{
    extern __shared__ __nv_bfloat16 gsm[];
    const int tid = threadIdx.x;
    const int m0 = blockIdx.y * 128, n0 = blockIdx.x * 128;

    float acc[4][4][4];
#pragma unroll
    for (int mt = 0; mt < 4; mt++)
#pragma unroll
        for (int nt = 0; nt < 4; nt++)
#pragma unroll
            for (int c = 0; c < 4; c++) acc[mt][nt][c] = 0.0f;

    hmma_core(Ap, Bp, m0, n0, tid, acc, gsm);

    const int w = tid >> 5, lane = tid & 31;
    const int g = lane >> 2, t4 = lane & 3;
    const int wm = w >> 2, wn = w & 3;

#pragma unroll
    for (int mt = 0; mt < 4; mt++) {
        int r0 = m0 + wm * 64 + mt * 16 + g;
        int r1 = r0 + 8;
        float a0 = xs[r0], a1 = xs[r1];
#pragma unroll
        for (int nt = 0; nt < 4; nt++) {
            int n = n0 + wn * 32 + nt * 8 + t4 * 2;
            float b0, b1;
            if (n0 < 2048)      { b0 = qws[n];        b1 = qws[n + 1]; }
            else if (n0 < 3072) { b0 = kws[n - 2048]; b1 = kws[n - 2047]; }
            else                { b0 = vws[n - 3072]; b1 = vws[n - 3071]; }
            float v00 = acc[mt][nt][0] * a0 * b0;
            float v01 = acc[mt][nt][1] * a0 * b1;
            float v10 = acc[mt][nt][2] * a1 * b0;
            float v11 = acc[mt][nt][3] * a1 * b1;
            if (n0 < 2048) {
                qq[(size_t)r0 * 2048 + n]     = __float2bfloat16(v00);
                qq[(size_t)r0 * 2048 + n + 1] = __float2bfloat16(v01);
                qq[(size_t)r1 * 2048 + n]     = __float2bfloat16(v10);
                qq[(size_t)r1 * 2048 + n + 1] = __float2bfloat16(v11);
            } else if (n0 < 3072) {
                int c = n - 2048;
                qk[(size_t)r0 * 1024 + c]     = __float2bfloat16(v00);
                qk[(size_t)r0 * 1024 + c + 1] = __float2bfloat16(v01);
                qk[(size_t)r1 * 1024 + c]     = __float2bfloat16(v10);
                qk[(size_t)r1 * 1024 + c + 1] = __float2bfloat16(v11);
            } else {
                int c = n - 3072;
                vf[((size_t)(c >> 7) * PS + r0) * PDH + (c & 127)]             = __float2bfloat16(v00);
                vf[((size_t)((c + 1) >> 7) * PS + r0) * PDH + ((c + 1) & 127)] = __float2bfloat16(v01);
                vf[((size_t)(c >> 7) * PS + r1) * PDH + (c & 127)]             = __float2bfloat16(v10);
                vf[((size_t)((c + 1) >> 7) * PS + r1) * PDH + ((c + 1) & 127)] = __float2bfloat16(v11);
            }
        }
    }
}

// ---------------------------------------------------------------------------
// o-proj GEMM -> float32 output of bf16-rounded values
// ---------------------------------------------------------------------------
__global__ __launch_bounds__(256, 2)
void gemm_o(const __nv_bfloat16* __restrict__ Ap, const __nv_bfloat16* __restrict__ Bp,
            const float* __restrict__ asc, const float* __restrict__ bsc,
            float* __restrict__ C)
{
    extern __shared__ __nv_bfloat16 gsm[];
    const int tid = threadIdx.x;
    const int m0 = blockIdx.y * 128, n0 = blockIdx.x * 128;

    float acc[4][4][4];
#pragma unroll
    for (int mt = 0; mt < 4; mt++)
#pragma unroll
        for (int nt = 0; nt < 4; nt++)
#pragma unroll
            for (int c = 0; c < 4; c++) acc[mt][nt][c] = 0.0f;

    hmma_core(Ap, Bp, m0, n0, tid, acc, gsm);

    const int w = tid >> 5, lane = tid & 31;
    const int g = lane >> 2, t4 = lane & 3;
    const int wm = w >> 2, wn = w & 3;

#pragma unroll
    for (int mt = 0; mt < 4; mt++) {
        int r0 = m0 + wm * 64 + mt * 16 + g;
        int r1 = r0 + 8;
        float a0 = asc[r0], a1 = asc[r1];
#pragma unroll
        for (int nt = 0; nt < 4; nt++) {
            int n = n0 + wn * 32 + nt * 8 + t4 * 2;
            float b0 = bsc[n], b1 = bsc[n + 1];
            C[(size_t)r0 * 2048 + n]     = __bfloat162float(__float2bfloat16(acc[mt][nt][0] * a0 * b0));
            C[(size_t)r0 * 2048 + n + 1] = __bfloat162float(__float2bfloat16(acc[mt][nt][1] * a0 * b1));
            C[(size_t)r1 * 2048 + n]     = __bfloat162float(__float2bfloat16(acc[mt][nt][2] * a1 * b0));
            C[(size_t)r1 * 2048 + n + 1] = __bfloat162float(__float2bfloat16(acc[mt][nt][3] * a1 * b1));
        }
    }
}

// ---------------------------------------------------------------------------
// RMSNorm + RoPE, one warp per (token, head).
// ---------------------------------------------------------------------------
__global__ __launch_bounds__(256)
void norm_rope_w(const __nv_bfloat16* __restrict__ in, const float* __restrict__ nw,
                 const float* __restrict__ cosp, const float* __restrict__ sinp,
                 __nv_bfloat16* __restrict__ out, int nh)
{
    int gw = (blockIdx.x * 256 + threadIdx.x) >> 5;
    int lane = threadIdx.x & 31;
    int s = gw / nh, h = gw - s * nh;
    if (s >= PS) return;

    const __nv_bfloat16* xi = in + ((size_t)s * nh + h) * PDH;
    float x[4];
#pragma unroll
    for (int k = 0; k < 4; k++) x[k] = __bfloat162float(xi[lane + 32 * k]);

    float ss = x[0]*x[0] + x[1]*x[1] + x[2]*x[2] + x[3]*x[3];
    ss += __shfl_xor_sync(0xffffffffu, ss, 16);
    ss += __shfl_xor_sync(0xffffffffu, ss, 8);
    ss += __shfl_xor_sync(0xffffffffu, ss, 4);
    ss += __shfl_xor_sync(0xffffffffu, ss, 2);
    ss += __shfl_xor_sync(0xffffffffu, ss, 1);
    float r = rsqrtf(ss * (1.0f / 128.0f) + 1e-6f);

    float y[4];
#pragma unroll
    for (int k = 0; k < 4; k++) {
        int col = lane + 32 * k;
        y[k] = __bfloat162float(__float2bfloat16(x[k] * r * nw[col]));
    }
    float rh[4] = { -y[2], -y[3], y[0], y[1] };

    __nv_bfloat16* od = out + ((size_t)h * PS + s) * PDH;
#pragma unroll
    for (int k = 0; k < 4; k++) {
        int col = lane + 32 * k;
        float c  = __bfloat162float(__float2bfloat16(cosp[(size_t)s * PDH + col]));
        float sn = __bfloat162float(__float2bfloat16(sinp[(size_t)s * PDH + col]));
        float t1 = __bfloat162float(__float2bfloat16(y[k] * c));
        float t2 = __bfloat162float(__float2bfloat16(rh[k] * sn));
        od[col] = __float2bfloat16(t1 + t2);
    }
}

// ---------------------------------------------------------------------------
// HMMA flash attention, cp.async double-buffered K/V. BM=128, BN=64.
// ---------------------------------------------------------------------------
#define QSTR 136
constexpr int FAM_SMEM = (128 + 4 * 64) * QSTR * 2;  // 104448 B

__device__ __forceinline__ uint32_t packbf2(float lo, float hi)
{
    __nv_bfloat162 h = __floats2bfloat162_rn(lo, hi);
    return *(uint32_t*)&h;
}

__global__ __launch_bounds__(256)
void flash_mma(const __nv_bfloat16* __restrict__ Q, const __nv_bfloat16* __restrict__ K,
               const __nv_bfloat16* __restrict__ V, const float* __restrict__ oisc,
               float* __restrict__ XO)
{
    extern __shared__ __nv_bfloat16 smb[];
    __nv_bfloat16* Qs = smb;
    __nv_bfloat16* Ks = Qs + 128 * QSTR;
    __nv_bfloat16* Vs = Ks + 2 * 64 * QSTR;
    const uint32_t qsB = (uint32_t)__cvta_generic_to_shared(Qs);
    const uint32_t ksB = (uint32_t)__cvta_generic_to_shared(Ks);
    const uint32_t vsB = (uint32_t)__cvta_generic_to_shared(Vs);
    constexpr uint32_t STG = 64 * QSTR * 2;

    const int tid  = threadIdx.x;
    const int w    = tid >> 5, lane = tid & 31;
    const int g    = lane >> 2, t4 = lane & 3;
    const int wi   = lane & 15, hi = lane >> 4;
    const int qb   = 31 - blockIdx.x;
    const int h    = blockIdx.y, hk = h >> 1;

    const __nv_bfloat16* Qg = Q + ((size_t)h * PS + qb * 128) * PDH;
    const __nv_bfloat16* Kg = K + (size_t)hk * PS * PDH;
    const __nv_bfloat16* Vg = V + (size_t)hk * PS * PDH;

    const int lrow = tid >> 2, ldhb = (tid & 3) * 32;
    const uint32_t lOff = (uint32_t)(lrow * QSTR + ldhb) * 2;

    {
        int row = tid >> 1, dhb = (tid & 1) * 64;
        const uint4* src = (const uint4*)(Qg + (size_t)row * PDH + dhb);
        uint4* dst = (uint4*)(Qs + row * QSTR + dhb);
#pragma unroll
        for (int i = 0; i < 8; i++) dst[i] = src[i];
    }

    {
        const __nv_bfloat16* sk = Kg + (size_t)lrow * PDH + ldhb;
        const __nv_bfloat16* sv = Vg + (size_t)lrow * PDH + ldhb;
#pragma unroll
        for (int i = 0; i < 4; i++) {
            CP_ASYNC16(ksB + lOff + i * 16, sk + i * 8);
            CP_ASYNC16(vsB + lOff + i * 16, sv + i * 8);
        }
        CP_COMMIT();
    }
    __syncthreads();

    uint32_t qa[8][4];
#pragma unroll
    for (int kt = 0; kt < 8; kt++) {
        uint32_t addr = qsB + (uint32_t)(((w * 16 + wi) * QSTR + kt * 16 + hi * 8) * 2);
        LDSM4(qa[kt][0], qa[kt][1], qa[kt][2], qa[kt][3], addr);
    }

    float oac[16][4];
#pragma unroll
    for (int n = 0; n < 16; n++)
#pragma unroll
        for (int c = 0; c < 4; c++) oac[n][c] = 0.0f;
    float li0 = 0.0f, li1 = 0.0f;
    const float scale = 0.08838834764831845f;

    const int gr0 = qb * 128 + w * 16 + g;
    const int gr1 = gr0 + 8;
    const int jtmax = 2 * qb + 1;

    for (int jt = 0; jt <= jtmax; jt++) {
        const uint32_t cur = (uint32_t)(jt & 1) * STG;
        CP_WAIT0();
        __syncthreads();

        if (jt < jtmax) {
            const uint32_t nxt = (uint32_t)((jt + 1) & 1) * STG;
            const __nv_bfloat16* sk = Kg + (size_t)((jt + 1) * 64 + lrow) * PDH + ldhb;
            const __nv_bfloat16* sv = Vg + (size_t)((jt + 1) * 64 + lrow) * PDH + ldhb;
#pragma unroll
            for (int i = 0; i < 4; i++) {
                CP_ASYNC16(ksB + nxt + lOff + i * 16, sk + i * 8);
                CP_ASYNC16(vsB + nxt + lOff + i * 16, sv + i * 8);
            }
            CP_COMMIT();
        }

        float sc[8][4];
#pragma unroll
        for (int n = 0; n < 8; n++)
#pragma unroll
            for (int c = 0; c < 4; c++) sc[n][c] = 0.0f;

#pragma unroll
        for (int kt = 0; kt < 8; kt++) {
#pragma unroll
            for (int ntp = 0; ntp < 4; ntp++) {
                uint32_t b0, b1, b2, b3;
                uint32_t addr = ksB + cur + (uint32_t)(((ntp * 16 + hi * 8 + (wi & 7)) * QSTR
                                                        + kt * 16 + (wi >> 3) * 8) * 2);
                LDSM4(b0, b1, b2, b3, addr);
                uint32_t bA[2] = { b0, b1 };
                uint32_t bB2[2] = { b2, b3 };
                MMA16816(sc[ntp * 2],     qa[kt], bA);
                MMA16816(sc[ntp * 2 + 1], qa[kt], bB2);
            }
        }

        float rs0 = 0.0f, rs1 = 0.0f;
        const int colb = jt * 64 + t4 * 2;
#pragma unroll
        for (int nt = 0; nt < 8; nt++) {
            int c0 = colb + nt * 8;
            float p0 = (c0     <= gr0) ? __expf(sc[nt][0] * scale) : 0.0f;
            float p1 = (c0 + 1 <= gr0) ? __expf(sc[nt][1] * scale) : 0.0f;
            float p2 = (c0     <= gr1) ? __expf(sc[nt][2] * scale) : 0.0f;
            float p3 = (c0 + 1 <= gr1) ? __expf(sc[nt][3] * scale) : 0.0f;
            sc[nt][0] = p0; sc[nt][1] = p1; sc[nt][2] = p2; sc[nt][3] = p3;
            rs0 += p0 + p1;
            rs1 += p2 + p3;
        }
        rs0 += __shfl_xor_sync(0xffffffffu, rs0, 1);
        rs0 += __shfl_xor_sync(0xffffffffu, rs0, 2);
        rs1 += __shfl_xor_sync(0xffffffffu, rs1, 1);
        rs1 += __shfl_xor_sync(0xffffffffu, rs1, 2);
        li0 += rs0;
        li1 += rs1;

        uint32_t Phi[4][4], Plo[4][4];
#pragma unroll
        for (int kt = 0; kt < 4; kt++) {
#pragma unroll
            for (int hv = 0; hv < 2; hv++) {
                float* c = sc[2 * kt + hv];
                __nv_bfloat16 h0 = __float2bfloat16_rn(c[0]);
                __nv_bfloat16 h1 = __float2bfloat16_rn(c[1]);
                __nv_bfloat16 h2 = __float2bfloat16_rn(c[2]);
                __nv_bfloat16 h3 = __float2bfloat16_rn(c[3]);
                float l0 = c[0] - __bfloat162float(h0);
                float l1 = c[1] - __bfloat162float(h1);
                float l2 = c[2] - __bfloat162float(h2);
                float l3 = c[3] - __bfloat162float(h3);
                Phi[kt][hv * 2 + 0] = ((uint32_t)*(uint16_t*)&h1 << 16) | *(uint16_t*)&h0;
                Phi[kt][hv * 2 + 1] = ((uint32_t)*(uint16_t*)&h3 << 16) | *(uint16_t*)&h2;
                Plo[kt][hv * 2 + 0] = packbf2(l0, l1);
                Plo[kt][hv * 2 + 1] = packbf2(l2, l3);
            }
        }

#pragma unroll
        for (int kt = 0; kt < 4; kt++) {
#pragma unroll
            for (int ntp = 0; ntp < 8; ntp++) {
                uint32_t b0, b1, b2, b3;
                uint32_t addr = vsB + cur + (uint32_t)(((kt * 16 + wi) * QSTR
                                                        + ntp * 16 + hi * 8) * 2);
                LDSM4T(b0, b1, b2, b3, addr);
                uint32_t bA[2] = { b0, b1 };
                uint32_t bB2[2] = { b2, b3 };
                MMA16816(oac[ntp * 2],     Phi[kt], bA);
                MMA16816(oac[ntp * 2],     Plo[kt], bA);
                MMA16816(oac[ntp * 2 + 1], Phi[kt], bB2);
                MMA16816(oac[ntp * 2 + 1], Plo[kt], bB2);
            }
        }
    }

    const float inv0 = 1.0f / li0;
    const float inv1 = 1.0f / li1;
#pragma unroll
    for (int nt2 = 0; nt2 < 16; nt2++) {
        int oc = h * PDH + nt2 * 8 + t4 * 2;
        float s0 = oisc[oc], s1 = oisc[oc + 1];
        XO[(size_t)gr0 * PDM + oc]     = oac[nt2][0] * inv0 / s0;
        XO[(size_t)gr0 * PDM + oc + 1] = oac[nt2][1] * inv0 / s1;
        XO[(size_t)gr1 * PDM + oc]     = oac[nt2][2] * inv1 / s0;
        XO[(size_t)gr1 * PDM + oc + 1] = oac[nt2][3] * inv1 / s1;
    }
}

// ---------------------------------------------------------------------------
// Per-token int8 quantization; quantized values stored as bf16 (exact).
// ---------------------------------------------------------------------------
__global__ __launch_bounds__(256)
void quant2(const float* __restrict__ XO, __nv_bfloat16* __restrict__ Xq,
            float* __restrict__ Xs)
{
    __shared__ float red[256];
    const int t = blockIdx.x, tid = threadIdx.x;

    float v[8];
    float m = 0.0f;
#pragma unroll
    for (int i = 0; i < 8; i++) {
        v[i] = XO[(size_t)t * PDM + tid * 8 + i];
        m = fmaxf(m, fabsf(v[i]));
    }
    red[tid] = m;
    __syncthreads();
    for (int o = 128; o > 0; o >>= 1) {
        if (tid < o) red[tid] = fmaxf(red[tid], red[tid + o]);
        __syncthreads();
    }
    float sc = fmaxf(red[0] * (1.0f / 127.0f), 1e-7f);

    __nv_bfloat162 q[4];
#pragma unroll
    for (int i = 0; i < 4; i++) {
        float q0 = fminf(fmaxf(rintf(v[2 * i]     / sc), -128.0f), 127.0f);
        float q1 = fminf(fmaxf(rintf(v[2 * i + 1] / sc), -128.0f), 127.0f);
        q[i] = __floats2bfloat162_rn(q0, q1);
    }
    *(uint4*)(Xq + (size_t)t * PDM + tid * 8) = *(uint4*)q;
    if (tid == 0) Xs[t] = sc;
}

// ---------------------------------------------------------------------------
// Launch
// ---------------------------------------------------------------------------
extern "C" void kernel_launch(void* const* d_in, const int* in_sizes, int n_in,
                              void* d_out, int out_size)
{
    const int*   x_i8 = (const int*)d_in[0];
    const float* x_s  = (const float*)d_in[1];
    const float* cosp = (const float*)d_in[3];
    const float* sinp = (const float*)d_in[4];
    const int*   q_w  = (const int*)d_in[5];
    const float* q_ws = (const float*)d_in[6];
    const int*   k_w  = (const int*)d_in[7];
    const float* k_ws = (const float*)d_in[8];
    const int*   v_w  = (const int*)d_in[9];
    const float* v_ws = (const float*)d_in[10];
    const int*   o_w  = (const int*)d_in[11];
    const float* o_ws = (const float*)d_in[12];
    const float* o_is = (const float*)d_in[13];
    const float* qnw  = (const float*)d_in[14];
    const float* knw  = (const float*)d_in[15];

    unsigned char* base = nullptr;
    cudaGetSymbolAddress((void**)&base, g_scratch);

    __nv_bfloat16* xb   = (__nv_bfloat16*)(base + OFF_XB);
    __nv_bfloat16* wqkv = (__nv_bfloat16*)(base + OFF_WQKV);
    __nv_bfloat16* owb  = (__nv_bfloat16*)(base + OFF_OWB);
    __nv_bfloat16* qq   = (__nv_bfloat16*)(base + OFF_QQ);
    __nv_bfloat16* qk   = (__nv_bfloat16*)(base + OFF_QK);
    __nv_bfloat16* qf   = (__nv_bfloat16*)(base + OFF_QF);
    __nv_bfloat16* kf   = (__nv_bfloat16*)(base + OFF_KF);
    __nv_bfloat16* vf   = (__nv_bfloat16*)(base + OFF_VF);
    float*         xo   = (float*)(base + OFF_XO);
    __nv_bfloat16* xob  = (__nv_bfloat16*)(base + OFF_XOB);
    float*         xos  = (float*)(base + OFF_XOS);

    cudaFuncSetAttribute(gemm_qkv, cudaFuncAttributeMaxDynamicSharedMemorySize, GEMM_SMEM);
    cudaFuncSetAttribute(gemm_o,   cudaFuncAttributeMaxDynamicSharedMemorySize, GEMM_SMEM);
    cudaFuncSetAttribute(flash_mma, cudaFuncAttributeMaxDynamicSharedMemorySize, FAM_SMEM);

    // fused pack -> bf16 operands (xb | wqkv | owb contiguous)
    pack_bf16<<<2621440 / 256, 256>>>(x_i8, q_w, k_w, v_w, o_w, xb);

    // fused QKV projection via bf16 HMMA
    gemm_qkv<<<dim3(32, 32), 256, GEMM_SMEM>>>(xb, wqkv, x_s, q_ws, k_ws, v_ws, qq, qk, vf);

    // rmsnorm + rope -> head-major
    norm_rope_w<<<(PS * PNH)  / 8, 256>>>(qq, qnw, cosp, sinp, qf, PNH);
    norm_rope_w<<<(PS * PNHK) / 8, 256>>>(qk, knw, cosp, sinp, kf, PNHK);

    // flash attention
    flash_mma<<<dim3(32, PNH), 256, FAM_SMEM>>>(qf, kf, vf, o_is, xo);

    // per-token quant -> bf16 values + scales
    quant2<<<PS, 256>>>(xo, xob, xos);

    // o-proj -> FLOAT32 output
    gemm_o<<<dim3(16, 32), 256, GEMM_SMEM>>>(xob, owb, xos, o_ws, (float*)d_out);
}